// round 6
// baseline (speedup 1.0000x reference)
#include <cuda_runtime.h>
#include <cstdint>

#define BB 4
#define CC 64
#define HIN 96
#define WIN 96
#define HOUT 192
#define WOUT 192
#define NPX (HIN*WIN)          // 9216

// Scratch + precomputed data (allocation-free rule: device globals)
__device__ float g_sta[BB*CC*NPX];       // sta_feat  [b][c][96][96]
__device__ float g_A[BB*NPX*CC];         // fusL@sta, channel-last [b][px][64]
__device__ float g_B[BB*NPX*CC];         // fusR@x,   channel-last
__device__ float g_X[BB*NPX*CC];         // x transposed, channel-last
__device__ float g_off[4][2];
__device__ float g_stoff[4][2];
__device__ float g_wcpx[4][512];         // [o*64+c]
__device__ float g_M[4][512];            // [j*64+o]  (fusR @ we_par)
// kc_w repacked into mma fragment order, hi/lo tf32 split
__device__ float g_bhi[25*4096];
__device__ float g_blo[25*4096];

// ============================ helpers ======================================
__device__ __forceinline__ uint32_t smem_u32(const void* p) {
  uint32_t a;
  asm("{ .reg .u64 t; cvta.to.shared.u64 t, %1; cvt.u32.u64 %0, t; }" : "=r"(a) : "l"(p));
  return a;
}
__device__ __forceinline__ uint32_t to_tf32(float v) {
  uint32_t u; asm("cvt.rna.tf32.f32 %0, %1;" : "=r"(u) : "f"(v)); return u;
}
__device__ __forceinline__ void cp16(uint32_t dst, const float* src) {
  asm volatile("cp.async.cg.shared.global [%0], [%1], 16;" :: "r"(dst), "l"(src));
}
#define CP_COMMIT() asm volatile("cp.async.commit_group;" ::: "memory")
#define CP_WAIT1()  asm volatile("cp.async.wait_group 1;" ::: "memory")
#define CP_WAIT0()  asm volatile("cp.async.wait_group 0;" ::: "memory")

#define MMA_TF32(d, a, b0v, b1v) \
  asm volatile("mma.sync.aligned.m16n8k8.row.col.f32.tf32.tf32.f32 " \
      "{%0,%1,%2,%3}, {%4,%5,%6,%7}, {%8,%9}, {%0,%1,%2,%3};" \
      : "+f"((d)[0]), "+f"((d)[1]), "+f"((d)[2]), "+f"((d)[3]) \
      : "r"((a)[0]), "r"((a)[1]), "r"((a)[2]), "r"((a)[3]), "r"(b0v), "r"(b1v))

// ---------------------------------------------------------------------------
// K01: blocks 0..199 repack kc_w; blocks 200..203 per-parity MLP + M matrices
// ---------------------------------------------------------------------------
__global__ void k01_prep(const float* __restrict__ kcw,
                         const float* __restrict__ b1w, const float* __restrict__ b1b,
                         const float* __restrict__ b2w, const float* __restrict__ b2b,
                         const float* __restrict__ rw,  const float* __restrict__ rb,
                         const float* __restrict__ ow,  const float* __restrict__ ob,
                         const float* __restrict__ sow, const float* __restrict__ sob,
                         const float* __restrict__ wc,  const float* __restrict__ we,
                         const float* __restrict__ fusw) {
  const int tid = threadIdx.x;
  if (blockIdx.x < 200) {
    int idx = blockIdx.x*256 + tid;
    if (idx >= 25*2048) return;
    int l  = idx & 31;
    int ks = (idx >> 5) & 7;
    int nt = (idx >> 8) & 7;
    int t  = idx >> 11;
    int c  = nt*8 + (l >> 2);
    int k0 = ks*8 + (l & 3);
    const float* row = kcw + (c*25 + t)*64;
    float v0 = row[k0], v1 = row[k0 + 4];
    uint32_t h0 = to_tf32(v0), h1 = to_tf32(v1);
    g_bhi[idx*2]     = __uint_as_float(h0);
    g_bhi[idx*2 + 1] = __uint_as_float(h1);
    g_blo[idx*2]     = __uint_as_float(to_tf32(v0 - __uint_as_float(h0)));
    g_blo[idx*2 + 1] = __uint_as_float(to_tf32(v1 - __uint_as_float(h1)));
    return;
  }
  // ---- parity branch ----
  __shared__ float hid[64], emb[64], r[4];
  __shared__ float s_we2[512];     // we_px [c*8+j]
  __shared__ float s_fr[64*65];    // fusR^T [c][o] padded
  const int ci = blockIdx.x - 200;
  const float in2 = (ci >> 1) ? 0.25f : -0.25f;
  const float in3 = (ci & 1)  ? 0.25f : -0.25f;

  for (int e = tid; e < 4096; e += 256) {
    int o = e >> 6, c = e & 63;
    s_fr[c*65 + o] = fusw[o*128 + 64 + c];
  }
  if (tid < 64) {
    float a = b1b[tid] + 0.5f*b1w[tid*4+0] + 0.5f*b1w[tid*4+1]
            + in2*b1w[tid*4+2] + in3*b1w[tid*4+3];
    hid[tid] = fmaxf(a, 0.f);
  }
  __syncthreads();
  if (tid < 64) {
    float a = b2b[tid];
    #pragma unroll 8
    for (int k = 0; k < 64; k++) a = fmaf(b2w[tid*64+k], hid[k], a);
    emb[tid] = fmaxf(a, 0.f);
  }
  __syncthreads();
  if (tid < 4) {
    float a = rb[tid];
    for (int k = 0; k < 64; k++) a = fmaf(rw[tid*64+k], emb[k], a);
    r[tid] = 1.f / (1.f + expf(-a));
  } else if (tid < 6) {
    int t = tid - 4; float a = ob[t];
    for (int k = 0; k < 64; k++) a = fmaf(ow[t*64+k], emb[k], a);
    g_off[ci][t] = a;
  } else if (tid < 8) {
    int t = tid - 6; float a = sob[t];
    for (int k = 0; k < 64; k++) a = fmaf(sow[t*64+k], emb[k], a);
    g_stoff[ci][t] = a;
  }
  __syncthreads();
  for (int e = tid; e < 512; e += 256) {
    float a = 0.f, bsum = 0.f;
    #pragma unroll
    for (int ex = 0; ex < 4; ex++) {
      a    = fmaf(r[ex], wc[ex*512+e], a);
      bsum = fmaf(r[ex], we[ex*512+e], bsum);
    }
    g_wcpx[ci][e] = a;
    s_we2[e] = bsum;
  }
  __syncthreads();
  for (int e = tid; e < 512; e += 256) {
    int j = e >> 6, o = e & 63;
    float a = 0.f;
    #pragma unroll 8
    for (int c = 0; c < 64; c++) a = fmaf(s_fr[c*65 + o], s_we2[c*8 + j], a);
    g_M[ci][j*64 + o] = a;
  }
}

// ---------------------------------------------------------------------------
// K2X: transpose x [b][64][9216] -> g_X [b][9216][64]  (channel-last)
// ---------------------------------------------------------------------------
__global__ __launch_bounds__(256) void k2x_transpose(const float* __restrict__ x) {
  __shared__ float tile[32][33];
  const int b = blockIdx.z, c0 = blockIdx.y*32, px0 = blockIdx.x*32;
  const int tx = threadIdx.x & 31, ty = threadIdx.x >> 5;
  #pragma unroll
  for (int i = 0; i < 4; i++)
    tile[ty + i*8][tx] = x[((size_t)(b*CC + c0 + ty + i*8))*NPX + px0 + tx];
  __syncthreads();
  #pragma unroll
  for (int i = 0; i < 4; i++) {
    int pxl = ty + i*8;
    g_X[((size_t)b*NPX + px0 + pxl)*CC + c0 + tx] = tile[tx][pxl];
  }
}

// ---------------------------------------------------------------------------
// K2 v3 (mma.sync tf32, 3x-split, double-buffered B): fused kernel_warp GEMM
// + 25-tap sta conv. Tile: (b, 4 rows, 32 px) -> M=128. 512 thr / 16 warps.
// Warp: m-tile mt = wid&7 (16 px), n-half nth = wid>>3 (32 ch).
// ---------------------------------------------------------------------------
// floats: s_b 2*8192, s_a 64*130, s_x 64*8*36, s_kb 1600
#define K2_SMEM_FLOATS (16384 + 8320 + 18432 + 1600)

__global__ __launch_bounds__(512, 1) void k2_sta_mma(const float* __restrict__ x,
                                                     const float* __restrict__ st,
                                                     const float* __restrict__ kcb) {
  extern __shared__ float sm[];
  float* s_b  = sm;                 // [2 buf][8192]  (hi 4096 | lo 4096)
  float* s_a  = sm + 16384;         // [k 64][px 128 pad130]
  float* s_x  = sm + 24704;         // [c 64][row 8][col 36]
  float* s_kb = sm + 43136;         // [1600]

  const int b = blockIdx.z, h0 = blockIdx.y*4, w0 = blockIdx.x*32;
  const int tid = threadIdx.x, wid = tid >> 5, l = tid & 31;
  const int g = l >> 2, tg = l & 3;
  const int mt = wid & 7, nth = wid >> 3;
  const uint32_t sb = smem_u32(s_b);

  // ---- B prologue: tap 0 -> buf 0 ----
  {
    const float* srch = g_bhi;
    const float* srcl = g_blo;
    #pragma unroll
    for (int i = 0; i < 2; i++) {
      int j = tid + i*512;                  // 0..1023 chunks of 16B per half
      cp16(sb + (uint32_t)j*16u,           srch + j*4);
      cp16(sb + 16384u + (uint32_t)j*16u,  srcl + j*4);
    }
    CP_COMMIT();
  }

  // ---- stage A (st) [k][px 0..127] ----
  for (int e = tid; e < 8192; e += 512) {
    int k = e >> 7, px = e & 127;
    s_a[k*130 + px] = st[((b*CC + k)*HIN + h0 + (px >> 5))*WIN + w0 + (px & 31)];
  }
  // ---- x halo [c][8 rows][36 cols], edge-clamped ----
  for (int e = tid; e < 64*8*36; e += 512) {
    int col = e % 36; int row = (e / 36) & 7; int c = e / 288;
    int gy = min(max(h0 - 2 + row, 0), HIN - 1);
    int gx = min(max(w0 - 2 + col, 0), WIN - 1);
    s_x[e] = x[((b*CC + c)*HIN + gy)*WIN + gx];
  }
  for (int e = tid; e < 1600; e += 512) s_kb[e] = kcb[e];
  __syncthreads();

  // ---- A fragments (hi/lo tf32), tap-invariant ----
  uint32_t ah[8][4], al[8][4];
  {
    const int px0 = mt*16 + g, px1 = px0 + 8;
    #pragma unroll
    for (int ks = 0; ks < 8; ks++) {
      int r0 = (ks*8 + tg)*130, r1 = r0 + 4*130;
      float v0 = s_a[r0 + px0], v1 = s_a[r0 + px1];
      float v2 = s_a[r1 + px0], v3 = s_a[r1 + px1];
      ah[ks][0] = to_tf32(v0); al[ks][0] = to_tf32(v0 - __uint_as_float(ah[ks][0]));
      ah[ks][1] = to_tf32(v1); al[ks][1] = to_tf32(v1 - __uint_as_float(ah[ks][1]));
      ah[ks][2] = to_tf32(v2); al[ks][2] = to_tf32(v2 - __uint_as_float(ah[ks][2]));
      ah[ks][3] = to_tf32(v3); al[ks][3] = to_tf32(v3 - __uint_as_float(ah[ks][3]));
    }
  }

  float sacc[16];
  #pragma unroll
  for (int i = 0; i < 16; i++) sacc[i] = 0.f;

  const int prow  = mt >> 1;            // row within 4-row tile
  const int pcol0 = (mt & 1)*16 + g;    // col within 32-px segment

  for (int t = 0; t < 25; t++) {
    const int buf = t & 1;
    // issue next tap's B into the other buffer, then wait for this tap's B
    if (t < 24) {
      const uint32_t nb = sb + (uint32_t)(1 - buf)*32768u;
      const float* srch = g_bhi + (t + 1)*4096;
      const float* srcl = g_blo + (t + 1)*4096;
      #pragma unroll
      for (int i = 0; i < 2; i++) {
        int j = tid + i*512;
        cp16(nb + (uint32_t)j*16u,           srch + j*4);
        cp16(nb + 16384u + (uint32_t)j*16u,  srcl + j*4);
      }
      CP_COMMIT();
      CP_WAIT1();
    } else {
      CP_WAIT0();
    }
    __syncthreads();

    const int rr = t / 5, dw = t - rr*5;
    const float* bb = s_b + buf*8192;

    float d[4][4];
    #pragma unroll
    for (int n = 0; n < 4; n++) {
      int c0 = ((nth*4 + n)*8 + 2*tg)*25 + t;
      d[n][0] = s_kb[c0];      d[n][1] = s_kb[c0 + 25];
      d[n][2] = d[n][0];       d[n][3] = d[n][1];
    }

    #pragma unroll
    for (int ks = 0; ks < 8; ks++) {
      #pragma unroll
      for (int n = 0; n < 4; n++) {
        int bo = ((nth*4 + n)*8 + ks)*64 + l*2;
        float2 bh = *(const float2*)&bb[bo];
        float2 bl = *(const float2*)&bb[4096 + bo];
        uint32_t bh0 = __float_as_uint(bh.x), bh1 = __float_as_uint(bh.y);
        uint32_t bl0 = __float_as_uint(bl.x), bl1 = __float_as_uint(bl.y);
        MMA_TF32(d[n], ah[ks], bh0, bh1);
        MMA_TF32(d[n], ah[ks], bl0, bl1);
        MMA_TF32(d[n], al[ks], bh0, bh1);
      }
    }

    // epilogue: lrelu(gate) * x_halo, accumulate
    #pragma unroll
    for (int n = 0; n < 4; n++) {
      int cb = (nth*4 + n)*8 + 2*tg;
      #pragma unroll
      for (int j = 0; j < 4; j++) {
        int c  = cb + (j & 1);
        int px = pcol0 + (j >> 1)*8;
        float gv = d[n][j];
        float lv = fmaf(0.45f, fabsf(gv), 0.55f*gv);
        float xv = s_x[c*288 + (prow + rr)*36 + px + dw];
        sacc[n*4 + j] = fmaf(lv, xv, sacc[n*4 + j]);
      }
    }
    __syncthreads();   // all mma reads of buf done before it is refilled at t+2
  }

  #pragma unroll
  for (int n = 0; n < 4; n++) {
    int cb = (nth*4 + n)*8 + 2*tg;
    #pragma unroll
    for (int j = 0; j < 4; j++) {
      int c  = cb + (j & 1);
      int px = pcol0 + (j >> 1)*8;
      g_sta[((b*CC + c)*HIN + h0 + prow)*WIN + w0 + px] = sacc[n*4 + j];
    }
  }
}

// ---------------------------------------------------------------------------
// K2B: LR GEMMs  A = fusL @ sta,  B = fusR @ x, output channel-last.
// ---------------------------------------------------------------------------
#define K2B_SMEM_FLOATS (8192 + 64*68)

__global__ __launch_bounds__(256, 4) void k2b_gemm(const float* __restrict__ x,
                                                   const float* __restrict__ fusw) {
  extern __shared__ float sm[];
  float* s_src = sm;           // [k 64][px 128]
  float* s_wT  = sm + 8192;    // [k 64][o 64 pad68]

  const int px0 = blockIdx.x*128, b = blockIdx.y, mat = blockIdx.z;
  const int tid = threadIdx.x;
  const float* src = mat ? (x + (size_t)b*CC*NPX) : (g_sta + (size_t)b*CC*NPX);
  const int mo = mat ? 64 : 0;
  float* dst = (mat ? g_B : g_A) + (size_t)b*NPX*CC;

  for (int e = tid; e < 8192; e += 256) {
    int k = e >> 7, p = e & 127;
    s_src[e] = src[(size_t)k*NPX + px0 + p];
  }
  for (int e = tid; e < 4096; e += 256) {
    int o = e >> 6, k = e & 63;
    s_wT[k*68 + o] = fusw[o*128 + mo + k];
  }
  __syncthreads();

  const int o0 = (tid & 15)*4, p0 = (tid >> 4)*8;
  float4 acc[8];
  #pragma unroll
  for (int i = 0; i < 8; i++) acc[i] = make_float4(0.f, 0.f, 0.f, 0.f);

  #pragma unroll 4
  for (int k = 0; k < 64; k++) {
    float4 w4 = *(const float4*)&s_wT[k*68 + o0];
    const float* sr = s_src + k*128 + p0;
    #pragma unroll
    for (int pp = 0; pp < 8; pp++) {
      float s = sr[pp];
      acc[pp].x = fmaf(w4.x, s, acc[pp].x);
      acc[pp].y = fmaf(w4.y, s, acc[pp].y);
      acc[pp].z = fmaf(w4.z, s, acc[pp].z);
      acc[pp].w = fmaf(w4.w, s, acc[pp].w);
    }
  }
  #pragma unroll
  for (int pp = 0; pp < 8; pp++)
    *(float4*)&dst[(size_t)(px0 + p0 + pp)*CC + o0] = acc[pp];
}

// ---------------------------------------------------------------------------
// K3 v3: out = bilin_stoff(A) + bilin_off(B) + M_par @ (wc_par @ bilin_off(X)) + fus_b
// ---------------------------------------------------------------------------
__global__ __launch_bounds__(256, 4) void k3_fuse(const float* __restrict__ fusb,
                                                  float* __restrict__ out) {
  __shared__ float  s_fea[4096];   // [c][64px]
  __shared__ float  s_t[512];      // [j][64px]
  __shared__ float  s_wc[1024];    // [pw][o*64+c]
  __shared__ float  s_M[1024];     // [pw][j*64+o]
  __shared__ float  s_fb[64];
  __shared__ int2   s_gi[128];     // [img][px]
  __shared__ float4 s_gw[128];     // (wxa, wxb, wy0, wy1)

  const int b = blockIdx.z, Y = blockIdx.y, X0 = blockIdx.x * 64;
  const int tid = threadIdx.x;
  const int ph = Y & 1;

  for (int e = tid; e < 1024; e += 256) {
    int pw = e >> 9, i = e & 511;
    s_wc[pw*512 + i] = g_wcpx[ph*2 + pw][i];
    s_M[pw*512 + i]  = g_M[ph*2 + pw][i];
  }
  if (tid < 64) s_fb[tid] = fusb[tid];
  if (tid < 128) {
    int img = tid >> 6, px = tid & 63;
    int X = X0 + px; int ci = ph*2 + (X & 1);
    float offx = img ? g_stoff[ci][0] : g_off[ci][0];
    float offy = img ? g_stoff[ci][1] : g_off[ci][1];
    float pxf = (X + 0.5f)*0.5f - 0.5f + offx;
    float pyf = (Y + 0.5f)*0.5f - 0.5f + offy;
    float xf = floorf(pxf), yf = floorf(pyf);
    int ix0 = (int)xf, iy0 = (int)yf;
    float fx = pxf - xf, fy = pyf - yf;
    int cb = min(max(ix0, 0), WIN - 2);
    float wxa = 0.f, wxb = 0.f;
    if (ix0 >= 0 && ix0 <= WIN - 2)      { wxa = 1.f - fx; wxb = fx; }
    else if (ix0 == -1)                  { wxa = fx; }
    else if (ix0 == WIN - 1)             { wxb = 1.f - fx; }
    int ry0 = min(max(iy0, 0), HIN - 1), ry1 = min(max(iy0 + 1, 0), HIN - 1);
    float wy0 = (iy0 >= 0 && iy0 <= HIN - 1) ? (1.f - fy) : 0.f;
    float wy1 = (iy0 + 1 >= 0 && iy0 + 1 <= HIN - 1) ? fy : 0.f;
    s_gi[tid] = make_int2(ry0*WIN + cb, ry1*WIN + cb);
    s_gw[tid] = make_float4(wxa, wxb, wy0, wy1);
  }
  __syncthreads();

  // P1: fea0 = bilin_off(X)
  {
    const float4* P = (const float4*)g_X + (size_t)b*NPX*16;
    for (int u = tid; u < 1024; u += 256) {
      int px = u & 63, c4 = u >> 6;
      int2 gi = s_gi[px];
      float4 w = s_gw[px];
      float4 a0 = __ldg(P + gi.x*16 + c4);
      float4 a1 = __ldg(P + gi.x*16 + 16 + c4);
      float4 b0 = __ldg(P + gi.y*16 + c4);
      float4 b1 = __ldg(P + gi.y*16 + 16 + c4);
      float4 v;
      v.x = w.z*(w.x*a0.x + w.y*a1.x) + w.w*(w.x*b0.x + w.y*b1.x);
      v.y = w.z*(w.x*a0.y + w.y*a1.y) + w.w*(w.x*b0.y + w.y*b1.y);
      v.z = w.z*(w.x*a0.z + w.y*a1.z) + w.w*(w.x*b0.z + w.y*b1.z);
      v.w = w.z*(w.x*a0.w + w.y*a1.w) + w.w*(w.x*b0.w + w.y*b1.w);
      int c = c4*4;
      s_fea[c*64 + px]     = v.x;
      s_fea[(c+1)*64 + px] = v.y;
      s_fea[(c+2)*64 + px] = v.z;
      s_fea[(c+3)*64 + px] = v.w;
    }
  }
  __syncthreads();

  // P2: t[j][px] = wc_par . fea0
  for (int e = tid; e < 512; e += 256) {
    int j = e >> 6, px = e & 63, pw = px & 1;
    const float* wr = s_wc + pw*512 + j*64;
    float a = 0.f;
    #pragma unroll 8
    for (int c = 0; c < 64; c++) a = fmaf(wr[c], s_fea[c*64 + px], a);
    s_t[j*64 + px] = a;
  }
  __syncthreads();

  // P3: out = bilinA + bilinB + M.t + bias
  {
    const float4* PA = (const float4*)g_A + (size_t)b*NPX*16;
    const float4* PB = (const float4*)g_B + (size_t)b*NPX*16;
    for (int u = tid; u < 1024; u += 256) {
      int px = u & 63, o4 = u >> 6, pw = px & 1;
      int2 gi1 = s_gi[64 + px]; float4 w1 = s_gw[64 + px];
      float4 A00 = __ldg(PA + gi1.x*16 + o4);
      float4 A01 = __ldg(PA + gi1.x*16 + 16 + o4);
      float4 A10 = __ldg(PA + gi1.y*16 + o4);
      float4 A11 = __ldg(PA + gi1.y*16 + 16 + o4);
      int2 gi0 = s_gi[px]; float4 w0 = s_gw[px];
      float4 B00 = __ldg(PB + gi0.x*16 + o4);
      float4 B01 = __ldg(PB + gi0.x*16 + 16 + o4);
      float4 B10 = __ldg(PB + gi0.y*16 + o4);
      float4 B11 = __ldg(PB + gi0.y*16 + 16 + o4);
      float4 r;
      r.x = w1.z*(w1.x*A00.x + w1.y*A01.x) + w1.w*(w1.x*A10.x + w1.y*A11.x)
          + w0.z*(w0.x*B00.x + w0.y*B01.x) + w0.w*(w0.x*B10.x + w0.y*B11.x);
      r.y = w1.z*(w1.x*A00.y + w1.y*A01.y) + w1.w*(w1.x*A10.y + w1.y*A11.y)
          + w0.z*(w0.x*B00.y + w0.y*B01.y) + w0.w*(w0.x*B10.y + w0.y*B11.y);
      r.z = w1.z*(w1.x*A00.z + w1.y*A01.z) + w1.w*(w1.x*A10.z + w1.y*A11.z)
          + w0.z*(w0.x*B00.z + w0.y*B01.z) + w0.w*(w0.x*B10.z + w0.y*B11.z);
      r.w = w1.z*(w1.x*A00.w + w1.y*A01.w) + w1.w*(w1.x*A10.w + w1.y*A11.w)
          + w0.z*(w0.x*B00.w + w0.y*B01.w) + w0.w*(w0.x*B10.w + w0.y*B11.w);
      int o0 = o4*4;
      r.x += s_fb[o0]; r.y += s_fb[o0+1]; r.z += s_fb[o0+2]; r.w += s_fb[o0+3];
      const float* Mp = s_M + pw*512;
      #pragma unroll
      for (int j = 0; j < 8; j++) {
        float tj = s_t[j*64 + px];
        float4 m4 = *(const float4*)&Mp[j*64 + o0];
        r.x = fmaf(m4.x, tj, r.x);
        r.y = fmaf(m4.y, tj, r.y);
        r.z = fmaf(m4.z, tj, r.z);
        r.w = fmaf(m4.w, tj, r.w);
      }
      float* op = out + ((size_t)(b*CC + o0)*HOUT + Y)*WOUT + X0 + px;
      op[0]            = r.x;
      op[HOUT*WOUT]    = r.y;
      op[2*HOUT*WOUT]  = r.z;
      op[3*HOUT*WOUT]  = r.w;
    }
  }
}

// ---------------------------------------------------------------------------
extern "C" void kernel_launch(void* const* d_in, const int* in_sizes, int n_in,
                              void* d_out, int out_size) {
  const float* x    = (const float*)d_in[0];
  const float* st   = (const float*)d_in[1];
  const float* kcw  = (const float*)d_in[2];
  const float* kcb  = (const float*)d_in[3];
  const float* wc   = (const float*)d_in[4];
  const float* we   = (const float*)d_in[5];
  const float* b1w  = (const float*)d_in[6];
  const float* b1b  = (const float*)d_in[7];
  const float* b2w  = (const float*)d_in[8];
  const float* b2b  = (const float*)d_in[9];
  const float* rw   = (const float*)d_in[10];
  const float* rb   = (const float*)d_in[11];
  const float* ow   = (const float*)d_in[12];
  const float* ob   = (const float*)d_in[13];
  const float* sow  = (const float*)d_in[14];
  const float* sob  = (const float*)d_in[15];
  const float* fusw = (const float*)d_in[16];
  const float* fusb = (const float*)d_in[17];
  float* out = (float*)d_out;

  const int smem2 = K2_SMEM_FLOATS * 4;
  const int smemb = K2B_SMEM_FLOATS * 4;
  cudaFuncSetAttribute(k2_sta_mma, cudaFuncAttributeMaxDynamicSharedMemorySize, smem2);
  cudaFuncSetAttribute(k2b_gemm,   cudaFuncAttributeMaxDynamicSharedMemorySize, smemb);

  k01_prep<<<204, 256>>>(kcw, b1w, b1b, b2w, b2b, rw, rb, ow, ob, sow, sob, wc, we, fusw);
  k2x_transpose<<<dim3(NPX/32, 2, BB), 256>>>(x);
  k2_sta_mma<<<dim3(WIN/32, HIN/4, BB), 512, smem2>>>(x, st, kcb);
  k2b_gemm<<<dim3(NPX/128, BB, 2), 256, smemb>>>(x, fusw);
  k3_fuse<<<dim3(WOUT/64, HOUT, BB), 256>>>(fusb, out);
}

// round 7
// speedup vs baseline: 1.1901x; 1.1901x over previous
#include <cuda_runtime.h>
#include <cuda_bf16.h>
#include <cstdint>

#define BB 4
#define CC 64
#define HIN 96
#define WIN 96
#define HOUT 192
#define WOUT 192
#define NPX (HIN*WIN)          // 9216

// Scratch + precomputed data (allocation-free rule: device globals)
__device__ float g_sta[BB*CC*NPX];       // sta_feat  [b][c][96][96]
__device__ float g_A[BB*NPX*CC];         // fusL@sta, channel-last [b][px][64]
__device__ float g_B[BB*NPX*CC];         // fusR@x,   channel-last
__device__ float g_X[BB*NPX*CC];         // x transposed, channel-last
__device__ float g_off[4][2];
__device__ float g_stoff[4][2];
__device__ float g_wcpx[4][512];         // [o*64+c]
__device__ float g_M[4][512];            // [j*64+o]  (fusR @ we_par)
// kc_w repacked: [t 25][q 8][ks 4][lane 32] uint4 = (b0h, b1h, b0l, b1l) bf16x2
__device__ uint4 g_b[25600];

// ============================ helpers ======================================
__device__ __forceinline__ uint32_t smem_u32(const void* p) {
  uint32_t a;
  asm("{ .reg .u64 t; cvta.to.shared.u64 t, %1; cvt.u32.u64 %0, t; }" : "=r"(a) : "l"(p));
  return a;
}
__device__ __forceinline__ void cp16(uint32_t dst, const float* src) {
  asm volatile("cp.async.cg.shared.global [%0], [%1], 16;" :: "r"(dst), "l"(src));
}
#define CP_COMMIT() asm volatile("cp.async.commit_group;" ::: "memory")
#define CP_WAIT0()  asm volatile("cp.async.wait_group 0;" ::: "memory")

// bf16 hi/lo split of two floats, packed as bf16x2
__device__ __forceinline__ uint32_t bf16_split2(float v0, float v1, uint32_t& lo_out) {
  __nv_bfloat162 h = __floats2bfloat162_rn(v0, v1);
  float r0 = v0 - __bfloat162float(h.x);
  float r1 = v1 - __bfloat162float(h.y);
  __nv_bfloat162 lo = __floats2bfloat162_rn(r0, r1);
  lo_out = *(uint32_t*)&lo;
  return *(uint32_t*)&h;
}

#define MMA_BF16(d, a, b0v, b1v) \
  asm volatile("mma.sync.aligned.m16n8k16.row.col.f32.bf16.bf16.f32 " \
      "{%0,%1,%2,%3}, {%4,%5,%6,%7}, {%8,%9}, {%0,%1,%2,%3};" \
      : "+f"((d)[0]), "+f"((d)[1]), "+f"((d)[2]), "+f"((d)[3]) \
      : "r"((a)[0]), "r"((a)[1]), "r"((a)[2]), "r"((a)[3]), "r"(b0v), "r"(b1v))

// ---------------------------------------------------------------------------
// K01: blocks 0..99 repack kc_w -> bf16 hi/lo fragments; blocks 100..103 parity
// B fragment for (t, q, ks, lane l: g=l>>2, tg=l&3):
//   c = q*8+g, kbase = ks*16+2tg
//   b0 = (k, k+1), b1 = (k+8, k+9)
// ---------------------------------------------------------------------------
__global__ void k01_prep(const float* __restrict__ kcw,
                         const float* __restrict__ b1w, const float* __restrict__ b1b,
                         const float* __restrict__ b2w, const float* __restrict__ b2b,
                         const float* __restrict__ rw,  const float* __restrict__ rb,
                         const float* __restrict__ ow,  const float* __restrict__ ob,
                         const float* __restrict__ sow, const float* __restrict__ sob,
                         const float* __restrict__ wc,  const float* __restrict__ we,
                         const float* __restrict__ fusw) {
  const int tid = threadIdx.x;
  if (blockIdx.x < 100) {
    int idx = blockIdx.x*256 + tid;          // 0..25599
    int l  = idx & 31;
    int ks = (idx >> 5) & 3;
    int q  = (idx >> 7) & 7;
    int t  = idx >> 10;
    int g = l >> 2, tg = l & 3;
    int c  = q*8 + g;
    int k0 = ks*16 + 2*tg;
    const float* row = kcw + (c*25 + t)*64;
    float v0 = row[k0], v1 = row[k0 + 1], v2 = row[k0 + 8], v3 = row[k0 + 9];
    uint32_t l01, l23;
    uint32_t h01 = bf16_split2(v0, v1, l01);
    uint32_t h23 = bf16_split2(v2, v3, l23);
    g_b[idx] = make_uint4(h01, h23, l01, l23);
    return;
  }
  // ---- parity branch ----
  __shared__ float hid[64], emb[64], r[4];
  __shared__ float s_we2[512];     // we_px [c*8+j]
  __shared__ float s_fr[64*65];    // fusR^T [c][o] padded
  const int ci = blockIdx.x - 100;
  const float in2 = (ci >> 1) ? 0.25f : -0.25f;
  const float in3 = (ci & 1)  ? 0.25f : -0.25f;

  for (int e = tid; e < 4096; e += 256) {
    int o = e >> 6, c = e & 63;
    s_fr[c*65 + o] = fusw[o*128 + 64 + c];
  }
  if (tid < 64) {
    float a = b1b[tid] + 0.5f*b1w[tid*4+0] + 0.5f*b1w[tid*4+1]
            + in2*b1w[tid*4+2] + in3*b1w[tid*4+3];
    hid[tid] = fmaxf(a, 0.f);
  }
  __syncthreads();
  if (tid < 64) {
    float a = b2b[tid];
    #pragma unroll 8
    for (int k = 0; k < 64; k++) a = fmaf(b2w[tid*64+k], hid[k], a);
    emb[tid] = fmaxf(a, 0.f);
  }
  __syncthreads();
  if (tid < 4) {
    float a = rb[tid];
    for (int k = 0; k < 64; k++) a = fmaf(rw[tid*64+k], emb[k], a);
    r[tid] = 1.f / (1.f + expf(-a));
  } else if (tid < 6) {
    int t = tid - 4; float a = ob[t];
    for (int k = 0; k < 64; k++) a = fmaf(ow[t*64+k], emb[k], a);
    g_off[ci][t] = a;
  } else if (tid < 8) {
    int t = tid - 6; float a = sob[t];
    for (int k = 0; k < 64; k++) a = fmaf(sow[t*64+k], emb[k], a);
    g_stoff[ci][t] = a;
  }
  __syncthreads();
  for (int e = tid; e < 512; e += 256) {
    float a = 0.f, bsum = 0.f;
    #pragma unroll
    for (int ex = 0; ex < 4; ex++) {
      a    = fmaf(r[ex], wc[ex*512+e], a);
      bsum = fmaf(r[ex], we[ex*512+e], bsum);
    }
    g_wcpx[ci][e] = a;
    s_we2[e] = bsum;
  }
  __syncthreads();
  for (int e = tid; e < 512; e += 256) {
    int j = e >> 6, o = e & 63;
    float a = 0.f;
    #pragma unroll 8
    for (int c = 0; c < 64; c++) a = fmaf(s_fr[c*65 + o], s_we2[c*8 + j], a);
    g_M[ci][j*64 + o] = a;
  }
}

// ---------------------------------------------------------------------------
// K2X: transpose x [b][64][9216] -> g_X [b][9216][64]  (channel-last)
// ---------------------------------------------------------------------------
__global__ __launch_bounds__(256) void k2x_transpose(const float* __restrict__ x) {
  __shared__ float tile[32][33];
  const int b = blockIdx.z, c0 = blockIdx.y*32, px0 = blockIdx.x*32;
  const int tx = threadIdx.x & 31, ty = threadIdx.x >> 5;
  #pragma unroll
  for (int i = 0; i < 4; i++)
    tile[ty + i*8][tx] = x[((size_t)(b*CC + c0 + ty + i*8))*NPX + px0 + tx];
  __syncthreads();
  #pragma unroll
  for (int i = 0; i < 4; i++) {
    int pxl = ty + i*8;
    g_X[((size_t)b*NPX + px0 + pxl)*CC + c0 + tx] = tile[tx][pxl];
  }
}

// ---------------------------------------------------------------------------
// K2 v4 (mma.sync bf16 m16n8k16, 3-term hi/lo): fused kernel_warp GEMM +
// 25-tap sta conv. Block: 256 thr / 8 warps, tile (b, 2 rows, 32 px), M=64.
// Warp: mt = wid&3 (16 px m-tile), nth = wid>>2 (32-ch half).
// Per tap per warp: 16 LDS.128 + 48 MMA.
// ---------------------------------------------------------------------------
// floats: s_b 4096 (16KB as uint4[1024]), s_a 4224, s_x 13824, s_kb 1600
#define K2_SMEM_FLOATS (4096 + 4224 + 13824 + 1600)

__global__ __launch_bounds__(256, 2) void k2_sta_mma(const float* __restrict__ x,
                                                     const float* __restrict__ st,
                                                     const float* __restrict__ kcb) {
  extern __shared__ float sm[];
  float* s_b  = sm;                // [1024] uint4 view: [q 8][ks 4][lane 32]
  float* s_a  = sm + 4096;         // [k 64][px 64 pad66]
  float* s_x  = sm + 8320;         // [c 64][row 6][col 36]
  float* s_kb = sm + 22144;        // [1600]

  const int b = blockIdx.z, h0 = blockIdx.y*2, w0 = blockIdx.x*32;
  const int tid = threadIdx.x, wid = tid >> 5, l = tid & 31;
  const int g = l >> 2, tg = l & 3;
  const int mt = wid & 3, nth = wid >> 2;
  const uint32_t sb = smem_u32(s_b);

  for (int e = tid; e < 4096; e += 256) {
    int k = e >> 6, px = e & 63;
    s_a[k*66 + px] = st[((b*CC + k)*HIN + h0 + (px >> 5))*WIN + w0 + (px & 31)];
  }
  for (int e = tid; e < 64*6*36; e += 256) {
    int col = e % 36; int row = (e / 36) % 6; int c = e / 216;
    int gy = min(max(h0 - 2 + row, 0), HIN - 1);
    int gx = min(max(w0 - 2 + col, 0), WIN - 1);
    s_x[e] = x[((b*CC + c)*HIN + gy)*WIN + gx];
  }
  for (int e = tid; e < 1600; e += 256) s_kb[e] = kcb[e];
  __syncthreads();

  // ---- A fragments (bf16 hi/lo), tap-invariant: [ks 4][4 regs] ----
  uint32_t ahi[4][4], alo[4][4];
  {
    const int pxg = mt*16 + g, pxg8 = pxg + 8;
    #pragma unroll
    for (int ks = 0; ks < 4; ks++) {
      int kb = ks*16 + 2*tg;
      ahi[ks][0] = bf16_split2(s_a[kb*66 + pxg],      s_a[(kb+1)*66 + pxg],  alo[ks][0]);
      ahi[ks][1] = bf16_split2(s_a[kb*66 + pxg8],     s_a[(kb+1)*66 + pxg8], alo[ks][1]);
      ahi[ks][2] = bf16_split2(s_a[(kb+8)*66 + pxg],  s_a[(kb+9)*66 + pxg],  alo[ks][2]);
      ahi[ks][3] = bf16_split2(s_a[(kb+8)*66 + pxg8], s_a[(kb+9)*66 + pxg8], alo[ks][3]);
    }
  }

  float sacc[16];
  #pragma unroll
  for (int i = 0; i < 16; i++) sacc[i] = 0.f;

  const int prow  = mt >> 1;
  const int pcol0 = (mt & 1)*16 + g;

  for (int t = 0; t < 25; t++) {
    // ---- stage B (16KB) via cp.async ----
    {
      const float* src = (const float*)(g_b + t*1024);
      #pragma unroll
      for (int i = 0; i < 4; i++) {
        int j = tid + i*256;                       // 0..1023 uint4 chunks
        cp16(sb + (uint32_t)j*16u, src + j*4);
      }
      CP_COMMIT(); CP_WAIT0();
      __syncthreads();
    }

    const int rr = t / 5, dw = t - rr*5;

    float d[4][4];
    #pragma unroll
    for (int n = 0; n < 4; n++) {
      int c0 = ((nth*4 + n)*8 + 2*tg)*25 + t;
      d[n][0] = s_kb[c0];      d[n][1] = s_kb[c0 + 25];
      d[n][2] = d[n][0];       d[n][3] = d[n][1];
    }

    const uint4* bb = (const uint4*)s_b;
    #pragma unroll
    for (int ks = 0; ks < 4; ks++) {
      #pragma unroll
      for (int n = 0; n < 4; n++) {
        uint4 bv = bb[((nth*4 + n)*4 + ks)*32 + l];
        MMA_BF16(d[n], ahi[ks], bv.x, bv.y);   // hi*hi
        MMA_BF16(d[n], ahi[ks], bv.z, bv.w);   // hi*lo
        MMA_BF16(d[n], alo[ks], bv.x, bv.y);   // lo*hi
      }
    }

    // epilogue: lrelu(gate) * x_halo, accumulate
    #pragma unroll
    for (int n = 0; n < 4; n++) {
      int cb = (nth*4 + n)*8 + 2*tg;
      #pragma unroll
      for (int j = 0; j < 4; j++) {
        int c  = cb + (j & 1);
        int px = pcol0 + (j >> 1)*8;
        float gv = d[n][j];
        float lv = fmaf(0.45f, fabsf(gv), 0.55f*gv);
        float xv = s_x[c*216 + (prow + rr)*36 + px + dw];
        sacc[n*4 + j] = fmaf(lv, xv, sacc[n*4 + j]);
      }
    }
    __syncthreads();
  }

  #pragma unroll
  for (int n = 0; n < 4; n++) {
    int cb = (nth*4 + n)*8 + 2*tg;
    #pragma unroll
    for (int j = 0; j < 4; j++) {
      int c  = cb + (j & 1);
      int px = pcol0 + (j >> 1)*8;
      g_sta[((b*CC + c)*HIN + h0 + prow)*WIN + w0 + px] = sacc[n*4 + j];
    }
  }
}

// ---------------------------------------------------------------------------
// K2B: LR GEMMs  A = fusL @ sta,  B = fusR @ x, output channel-last.
// ---------------------------------------------------------------------------
#define K2B_SMEM_FLOATS (8192 + 64*68)

__global__ __launch_bounds__(256, 4) void k2b_gemm(const float* __restrict__ x,
                                                   const float* __restrict__ fusw) {
  extern __shared__ float sm[];
  float* s_src = sm;           // [k 64][px 128]
  float* s_wT  = sm + 8192;    // [k 64][o 64 pad68]

  const int px0 = blockIdx.x*128, b = blockIdx.y, mat = blockIdx.z;
  const int tid = threadIdx.x;
  const float* src = mat ? (x + (size_t)b*CC*NPX) : (g_sta + (size_t)b*CC*NPX);
  const int mo = mat ? 64 : 0;
  float* dst = (mat ? g_B : g_A) + (size_t)b*NPX*CC;

  for (int e = tid; e < 8192; e += 256) {
    int k = e >> 7, p = e & 127;
    s_src[e] = src[(size_t)k*NPX + px0 + p];
  }
  for (int e = tid; e < 4096; e += 256) {
    int o = e >> 6, k = e & 63;
    s_wT[k*68 + o] = fusw[o*128 + mo + k];
  }
  __syncthreads();

  const int o0 = (tid & 15)*4, p0 = (tid >> 4)*8;
  float4 acc[8];
  #pragma unroll
  for (int i = 0; i < 8; i++) acc[i] = make_float4(0.f, 0.f, 0.f, 0.f);

  #pragma unroll 4
  for (int k = 0; k < 64; k++) {
    float4 w4 = *(const float4*)&s_wT[k*68 + o0];
    const float* sr = s_src + k*128 + p0;
    #pragma unroll
    for (int pp = 0; pp < 8; pp++) {
      float s = sr[pp];
      acc[pp].x = fmaf(w4.x, s, acc[pp].x);
      acc[pp].y = fmaf(w4.y, s, acc[pp].y);
      acc[pp].z = fmaf(w4.z, s, acc[pp].z);
      acc[pp].w = fmaf(w4.w, s, acc[pp].w);
    }
  }
  #pragma unroll
  for (int pp = 0; pp < 8; pp++)
    *(float4*)&dst[(size_t)(px0 + p0 + pp)*CC + o0] = acc[pp];
}

// ---------------------------------------------------------------------------
// K3 v3: out = bilin_stoff(A) + bilin_off(B) + M_par @ (wc_par @ bilin_off(X)) + fus_b
// ---------------------------------------------------------------------------
__global__ __launch_bounds__(256, 4) void k3_fuse(const float* __restrict__ fusb,
                                                  float* __restrict__ out) {
  __shared__ float  s_fea[4096];   // [c][64px]
  __shared__ float  s_t[512];      // [j][64px]
  __shared__ float  s_wc[1024];    // [pw][o*64+c]
  __shared__ float  s_M[1024];     // [pw][j*64+o]
  __shared__ float  s_fb[64];
  __shared__ int2   s_gi[128];     // [img][px]
  __shared__ float4 s_gw[128];     // (wxa, wxb, wy0, wy1)

  const int b = blockIdx.z, Y = blockIdx.y, X0 = blockIdx.x * 64;
  const int tid = threadIdx.x;
  const int ph = Y & 1;

  for (int e = tid; e < 1024; e += 256) {
    int pw = e >> 9, i = e & 511;
    s_wc[pw*512 + i] = g_wcpx[ph*2 + pw][i];
    s_M[pw*512 + i]  = g_M[ph*2 + pw][i];
  }
  if (tid < 64) s_fb[tid] = fusb[tid];
  if (tid < 128) {
    int img = tid >> 6, px = tid & 63;
    int X = X0 + px; int ci = ph*2 + (X & 1);
    float offx = img ? g_stoff[ci][0] : g_off[ci][0];
    float offy = img ? g_stoff[ci][1] : g_off[ci][1];
    float pxf = (X + 0.5f)*0.5f - 0.5f + offx;
    float pyf = (Y + 0.5f)*0.5f - 0.5f + offy;
    float xf = floorf(pxf), yf = floorf(pyf);
    int ix0 = (int)xf, iy0 = (int)yf;
    float fx = pxf - xf, fy = pyf - yf;
    int cb = min(max(ix0, 0), WIN - 2);
    float wxa = 0.f, wxb = 0.f;
    if (ix0 >= 0 && ix0 <= WIN - 2)      { wxa = 1.f - fx; wxb = fx; }
    else if (ix0 == -1)                  { wxa = fx; }
    else if (ix0 == WIN - 1)             { wxb = 1.f - fx; }
    int ry0 = min(max(iy0, 0), HIN - 1), ry1 = min(max(iy0 + 1, 0), HIN - 1);
    float wy0 = (iy0 >= 0 && iy0 <= HIN - 1) ? (1.f - fy) : 0.f;
    float wy1 = (iy0 + 1 >= 0 && iy0 + 1 <= HIN - 1) ? fy : 0.f;
    s_gi[tid] = make_int2(ry0*WIN + cb, ry1*WIN + cb);
    s_gw[tid] = make_float4(wxa, wxb, wy0, wy1);
  }
  __syncthreads();

  // P1: fea0 = bilin_off(X)
  {
    const float4* P = (const float4*)g_X + (size_t)b*NPX*16;
    for (int u = tid; u < 1024; u += 256) {
      int px = u & 63, c4 = u >> 6;
      int2 gi = s_gi[px];
      float4 w = s_gw[px];
      float4 a0 = __ldg(P + gi.x*16 + c4);
      float4 a1 = __ldg(P + gi.x*16 + 16 + c4);
      float4 b0 = __ldg(P + gi.y*16 + c4);
      float4 b1 = __ldg(P + gi.y*16 + 16 + c4);
      float4 v;
      v.x = w.z*(w.x*a0.x + w.y*a1.x) + w.w*(w.x*b0.x + w.y*b1.x);
      v.y = w.z*(w.x*a0.y + w.y*a1.y) + w.w*(w.x*b0.y + w.y*b1.y);
      v.z = w.z*(w.x*a0.z + w.y*a1.z) + w.w*(w.x*b0.z + w.y*b1.z);
      v.w = w.z*(w.x*a0.w + w.y*a1.w) + w.w*(w.x*b0.w + w.y*b1.w);
      int c = c4*4;
      s_fea[c*64 + px]     = v.x;
      s_fea[(c+1)*64 + px] = v.y;
      s_fea[(c+2)*64 + px] = v.z;
      s_fea[(c+3)*64 + px] = v.w;
    }
  }
  __syncthreads();

  // P2: t[j][px] = wc_par . fea0
  for (int e = tid; e < 512; e += 256) {
    int j = e >> 6, px = e & 63, pw = px & 1;
    const float* wr = s_wc + pw*512 + j*64;
    float a = 0.f;
    #pragma unroll 8
    for (int c = 0; c < 64; c++) a = fmaf(wr[c], s_fea[c*64 + px], a);
    s_t[j*64 + px] = a;
  }
  __syncthreads();

  // P3: out = bilinA + bilinB + M.t + bias
  {
    const float4* PA = (const float4*)g_A + (size_t)b*NPX*16;
    const float4* PB = (const float4*)g_B + (size_t)b*NPX*16;
    for (int u = tid; u < 1024; u += 256) {
      int px = u & 63, o4 = u >> 6, pw = px & 1;
      int2 gi1 = s_gi[64 + px]; float4 w1 = s_gw[64 + px];
      float4 A00 = __ldg(PA + gi1.x*16 + o4);
      float4 A01 = __ldg(PA + gi1.x*16 + 16 + o4);
      float4 A10 = __ldg(PA + gi1.y*16 + o4);
      float4 A11 = __ldg(PA + gi1.y*16 + 16 + o4);
      int2 gi0 = s_gi[px]; float4 w0 = s_gw[px];
      float4 B00 = __ldg(PB + gi0.x*16 + o4);
      float4 B01 = __ldg(PB + gi0.x*16 + 16 + o4);
      float4 B10 = __ldg(PB + gi0.y*16 + o4);
      float4 B11 = __ldg(PB + gi0.y*16 + 16 + o4);
      float4 r;
      r.x = w1.z*(w1.x*A00.x + w1.y*A01.x) + w1.w*(w1.x*A10.x + w1.y*A11.x)
          + w0.z*(w0.x*B00.x + w0.y*B01.x) + w0.w*(w0.x*B10.x + w0.y*B11.x);
      r.y = w1.z*(w1.x*A00.y + w1.y*A01.y) + w1.w*(w1.x*A10.y + w1.y*A11.y)
          + w0.z*(w0.x*B00.y + w0.y*B01.y) + w0.w*(w0.x*B10.y + w0.y*B11.y);
      r.z = w1.z*(w1.x*A00.z + w1.y*A01.z) + w1.w*(w1.x*A10.z + w1.y*A11.z)
          + w0.z*(w0.x*B00.z + w0.y*B01.z) + w0.w*(w0.x*B10.z + w0.y*B11.z);
      r.w = w1.z*(w1.x*A00.w + w1.y*A01.w) + w1.w*(w1.x*A10.w + w1.y*A11.w)
          + w0.z*(w0.x*B00.w + w0.y*B01.w) + w0.w*(w0.x*B10.w + w0.y*B11.w);
      int o0 = o4*4;
      r.x += s_fb[o0]; r.y += s_fb[o0+1]; r.z += s_fb[o0+2]; r.w += s_fb[o0+3];
      const float* Mp = s_M + pw*512;
      #pragma unroll
      for (int j = 0; j < 8; j++) {
        float tj = s_t[j*64 + px];
        float4 m4 = *(const float4*)&Mp[j*64 + o0];
        r.x = fmaf(m4.x, tj, r.x);
        r.y = fmaf(m4.y, tj, r.y);
        r.z = fmaf(m4.z, tj, r.z);
        r.w = fmaf(m4.w, tj, r.w);
      }
      float* op = out + ((size_t)(b*CC + o0)*HOUT + Y)*WOUT + X0 + px;
      op[0]            = r.x;
      op[HOUT*WOUT]    = r.y;
      op[2*HOUT*WOUT]  = r.z;
      op[3*HOUT*WOUT]  = r.w;
    }
  }
}

// ---------------------------------------------------------------------------
extern "C" void kernel_launch(void* const* d_in, const int* in_sizes, int n_in,
                              void* d_out, int out_size) {
  const float* x    = (const float*)d_in[0];
  const float* st   = (const float*)d_in[1];
  const float* kcw  = (const float*)d_in[2];
  const float* kcb  = (const float*)d_in[3];
  const float* wc   = (const float*)d_in[4];
  const float* we   = (const float*)d_in[5];
  const float* b1w  = (const float*)d_in[6];
  const float* b1b  = (const float*)d_in[7];
  const float* b2w  = (const float*)d_in[8];
  const float* b2b  = (const float*)d_in[9];
  const float* rw   = (const float*)d_in[10];
  const float* rb   = (const float*)d_in[11];
  const float* ow   = (const float*)d_in[12];
  const float* ob   = (const float*)d_in[13];
  const float* sow  = (const float*)d_in[14];
  const float* sob  = (const float*)d_in[15];
  const float* fusw = (const float*)d_in[16];
  const float* fusb = (const float*)d_in[17];
  float* out = (float*)d_out;

  const int smem2 = K2_SMEM_FLOATS * 4;
  const int smemb = K2B_SMEM_FLOATS * 4;
  cudaFuncSetAttribute(k2_sta_mma, cudaFuncAttributeMaxDynamicSharedMemorySize, smem2);
  cudaFuncSetAttribute(k2b_gemm,   cudaFuncAttributeMaxDynamicSharedMemorySize, smemb);

  k01_prep<<<104, 256>>>(kcw, b1w, b1b, b2w, b2b, rw, rb, ow, ob, sow, sob, wc, we, fusw);
  k2x_transpose<<<dim3(NPX/32, 2, BB), 256>>>(x);
  k2_sta_mma<<<dim3(WIN/32, HIN/2, BB), 256, smem2>>>(x, st, kcb);
  k2b_gemm<<<dim3(NPX/128, BB, 2), 256, smemb>>>(x, fusw);
  k3_fuse<<<dim3(WOUT/64, HOUT, BB), 256>>>(fusb, out);
}

// round 8
// speedup vs baseline: 1.2250x; 1.0294x over previous
#include <cuda_runtime.h>
#include <cuda_bf16.h>
#include <cstdint>

#define BB 4
#define CC 64
#define HIN 96
#define WIN 96
#define HOUT 192
#define WOUT 192
#define NPX (HIN*WIN)          // 9216

// Scratch + precomputed data (allocation-free rule: device globals)
__device__ float g_sta[BB*CC*NPX];       // sta_feat  [b][c][96][96]
__device__ float g_A[BB*NPX*CC];         // fusL@sta, channel-last [b][px][64]
__device__ float g_B[BB*NPX*CC];         // fusR@x,   channel-last
__device__ float g_X[BB*NPX*CC];         // x transposed, channel-last
__device__ float g_off[4][2];
__device__ float g_stoff[4][2];
__device__ float g_wcpx[4][512];         // [o*64+c]
__device__ float g_M[4][512];            // [j*64+o]  (fusR @ we_par)
// kc_w repacked: [t 25][q 8][ks 4][lane 32] uint4 = (b0h, b1h, b0l, b1l) bf16x2
__device__ uint4 g_b[25600];

// ============================ helpers ======================================
__device__ __forceinline__ uint32_t smem_u32(const void* p) {
  uint32_t a;
  asm("{ .reg .u64 t; cvta.to.shared.u64 t, %1; cvt.u32.u64 %0, t; }" : "=r"(a) : "l"(p));
  return a;
}
__device__ __forceinline__ void cp16(uint32_t dst, const float* src) {
  asm volatile("cp.async.cg.shared.global [%0], [%1], 16;" :: "r"(dst), "l"(src));
}
#define CP_COMMIT() asm volatile("cp.async.commit_group;" ::: "memory")
#define CP_WAIT0()  asm volatile("cp.async.wait_group 0;" ::: "memory")

// bf16 hi/lo split of two floats, packed as bf16x2
__device__ __forceinline__ uint32_t bf16_split2(float v0, float v1, uint32_t& lo_out) {
  __nv_bfloat162 h = __floats2bfloat162_rn(v0, v1);
  float r0 = v0 - __bfloat162float(h.x);
  float r1 = v1 - __bfloat162float(h.y);
  __nv_bfloat162 lo = __floats2bfloat162_rn(r0, r1);
  lo_out = *(uint32_t*)&lo;
  return *(uint32_t*)&h;
}

#define MMA_BF16(d, a, b0v, b1v) \
  asm volatile("mma.sync.aligned.m16n8k16.row.col.f32.bf16.bf16.f32 " \
      "{%0,%1,%2,%3}, {%4,%5,%6,%7}, {%8,%9}, {%0,%1,%2,%3};" \
      : "+f"((d)[0]), "+f"((d)[1]), "+f"((d)[2]), "+f"((d)[3]) \
      : "r"((a)[0]), "r"((a)[1]), "r"((a)[2]), "r"((a)[3]), "r"(b0v), "r"(b1v))

// ---------------------------------------------------------------------------
// K01: blocks 0..99 repack kc_w -> bf16 hi/lo fragments; blocks 100..103 parity
// ---------------------------------------------------------------------------
__global__ void k01_prep(const float* __restrict__ kcw,
                         const float* __restrict__ b1w, const float* __restrict__ b1b,
                         const float* __restrict__ b2w, const float* __restrict__ b2b,
                         const float* __restrict__ rw,  const float* __restrict__ rb,
                         const float* __restrict__ ow,  const float* __restrict__ ob,
                         const float* __restrict__ sow, const float* __restrict__ sob,
                         const float* __restrict__ wc,  const float* __restrict__ we,
                         const float* __restrict__ fusw) {
  const int tid = threadIdx.x;
  if (blockIdx.x < 100) {
    int idx = blockIdx.x*256 + tid;          // 0..25599
    int l  = idx & 31;
    int ks = (idx >> 5) & 3;
    int q  = (idx >> 7) & 7;
    int t  = idx >> 10;
    int g = l >> 2, tg = l & 3;
    int c  = q*8 + g;
    int k0 = ks*16 + 2*tg;
    const float* row = kcw + (c*25 + t)*64;
    float v0 = row[k0], v1 = row[k0 + 1], v2 = row[k0 + 8], v3 = row[k0 + 9];
    uint32_t l01, l23;
    uint32_t h01 = bf16_split2(v0, v1, l01);
    uint32_t h23 = bf16_split2(v2, v3, l23);
    g_b[idx] = make_uint4(h01, h23, l01, l23);
    return;
  }
  // ---- parity branch ----
  __shared__ float hid[64], emb[64], r[4];
  __shared__ float s_we2[512];     // we_px [c*8+j]
  __shared__ float s_fr[64*65];    // fusR^T [c][o] padded
  const int ci = blockIdx.x - 100;
  const float in2 = (ci >> 1) ? 0.25f : -0.25f;
  const float in3 = (ci & 1)  ? 0.25f : -0.25f;

  for (int e = tid; e < 4096; e += 256) {
    int o = e >> 6, c = e & 63;
    s_fr[c*65 + o] = fusw[o*128 + 64 + c];
  }
  if (tid < 64) {
    float a = b1b[tid] + 0.5f*b1w[tid*4+0] + 0.5f*b1w[tid*4+1]
            + in2*b1w[tid*4+2] + in3*b1w[tid*4+3];
    hid[tid] = fmaxf(a, 0.f);
  }
  __syncthreads();
  if (tid < 64) {
    float a = b2b[tid];
    #pragma unroll 8
    for (int k = 0; k < 64; k++) a = fmaf(b2w[tid*64+k], hid[k], a);
    emb[tid] = fmaxf(a, 0.f);
  }
  __syncthreads();
  if (tid < 4) {
    float a = rb[tid];
    for (int k = 0; k < 64; k++) a = fmaf(rw[tid*64+k], emb[k], a);
    r[tid] = 1.f / (1.f + expf(-a));
  } else if (tid < 6) {
    int t = tid - 4; float a = ob[t];
    for (int k = 0; k < 64; k++) a = fmaf(ow[t*64+k], emb[k], a);
    g_off[ci][t] = a;
  } else if (tid < 8) {
    int t = tid - 6; float a = sob[t];
    for (int k = 0; k < 64; k++) a = fmaf(sow[t*64+k], emb[k], a);
    g_stoff[ci][t] = a;
  }
  __syncthreads();
  for (int e = tid; e < 512; e += 256) {
    float a = 0.f, bsum = 0.f;
    #pragma unroll
    for (int ex = 0; ex < 4; ex++) {
      a    = fmaf(r[ex], wc[ex*512+e], a);
      bsum = fmaf(r[ex], we[ex*512+e], bsum);
    }
    g_wcpx[ci][e] = a;
    s_we2[e] = bsum;
  }
  __syncthreads();
  for (int e = tid; e < 512; e += 256) {
    int j = e >> 6, o = e & 63;
    float a = 0.f;
    #pragma unroll 8
    for (int c = 0; c < 64; c++) a = fmaf(s_fr[c*65 + o], s_we2[c*8 + j], a);
    g_M[ci][j*64 + o] = a;
  }
}

// ---------------------------------------------------------------------------
// K2X: transpose x [b][64][9216] -> g_X [b][9216][64]  (channel-last)
// ---------------------------------------------------------------------------
__global__ __launch_bounds__(256) void k2x_transpose(const float* __restrict__ x) {
  __shared__ float tile[32][33];
  const int b = blockIdx.z, c0 = blockIdx.y*32, px0 = blockIdx.x*32;
  const int tx = threadIdx.x & 31, ty = threadIdx.x >> 5;
  #pragma unroll
  for (int i = 0; i < 4; i++)
    tile[ty + i*8][tx] = x[((size_t)(b*CC + c0 + ty + i*8))*NPX + px0 + tx];
  __syncthreads();
  #pragma unroll
  for (int i = 0; i < 4; i++) {
    int pxl = ty + i*8;
    g_X[((size_t)b*NPX + px0 + pxl)*CC + c0 + tx] = tile[tx][pxl];
  }
}

// ---------------------------------------------------------------------------
// K2 v5 (mma.sync bf16 m16n8k16, 3-term hi/lo, 2-stage cp.async pipeline):
// fused kernel_warp GEMM + 25-tap sta conv.
// Block: 256 thr / 8 warps, tile (b, 2 rows, 32 px), M=64.
// Pipeline per tap: wait(t) -> sync -> issue(t+1) -> mma+epilogue(t).
// ---------------------------------------------------------------------------
// floats: s_b 2*4096 (2x16KB), s_a 4224, s_x 13824, s_kb 1600
#define K2_SMEM_FLOATS (8192 + 4224 + 13824 + 1600)

__global__ __launch_bounds__(256, 2) void k2_sta_mma(const float* __restrict__ x,
                                                     const float* __restrict__ st,
                                                     const float* __restrict__ kcb) {
  extern __shared__ float sm[];
  float* s_b  = sm;                // [2][1024 uint4]: [q 8][ks 4][lane 32]
  float* s_a  = sm + 8192;         // [k 64][px 64 pad66]
  float* s_x  = sm + 12416;        // [c 64][row 6][col 36]
  float* s_kb = sm + 26240;        // [1600]

  const int b = blockIdx.z, h0 = blockIdx.y*2, w0 = blockIdx.x*32;
  const int tid = threadIdx.x, wid = tid >> 5, l = tid & 31;
  const int g = l >> 2, tg = l & 3;
  const int mt = wid & 3, nth = wid >> 2;
  const uint32_t sb = smem_u32(s_b);

  // ---- prologue: issue B load for tap 0 into buf 0 ----
  {
    const float* src = (const float*)(g_b + 0*1024);
    #pragma unroll
    for (int i = 0; i < 4; i++) {
      int j = tid + i*256;
      cp16(sb + (uint32_t)j*16u, src + j*4);
    }
    CP_COMMIT();
  }

  for (int e = tid; e < 4096; e += 256) {
    int k = e >> 6, px = e & 63;
    s_a[k*66 + px] = st[((b*CC + k)*HIN + h0 + (px >> 5))*WIN + w0 + (px & 31)];
  }
  for (int e = tid; e < 64*6*36; e += 256) {
    int col = e % 36; int row = (e / 36) % 6; int c = e / 216;
    int gy = min(max(h0 - 2 + row, 0), HIN - 1);
    int gx = min(max(w0 - 2 + col, 0), WIN - 1);
    s_x[e] = x[((b*CC + c)*HIN + gy)*WIN + gx];
  }
  for (int e = tid; e < 1600; e += 256) s_kb[e] = kcb[e];
  __syncthreads();

  // ---- A fragments (bf16 hi/lo), tap-invariant: [ks 4][4 regs] ----
  uint32_t ahi[4][4], alo[4][4];
  {
    const int pxg = mt*16 + g, pxg8 = pxg + 8;
    #pragma unroll
    for (int ks = 0; ks < 4; ks++) {
      int kb = ks*16 + 2*tg;
      ahi[ks][0] = bf16_split2(s_a[kb*66 + pxg],      s_a[(kb+1)*66 + pxg],  alo[ks][0]);
      ahi[ks][1] = bf16_split2(s_a[kb*66 + pxg8],     s_a[(kb+1)*66 + pxg8], alo[ks][1]);
      ahi[ks][2] = bf16_split2(s_a[(kb+8)*66 + pxg],  s_a[(kb+9)*66 + pxg],  alo[ks][2]);
      ahi[ks][3] = bf16_split2(s_a[(kb+8)*66 + pxg8], s_a[(kb+9)*66 + pxg8], alo[ks][3]);
    }
  }

  float sacc[16];
  #pragma unroll
  for (int i = 0; i < 16; i++) sacc[i] = 0.f;

  const int prow  = mt >> 1;
  const int pcol0 = (mt & 1)*16 + g;

  for (int t = 0; t < 25; t++) {
    const int buf = t & 1;
    // wait for this tap's B; barrier also retires all reads of the other buf
    CP_WAIT0();
    __syncthreads();
    // issue next tap's B into the other buffer (overlaps with compute below)
    if (t < 24) {
      const float* src = (const float*)(g_b + (t + 1)*1024);
      const uint32_t nb = sb + (uint32_t)(1 - buf)*16384u;
      #pragma unroll
      for (int i = 0; i < 4; i++) {
        int j = tid + i*256;
        cp16(nb + (uint32_t)j*16u, src + j*4);
      }
      CP_COMMIT();
    }

    const int rr = t / 5, dw = t - rr*5;

    float d[4][4];
    #pragma unroll
    for (int n = 0; n < 4; n++) {
      int c0 = ((nth*4 + n)*8 + 2*tg)*25 + t;
      d[n][0] = s_kb[c0];      d[n][1] = s_kb[c0 + 25];
      d[n][2] = d[n][0];       d[n][3] = d[n][1];
    }

    const uint4* bb = (const uint4*)(s_b + buf*4096);
    #pragma unroll
    for (int ks = 0; ks < 4; ks++) {
      #pragma unroll
      for (int n = 0; n < 4; n++) {
        uint4 bv = bb[((nth*4 + n)*4 + ks)*32 + l];
        MMA_BF16(d[n], ahi[ks], bv.x, bv.y);   // hi*hi
        MMA_BF16(d[n], ahi[ks], bv.z, bv.w);   // hi*lo
        MMA_BF16(d[n], alo[ks], bv.x, bv.y);   // lo*hi
      }
    }

    // epilogue: lrelu(gate) * x_halo, accumulate
    #pragma unroll
    for (int n = 0; n < 4; n++) {
      int cb = (nth*4 + n)*8 + 2*tg;
      #pragma unroll
      for (int j = 0; j < 4; j++) {
        int c  = cb + (j & 1);
        int px = pcol0 + (j >> 1)*8;
        float gv = d[n][j];
        float lv = fmaf(0.45f, fabsf(gv), 0.55f*gv);
        float xv = s_x[c*216 + (prow + rr)*36 + px + dw];
        sacc[n*4 + j] = fmaf(lv, xv, sacc[n*4 + j]);
      }
    }
  }

  #pragma unroll
  for (int n = 0; n < 4; n++) {
    int cb = (nth*4 + n)*8 + 2*tg;
    #pragma unroll
    for (int j = 0; j < 4; j++) {
      int c  = cb + (j & 1);
      int px = pcol0 + (j >> 1)*8;
      g_sta[((b*CC + c)*HIN + h0 + prow)*WIN + w0 + px] = sacc[n*4 + j];
    }
  }
}

// ---------------------------------------------------------------------------
// K2B: LR GEMMs  A = fusL @ sta,  B = fusR @ x, output channel-last.
// ---------------------------------------------------------------------------
#define K2B_SMEM_FLOATS (8192 + 64*68)

__global__ __launch_bounds__(256, 4) void k2b_gemm(const float* __restrict__ x,
                                                   const float* __restrict__ fusw) {
  extern __shared__ float sm[];
  float* s_src = sm;           // [k 64][px 128]
  float* s_wT  = sm + 8192;    // [k 64][o 64 pad68]

  const int px0 = blockIdx.x*128, b = blockIdx.y, mat = blockIdx.z;
  const int tid = threadIdx.x;
  const float* src = mat ? (x + (size_t)b*CC*NPX) : (g_sta + (size_t)b*CC*NPX);
  const int mo = mat ? 64 : 0;
  float* dst = (mat ? g_B : g_A) + (size_t)b*NPX*CC;

  for (int e = tid; e < 8192; e += 256) {
    int k = e >> 7, p = e & 127;
    s_src[e] = src[(size_t)k*NPX + px0 + p];
  }
  for (int e = tid; e < 4096; e += 256) {
    int o = e >> 6, k = e & 63;
    s_wT[k*68 + o] = fusw[o*128 + mo + k];
  }
  __syncthreads();

  const int o0 = (tid & 15)*4, p0 = (tid >> 4)*8;
  float4 acc[8];
  #pragma unroll
  for (int i = 0; i < 8; i++) acc[i] = make_float4(0.f, 0.f, 0.f, 0.f);

  #pragma unroll 4
  for (int k = 0; k < 64; k++) {
    float4 w4 = *(const float4*)&s_wT[k*68 + o0];
    const float* sr = s_src + k*128 + p0;
    #pragma unroll
    for (int pp = 0; pp < 8; pp++) {
      float s = sr[pp];
      acc[pp].x = fmaf(w4.x, s, acc[pp].x);
      acc[pp].y = fmaf(w4.y, s, acc[pp].y);
      acc[pp].z = fmaf(w4.z, s, acc[pp].z);
      acc[pp].w = fmaf(w4.w, s, acc[pp].w);
    }
  }
  #pragma unroll
  for (int pp = 0; pp < 8; pp++)
    *(float4*)&dst[(size_t)(px0 + p0 + pp)*CC + o0] = acc[pp];
}

// ---------------------------------------------------------------------------
// K3 v3: out = bilin_stoff(A) + bilin_off(B) + M_par @ (wc_par @ bilin_off(X)) + fus_b
// ---------------------------------------------------------------------------
__global__ __launch_bounds__(256, 4) void k3_fuse(const float* __restrict__ fusb,
                                                  float* __restrict__ out) {
  __shared__ float  s_fea[4096];   // [c][64px]
  __shared__ float  s_t[512];      // [j][64px]
  __shared__ float  s_wc[1024];    // [pw][o*64+c]
  __shared__ float  s_M[1024];     // [pw][j*64+o]
  __shared__ float  s_fb[64];
  __shared__ int2   s_gi[128];     // [img][px]
  __shared__ float4 s_gw[128];     // (wxa, wxb, wy0, wy1)

  const int b = blockIdx.z, Y = blockIdx.y, X0 = blockIdx.x * 64;
  const int tid = threadIdx.x;
  const int ph = Y & 1;

  for (int e = tid; e < 1024; e += 256) {
    int pw = e >> 9, i = e & 511;
    s_wc[pw*512 + i] = g_wcpx[ph*2 + pw][i];
    s_M[pw*512 + i]  = g_M[ph*2 + pw][i];
  }
  if (tid < 64) s_fb[tid] = fusb[tid];
  if (tid < 128) {
    int img = tid >> 6, px = tid & 63;
    int X = X0 + px; int ci = ph*2 + (X & 1);
    float offx = img ? g_stoff[ci][0] : g_off[ci][0];
    float offy = img ? g_stoff[ci][1] : g_off[ci][1];
    float pxf = (X + 0.5f)*0.5f - 0.5f + offx;
    float pyf = (Y + 0.5f)*0.5f - 0.5f + offy;
    float xf = floorf(pxf), yf = floorf(pyf);
    int ix0 = (int)xf, iy0 = (int)yf;
    float fx = pxf - xf, fy = pyf - yf;
    int cb = min(max(ix0, 0), WIN - 2);
    float wxa = 0.f, wxb = 0.f;
    if (ix0 >= 0 && ix0 <= WIN - 2)      { wxa = 1.f - fx; wxb = fx; }
    else if (ix0 == -1)                  { wxa = fx; }
    else if (ix0 == WIN - 1)             { wxb = 1.f - fx; }
    int ry0 = min(max(iy0, 0), HIN - 1), ry1 = min(max(iy0 + 1, 0), HIN - 1);
    float wy0 = (iy0 >= 0 && iy0 <= HIN - 1) ? (1.f - fy) : 0.f;
    float wy1 = (iy0 + 1 >= 0 && iy0 + 1 <= HIN - 1) ? fy : 0.f;
    s_gi[tid] = make_int2(ry0*WIN + cb, ry1*WIN + cb);
    s_gw[tid] = make_float4(wxa, wxb, wy0, wy1);
  }
  __syncthreads();

  // P1: fea0 = bilin_off(X)
  {
    const float4* P = (const float4*)g_X + (size_t)b*NPX*16;
    for (int u = tid; u < 1024; u += 256) {
      int px = u & 63, c4 = u >> 6;
      int2 gi = s_gi[px];
      float4 w = s_gw[px];
      float4 a0 = __ldg(P + gi.x*16 + c4);
      float4 a1 = __ldg(P + gi.x*16 + 16 + c4);
      float4 b0 = __ldg(P + gi.y*16 + c4);
      float4 b1 = __ldg(P + gi.y*16 + 16 + c4);
      float4 v;
      v.x = w.z*(w.x*a0.x + w.y*a1.x) + w.w*(w.x*b0.x + w.y*b1.x);
      v.y = w.z*(w.x*a0.y + w.y*a1.y) + w.w*(w.x*b0.y + w.y*b1.y);
      v.z = w.z*(w.x*a0.z + w.y*a1.z) + w.w*(w.x*b0.z + w.y*b1.z);
      v.w = w.z*(w.x*a0.w + w.y*a1.w) + w.w*(w.x*b0.w + w.y*b1.w);
      int c = c4*4;
      s_fea[c*64 + px]     = v.x;
      s_fea[(c+1)*64 + px] = v.y;
      s_fea[(c+2)*64 + px] = v.z;
      s_fea[(c+3)*64 + px] = v.w;
    }
  }
  __syncthreads();

  // P2: t[j][px] = wc_par . fea0
  for (int e = tid; e < 512; e += 256) {
    int j = e >> 6, px = e & 63, pw = px & 1;
    const float* wr = s_wc + pw*512 + j*64;
    float a = 0.f;
    #pragma unroll 8
    for (int c = 0; c < 64; c++) a = fmaf(wr[c], s_fea[c*64 + px], a);
    s_t[j*64 + px] = a;
  }
  __syncthreads();

  // P3: out = bilinA + bilinB + M.t + bias
  {
    const float4* PA = (const float4*)g_A + (size_t)b*NPX*16;
    const float4* PB = (const float4*)g_B + (size_t)b*NPX*16;
    for (int u = tid; u < 1024; u += 256) {
      int px = u & 63, o4 = u >> 6, pw = px & 1;
      int2 gi1 = s_gi[64 + px]; float4 w1 = s_gw[64 + px];
      float4 A00 = __ldg(PA + gi1.x*16 + o4);
      float4 A01 = __ldg(PA + gi1.x*16 + 16 + o4);
      float4 A10 = __ldg(PA + gi1.y*16 + o4);
      float4 A11 = __ldg(PA + gi1.y*16 + 16 + o4);
      int2 gi0 = s_gi[px]; float4 w0 = s_gw[px];
      float4 B00 = __ldg(PB + gi0.x*16 + o4);
      float4 B01 = __ldg(PB + gi0.x*16 + 16 + o4);
      float4 B10 = __ldg(PB + gi0.y*16 + o4);
      float4 B11 = __ldg(PB + gi0.y*16 + 16 + o4);
      float4 r;
      r.x = w1.z*(w1.x*A00.x + w1.y*A01.x) + w1.w*(w1.x*A10.x + w1.y*A11.x)
          + w0.z*(w0.x*B00.x + w0.y*B01.x) + w0.w*(w0.x*B10.x + w0.y*B11.x);
      r.y = w1.z*(w1.x*A00.y + w1.y*A01.y) + w1.w*(w1.x*A10.y + w1.y*A11.y)
          + w0.z*(w0.x*B00.y + w0.y*B01.y) + w0.w*(w0.x*B10.y + w0.y*B11.y);
      r.z = w1.z*(w1.x*A00.z + w1.y*A01.z) + w1.w*(w1.x*A10.z + w1.y*A11.z)
          + w0.z*(w0.x*B00.z + w0.y*B01.z) + w0.w*(w0.x*B10.z + w0.y*B11.z);
      r.w = w1.z*(w1.x*A00.w + w1.y*A01.w) + w1.w*(w1.x*A10.w + w1.y*A11.w)
          + w0.z*(w0.x*B00.w + w0.y*B01.w) + w0.w*(w0.x*B10.w + w0.y*B11.w);
      int o0 = o4*4;
      r.x += s_fb[o0]; r.y += s_fb[o0+1]; r.z += s_fb[o0+2]; r.w += s_fb[o0+3];
      const float* Mp = s_M + pw*512;
      #pragma unroll
      for (int j = 0; j < 8; j++) {
        float tj = s_t[j*64 + px];
        float4 m4 = *(const float4*)&Mp[j*64 + o0];
        r.x = fmaf(m4.x, tj, r.x);
        r.y = fmaf(m4.y, tj, r.y);
        r.z = fmaf(m4.z, tj, r.z);
        r.w = fmaf(m4.w, tj, r.w);
      }
      float* op = out + ((size_t)(b*CC + o0)*HOUT + Y)*WOUT + X0 + px;
      op[0]            = r.x;
      op[HOUT*WOUT]    = r.y;
      op[2*HOUT*WOUT]  = r.z;
      op[3*HOUT*WOUT]  = r.w;
    }
  }
}

// ---------------------------------------------------------------------------
extern "C" void kernel_launch(void* const* d_in, const int* in_sizes, int n_in,
                              void* d_out, int out_size) {
  const float* x    = (const float*)d_in[0];
  const float* st   = (const float*)d_in[1];
  const float* kcw  = (const float*)d_in[2];
  const float* kcb  = (const float*)d_in[3];
  const float* wc   = (const float*)d_in[4];
  const float* we   = (const float*)d_in[5];
  const float* b1w  = (const float*)d_in[6];
  const float* b1b  = (const float*)d_in[7];
  const float* b2w  = (const float*)d_in[8];
  const float* b2b  = (const float*)d_in[9];
  const float* rw   = (const float*)d_in[10];
  const float* rb   = (const float*)d_in[11];
  const float* ow   = (const float*)d_in[12];
  const float* ob   = (const float*)d_in[13];
  const float* sow  = (const float*)d_in[14];
  const float* sob  = (const float*)d_in[15];
  const float* fusw = (const float*)d_in[16];
  const float* fusb = (const float*)d_in[17];
  float* out = (float*)d_out;

  const int smem2 = K2_SMEM_FLOATS * 4;
  const int smemb = K2B_SMEM_FLOATS * 4;
  cudaFuncSetAttribute(k2_sta_mma, cudaFuncAttributeMaxDynamicSharedMemorySize, smem2);
  cudaFuncSetAttribute(k2b_gemm,   cudaFuncAttributeMaxDynamicSharedMemorySize, smemb);

  k01_prep<<<104, 256>>>(kcw, b1w, b1b, b2w, b2b, rw, rb, ow, ob, sow, sob, wc, we, fusw);
  k2x_transpose<<<dim3(NPX/32, 2, BB), 256>>>(x);
  k2_sta_mma<<<dim3(WIN/32, HIN/2, BB), 256, smem2>>>(x, st, kcb);
  k2b_gemm<<<dim3(NPX/128, BB, 2), 256, smemb>>>(x, fusw);
  k3_fuse<<<dim3(WOUT/64, HOUT, BB), 256>>>(fusb, out);
}

// round 9
// speedup vs baseline: 1.3634x; 1.1130x over previous
#include <cuda_runtime.h>
#include <cuda_bf16.h>
#include <cstdint>

#define BB 4
#define CC 64
#define HIN 96
#define WIN 96
#define HOUT 192
#define WOUT 192
#define NPX (HIN*WIN)          // 9216

// Scratch + precomputed data (allocation-free rule: device globals)
__device__ float g_sta[BB*CC*NPX];       // sta_feat  [b][c][96][96]
__device__ float g_A[BB*NPX*CC];         // fusL@sta, channel-last [b][px][64]
__device__ float g_B[BB*NPX*CC];         // fusR@x,   channel-last
__device__ float g_X[BB*NPX*CC];         // x transposed, channel-last
__device__ float g_U[BB*4*NPX*8];        // wc_ci @ X, [b][ci][src][8]
__device__ float g_off[4][2];
__device__ float g_stoff[4][2];
__device__ float g_wcpx[4][512];         // [j*64+c]
__device__ float g_M[4][512];            // [j*64+o]  (fusR @ we_par)
// kc_w repacked: [t 25][q 8][ks 4][lane 32] uint4 = (b0h, b1h, b0l, b1l) bf16x2
__device__ uint4 g_b[25600];

// ============================ helpers ======================================
__device__ __forceinline__ uint32_t smem_u32(const void* p) {
  uint32_t a;
  asm("{ .reg .u64 t; cvta.to.shared.u64 t, %1; cvt.u32.u64 %0, t; }" : "=r"(a) : "l"(p));
  return a;
}
__device__ __forceinline__ void cp16(uint32_t dst, const float* src) {
  asm volatile("cp.async.cg.shared.global [%0], [%1], 16;" :: "r"(dst), "l"(src));
}
#define CP_COMMIT() asm volatile("cp.async.commit_group;" ::: "memory")
#define CP_WAIT0()  asm volatile("cp.async.wait_group 0;" ::: "memory")

__device__ __forceinline__ uint32_t bf16_split2(float v0, float v1, uint32_t& lo_out) {
  __nv_bfloat162 h = __floats2bfloat162_rn(v0, v1);
  float r0 = v0 - __bfloat162float(h.x);
  float r1 = v1 - __bfloat162float(h.y);
  __nv_bfloat162 lo = __floats2bfloat162_rn(r0, r1);
  lo_out = *(uint32_t*)&lo;
  return *(uint32_t*)&h;
}

#define MMA_BF16(d, a, b0v, b1v) \
  asm volatile("mma.sync.aligned.m16n8k16.row.col.f32.bf16.bf16.f32 " \
      "{%0,%1,%2,%3}, {%4,%5,%6,%7}, {%8,%9}, {%0,%1,%2,%3};" \
      : "+f"((d)[0]), "+f"((d)[1]), "+f"((d)[2]), "+f"((d)[3]) \
      : "r"((a)[0]), "r"((a)[1]), "r"((a)[2]), "r"((a)[3]), "r"(b0v), "r"(b1v))

__device__ __forceinline__ float4 f4maf(float s, float4 a, float4 r) {
  r.x = fmaf(s, a.x, r.x); r.y = fmaf(s, a.y, r.y);
  r.z = fmaf(s, a.z, r.z); r.w = fmaf(s, a.w, r.w);
  return r;
}

// ---------------------------------------------------------------------------
// K01: blocks 0..99 repack kc_w -> bf16 hi/lo fragments; blocks 100..103 parity
// ---------------------------------------------------------------------------
__global__ void k01_prep(const float* __restrict__ kcw,
                         const float* __restrict__ b1w, const float* __restrict__ b1b,
                         const float* __restrict__ b2w, const float* __restrict__ b2b,
                         const float* __restrict__ rw,  const float* __restrict__ rb,
                         const float* __restrict__ ow,  const float* __restrict__ ob,
                         const float* __restrict__ sow, const float* __restrict__ sob,
                         const float* __restrict__ wc,  const float* __restrict__ we,
                         const float* __restrict__ fusw) {
  const int tid = threadIdx.x;
  if (blockIdx.x < 100) {
    int idx = blockIdx.x*256 + tid;
    int l  = idx & 31;
    int ks = (idx >> 5) & 3;
    int q  = (idx >> 7) & 7;
    int t  = idx >> 10;
    int g = l >> 2, tg = l & 3;
    int c  = q*8 + g;
    int k0 = ks*16 + 2*tg;
    const float* row = kcw + (c*25 + t)*64;
    float v0 = row[k0], v1 = row[k0 + 1], v2 = row[k0 + 8], v3 = row[k0 + 9];
    uint32_t l01, l23;
    uint32_t h01 = bf16_split2(v0, v1, l01);
    uint32_t h23 = bf16_split2(v2, v3, l23);
    g_b[idx] = make_uint4(h01, h23, l01, l23);
    return;
  }
  __shared__ float hid[64], emb[64], r[4];
  __shared__ float s_we2[512];
  __shared__ float s_fr[64*65];
  const int ci = blockIdx.x - 100;
  const float in2 = (ci >> 1) ? 0.25f : -0.25f;
  const float in3 = (ci & 1)  ? 0.25f : -0.25f;

  for (int e = tid; e < 4096; e += 256) {
    int o = e >> 6, c = e & 63;
    s_fr[c*65 + o] = fusw[o*128 + 64 + c];
  }
  if (tid < 64) {
    float a = b1b[tid] + 0.5f*b1w[tid*4+0] + 0.5f*b1w[tid*4+1]
            + in2*b1w[tid*4+2] + in3*b1w[tid*4+3];
    hid[tid] = fmaxf(a, 0.f);
  }
  __syncthreads();
  if (tid < 64) {
    float a = b2b[tid];
    #pragma unroll 8
    for (int k = 0; k < 64; k++) a = fmaf(b2w[tid*64+k], hid[k], a);
    emb[tid] = fmaxf(a, 0.f);
  }
  __syncthreads();
  if (tid < 4) {
    float a = rb[tid];
    for (int k = 0; k < 64; k++) a = fmaf(rw[tid*64+k], emb[k], a);
    r[tid] = 1.f / (1.f + expf(-a));
  } else if (tid < 6) {
    int t = tid - 4; float a = ob[t];
    for (int k = 0; k < 64; k++) a = fmaf(ow[t*64+k], emb[k], a);
    g_off[ci][t] = a;
  } else if (tid < 8) {
    int t = tid - 6; float a = sob[t];
    for (int k = 0; k < 64; k++) a = fmaf(sow[t*64+k], emb[k], a);
    g_stoff[ci][t] = a;
  }
  __syncthreads();
  for (int e = tid; e < 512; e += 256) {
    float a = 0.f, bsum = 0.f;
    #pragma unroll
    for (int ex = 0; ex < 4; ex++) {
      a    = fmaf(r[ex], wc[ex*512+e], a);
      bsum = fmaf(r[ex], we[ex*512+e], bsum);
    }
    g_wcpx[ci][e] = a;
    s_we2[e] = bsum;
  }
  __syncthreads();
  for (int e = tid; e < 512; e += 256) {
    int j = e >> 6, o = e & 63;
    float a = 0.f;
    #pragma unroll 8
    for (int c = 0; c < 64; c++) a = fmaf(s_fr[c*65 + o], s_we2[c*8 + j], a);
    g_M[ci][j*64 + o] = a;
  }
}

// ---------------------------------------------------------------------------
// K2X: transpose x [b][64][9216] -> g_X [b][9216][64]  (channel-last)
// ---------------------------------------------------------------------------
__global__ __launch_bounds__(256) void k2x_transpose(const float* __restrict__ x) {
  __shared__ float tile[32][33];
  const int b = blockIdx.z, c0 = blockIdx.y*32, px0 = blockIdx.x*32;
  const int tx = threadIdx.x & 31, ty = threadIdx.x >> 5;
  #pragma unroll
  for (int i = 0; i < 4; i++)
    tile[ty + i*8][tx] = x[((size_t)(b*CC + c0 + ty + i*8))*NPX + px0 + tx];
  __syncthreads();
  #pragma unroll
  for (int i = 0; i < 4; i++) {
    int pxl = ty + i*8;
    g_X[((size_t)b*NPX + px0 + pxl)*CC + c0 + tx] = tile[tx][pxl];
  }
}

// ---------------------------------------------------------------------------
// K2U: U[b][ci][src][8] = wc_ci @ X[src]   (channel contraction pre-interp)
// grid (72, BB), 256 thr. thread = (px 128, half 2) -> 2 ci x 8 j dots.
// ---------------------------------------------------------------------------
__global__ __launch_bounds__(256, 4) void k2u_gemm() {
  __shared__ float sX[128*68];
  __shared__ float swc[2048];
  const int px0 = blockIdx.x*128, b = blockIdx.y;
  const int tid = threadIdx.x;
  const float4* X4 = (const float4*)g_X + (size_t)(b*NPX + px0)*16;
  for (int e = tid; e < 2048; e += 256) {
    int px = e >> 4, c4 = e & 15;
    *(float4*)&sX[px*68 + c4*4] = X4[px*16 + c4];
  }
  for (int e = tid; e < 2048; e += 256) swc[e] = g_wcpx[e >> 9][e & 511];
  __syncthreads();

  const int px = tid & 127, half = tid >> 7;
  const float4* xv = (const float4*)&sX[px*68];
  float out8[2][8];
  #pragma unroll
  for (int ci2 = 0; ci2 < 2; ci2++) {
    const float4* w4 = (const float4*)&swc[(half*2 + ci2)*512];
    float4 accs[8];
    #pragma unroll
    for (int j = 0; j < 8; j++) accs[j] = make_float4(0.f, 0.f, 0.f, 0.f);
    #pragma unroll
    for (int c4 = 0; c4 < 16; c4++) {
      float4 xa = xv[c4];
      #pragma unroll
      for (int j = 0; j < 8; j++) {
        float4 wv = w4[j*16 + c4];
        accs[j].x = fmaf(wv.x, xa.x, accs[j].x);
        accs[j].y = fmaf(wv.y, xa.y, accs[j].y);
        accs[j].z = fmaf(wv.z, xa.z, accs[j].z);
        accs[j].w = fmaf(wv.w, xa.w, accs[j].w);
      }
    }
    #pragma unroll
    for (int j = 0; j < 8; j++)
      out8[ci2][j] = (accs[j].x + accs[j].y) + (accs[j].z + accs[j].w);
  }
  float* dst = g_U + ((size_t)(b*4 + half*2)*NPX + px0 + px)*8;
  *(float4*)dst       = make_float4(out8[0][0], out8[0][1], out8[0][2], out8[0][3]);
  *(float4*)(dst + 4) = make_float4(out8[0][4], out8[0][5], out8[0][6], out8[0][7]);
  float* dst1 = dst + (size_t)NPX*8;
  *(float4*)dst1       = make_float4(out8[1][0], out8[1][1], out8[1][2], out8[1][3]);
  *(float4*)(dst1 + 4) = make_float4(out8[1][4], out8[1][5], out8[1][6], out8[1][7]);
}

// ---------------------------------------------------------------------------
// K2 v5 (mma.sync bf16 m16n8k16, 3-term hi/lo, 2-stage cp.async pipeline)
// ---------------------------------------------------------------------------
#define K2_SMEM_FLOATS (8192 + 4224 + 13824 + 1600)

__global__ __launch_bounds__(256, 2) void k2_sta_mma(const float* __restrict__ x,
                                                     const float* __restrict__ st,
                                                     const float* __restrict__ kcb) {
  extern __shared__ float sm[];
  float* s_b  = sm;                // [2][1024 uint4]
  float* s_a  = sm + 8192;         // [k 64][px 64 pad66]
  float* s_x  = sm + 12416;        // [c 64][row 6][col 36]
  float* s_kb = sm + 26240;        // [1600]

  const int b = blockIdx.z, h0 = blockIdx.y*2, w0 = blockIdx.x*32;
  const int tid = threadIdx.x, wid = tid >> 5, l = tid & 31;
  const int g = l >> 2, tg = l & 3;
  const int mt = wid & 3, nth = wid >> 2;
  const uint32_t sb = smem_u32(s_b);

  {
    const float* src = (const float*)(g_b + 0*1024);
    #pragma unroll
    for (int i = 0; i < 4; i++) {
      int j = tid + i*256;
      cp16(sb + (uint32_t)j*16u, src + j*4);
    }
    CP_COMMIT();
  }

  for (int e = tid; e < 4096; e += 256) {
    int k = e >> 6, px = e & 63;
    s_a[k*66 + px] = st[((b*CC + k)*HIN + h0 + (px >> 5))*WIN + w0 + (px & 31)];
  }
  for (int e = tid; e < 64*6*36; e += 256) {
    int col = e % 36; int row = (e / 36) % 6; int c = e / 216;
    int gy = min(max(h0 - 2 + row, 0), HIN - 1);
    int gx = min(max(w0 - 2 + col, 0), WIN - 1);
    s_x[e] = x[((b*CC + c)*HIN + gy)*WIN + gx];
  }
  for (int e = tid; e < 1600; e += 256) s_kb[e] = kcb[e];
  __syncthreads();

  uint32_t ahi[4][4], alo[4][4];
  {
    const int pxg = mt*16 + g, pxg8 = pxg + 8;
    #pragma unroll
    for (int ks = 0; ks < 4; ks++) {
      int kb = ks*16 + 2*tg;
      ahi[ks][0] = bf16_split2(s_a[kb*66 + pxg],      s_a[(kb+1)*66 + pxg],  alo[ks][0]);
      ahi[ks][1] = bf16_split2(s_a[kb*66 + pxg8],     s_a[(kb+1)*66 + pxg8], alo[ks][1]);
      ahi[ks][2] = bf16_split2(s_a[(kb+8)*66 + pxg],  s_a[(kb+9)*66 + pxg],  alo[ks][2]);
      ahi[ks][3] = bf16_split2(s_a[(kb+8)*66 + pxg8], s_a[(kb+9)*66 + pxg8], alo[ks][3]);
    }
  }

  float sacc[16];
  #pragma unroll
  for (int i = 0; i < 16; i++) sacc[i] = 0.f;

  const int prow  = mt >> 1;
  const int pcol0 = (mt & 1)*16 + g;

  for (int t = 0; t < 25; t++) {
    const int buf = t & 1;
    CP_WAIT0();
    __syncthreads();
    if (t < 24) {
      const float* src = (const float*)(g_b + (t + 1)*1024);
      const uint32_t nb = sb + (uint32_t)(1 - buf)*16384u;
      #pragma unroll
      for (int i = 0; i < 4; i++) {
        int j = tid + i*256;
        cp16(nb + (uint32_t)j*16u, src + j*4);
      }
      CP_COMMIT();
    }

    const int rr = t / 5, dw = t - rr*5;

    float d[4][4];
    #pragma unroll
    for (int n = 0; n < 4; n++) {
      int c0 = ((nth*4 + n)*8 + 2*tg)*25 + t;
      d[n][0] = s_kb[c0];      d[n][1] = s_kb[c0 + 25];
      d[n][2] = d[n][0];       d[n][3] = d[n][1];
    }

    const uint4* bb = (const uint4*)(s_b + buf*4096);
    #pragma unroll
    for (int ks = 0; ks < 4; ks++) {
      #pragma unroll
      for (int n = 0; n < 4; n++) {
        uint4 bv = bb[((nth*4 + n)*4 + ks)*32 + l];
        MMA_BF16(d[n], ahi[ks], bv.x, bv.y);
        MMA_BF16(d[n], ahi[ks], bv.z, bv.w);
        MMA_BF16(d[n], alo[ks], bv.x, bv.y);
      }
    }

    #pragma unroll
    for (int n = 0; n < 4; n++) {
      int cb = (nth*4 + n)*8 + 2*tg;
      #pragma unroll
      for (int j = 0; j < 4; j++) {
        int c  = cb + (j & 1);
        int px = pcol0 + (j >> 1)*8;
        float gv = d[n][j];
        float lv = fmaf(0.45f, fabsf(gv), 0.55f*gv);
        float xv = s_x[c*216 + (prow + rr)*36 + px + dw];
        sacc[n*4 + j] = fmaf(lv, xv, sacc[n*4 + j]);
      }
    }
  }

  #pragma unroll
  for (int n = 0; n < 4; n++) {
    int cb = (nth*4 + n)*8 + 2*tg;
    #pragma unroll
    for (int j = 0; j < 4; j++) {
      int c  = cb + (j & 1);
      int px = pcol0 + (j >> 1)*8;
      g_sta[((b*CC + c)*HIN + h0 + prow)*WIN + w0 + px] = sacc[n*4 + j];
    }
  }
}

// ---------------------------------------------------------------------------
// K2B: LR GEMMs  A = fusL @ sta,  B = fusR @ x, output channel-last.
// ---------------------------------------------------------------------------
#define K2B_SMEM_FLOATS (8192 + 64*68)

__global__ __launch_bounds__(256, 4) void k2b_gemm(const float* __restrict__ x,
                                                   const float* __restrict__ fusw) {
  extern __shared__ float sm[];
  float* s_src = sm;           // [k 64][px 128]
  float* s_wT  = sm + 8192;    // [k 64][o 64 pad68]

  const int px0 = blockIdx.x*128, b = blockIdx.y, mat = blockIdx.z;
  const int tid = threadIdx.x;
  const float* src = mat ? (x + (size_t)b*CC*NPX) : (g_sta + (size_t)b*CC*NPX);
  const int mo = mat ? 64 : 0;
  float* dst = (mat ? g_B : g_A) + (size_t)b*NPX*CC;

  for (int e = tid; e < 8192; e += 256) {
    int k = e >> 7, p = e & 127;
    s_src[e] = src[(size_t)k*NPX + px0 + p];
  }
  for (int e = tid; e < 4096; e += 256) {
    int o = e >> 6, k = e & 63;
    s_wT[k*68 + o] = fusw[o*128 + mo + k];
  }
  __syncthreads();

  const int o0 = (tid & 15)*4, p0 = (tid >> 4)*8;
  float4 acc[8];
  #pragma unroll
  for (int i = 0; i < 8; i++) acc[i] = make_float4(0.f, 0.f, 0.f, 0.f);

  #pragma unroll 4
  for (int k = 0; k < 64; k++) {
    float4 w4 = *(const float4*)&s_wT[k*68 + o0];
    const float* sr = s_src + k*128 + p0;
    #pragma unroll
    for (int pp = 0; pp < 8; pp++) {
      float s = sr[pp];
      acc[pp].x = fmaf(w4.x, s, acc[pp].x);
      acc[pp].y = fmaf(w4.y, s, acc[pp].y);
      acc[pp].z = fmaf(w4.z, s, acc[pp].z);
      acc[pp].w = fmaf(w4.w, s, acc[pp].w);
    }
  }
  #pragma unroll
  for (int pp = 0; pp < 8; pp++)
    *(float4*)&dst[(size_t)(px0 + p0 + pp)*CC + o0] = acc[pp];
}

// ---------------------------------------------------------------------------
// K3 v4: staged + row-precombined bilinear taps; t via interp of U.
// out = tapA(sA) + tapB(sB) + M_par @ tap(sU) + fus_b
// Block: (b, Y, 64 out px), 256 thr.
// class k: 0 = off geometry (B, U), 1 = stoff geometry (A).
// ---------------------------------------------------------------------------
__global__ __launch_bounds__(256, 4) void k3_fuse(const float* __restrict__ fusb,
                                                  float* __restrict__ out) {
  __shared__ float sAB[4*34*68];     // [k*2+p][col 34][68 pad]  row-combined
  __shared__ float sU[2*34*8];       // [p][col 34][8]           row-combined
  __shared__ float s_M[1024];        // [pw][j*64+o]
  __shared__ float s_fb[64];
  __shared__ float s_w0[2][64], s_w1[2][64];
  __shared__ int   s_lb[2][64];
  __shared__ int   s_rows[2][2][2];  // [k][p][tap] clamped row idx
  __shared__ float s_wy[2][2][2];
  __shared__ int   s_fc[2][2];
  __shared__ float s_frc[2][2];
  __shared__ int   s_base[2];

  const int b = blockIdx.z, Y = blockIdx.y, X0 = blockIdx.x * 64;
  const int tid = threadIdx.x;
  const int ph = Y & 1;

  // phase 0: per-class scalars (one thread per class)
  if (tid < 2) {
    const int k = tid;
    int fc0 = 0, fc1 = 0;
    #pragma unroll
    for (int p = 0; p < 2; p++) {
      int ci = ph*2 + p;
      float offx = k ? g_stoff[ci][0] : g_off[ci][0];
      float offy = k ? g_stoff[ci][1] : g_off[ci][1];
      float pyf = (Y + 0.5f)*0.5f - 0.5f + offy;
      float yf = floorf(pyf); int iy = (int)yf; float fy = pyf - yf;
      s_wy[k][p][0] = (iy   >= 0 && iy   <= HIN-1) ? (1.f - fy) : 0.f;
      s_wy[k][p][1] = (iy+1 >= 0 && iy+1 <= HIN-1) ? fy : 0.f;
      s_rows[k][p][0] = min(max(iy, 0), HIN-1);
      s_rows[k][p][1] = min(max(iy+1, 0), HIN-1);
      float xo = (p ? 0.25f : -0.25f) + offx;      // src x = m + xo
      float xf = floorf(xo); int fc = (int)xf;
      s_fc[k][p] = fc; s_frc[k][p] = xo - xf;
      if (p == 0) fc0 = fc; else fc1 = fc;
    }
    s_base[k] = X0/2 + min(fc0, fc1);
  }
  __syncthreads();

  // per-px tap tables
  if (tid < 128) {
    int k = tid >> 6, u = tid & 63, p = u & 1;
    int sg = X0/2 + (u >> 1) + s_fc[k][p];
    float fr = s_frc[k][p];
    s_lb[k][u] = sg - s_base[k];
    s_w0[k][u] = (sg   >= 0 && sg   <= WIN-1) ? (1.f - fr) : 0.f;
    s_w1[k][u] = (sg+1 >= 0 && sg+1 <= WIN-1) ? fr : 0.f;
  }

  // stage A/B segments, row-precombined  (kp = k*2+p)
  for (int e = tid; e < 2176; e += 256) {
    int kp = e / 544, rem = e - kp*544;
    int i = rem >> 4, c4 = rem & 15;
    int k = kp >> 1, p = kp & 1;
    int cg = min(max(s_base[k] + i, 0), WIN-1);
    const float4* src = (const float4*)(k ? g_A : g_B) + (size_t)(b*NPX)*16;
    float4 v0 = src[(s_rows[k][p][0]*WIN + cg)*16 + c4];
    float4 v1 = src[(s_rows[k][p][1]*WIN + cg)*16 + c4];
    float wy0 = s_wy[k][p][0], wy1 = s_wy[k][p][1];
    float4 vv;
    vv.x = wy0*v0.x + wy1*v1.x;  vv.y = wy0*v0.y + wy1*v1.y;
    vv.z = wy0*v0.z + wy1*v1.z;  vv.w = wy0*v0.w + wy1*v1.w;
    *(float4*)&sAB[(kp*34 + i)*68 + c4*4] = vv;
  }
  // stage U segments (class 0 geometry), row-precombined
  if (tid < 136) {
    int p = tid / 68, rem = tid - p*68;
    int i = rem >> 1, h = rem & 1;
    int ci = ph*2 + p;
    int cg = min(max(s_base[0] + i, 0), WIN-1);
    const float4* src = (const float4*)g_U + ((size_t)(b*4 + ci)*NPX)*2;
    float4 u0 = src[(s_rows[0][p][0]*WIN + cg)*2 + h];
    float4 u1 = src[(s_rows[0][p][1]*WIN + cg)*2 + h];
    float wy0 = s_wy[0][p][0], wy1 = s_wy[0][p][1];
    float4 vv;
    vv.x = wy0*u0.x + wy1*u1.x;  vv.y = wy0*u0.y + wy1*u1.y;
    vv.z = wy0*u0.z + wy1*u1.z;  vv.w = wy0*u0.w + wy1*u1.w;
    *(float4*)&sU[(p*34 + i)*8 + h*4] = vv;
  }
  for (int e = tid; e < 1024; e += 256)
    s_M[e] = g_M[ph*2 + (e >> 9)][e & 511];
  if (tid < 64) s_fb[tid] = fusb[tid];
  __syncthreads();

  // compute
  const int u = tid & 63, q = tid >> 6, p = u & 1;
  const int   lbB = s_lb[0][u], lbA = s_lb[1][u];
  const float wB0 = s_w0[0][u], wB1 = s_w1[0][u];
  const float wA0 = s_w0[1][u], wA1 = s_w1[1][u];

  // t8 = 2-tap interp of U
  float tt[8];
  {
    const float4* Up = (const float4*)&sU[(p*34 + lbB)*8];
    float4 t0 = f4maf(wB1, Up[2], f4maf(wB0, Up[0], make_float4(0,0,0,0)));
    float4 t1 = f4maf(wB1, Up[3], f4maf(wB0, Up[1], make_float4(0,0,0,0)));
    tt[0]=t0.x; tt[1]=t0.y; tt[2]=t0.z; tt[3]=t0.w;
    tt[4]=t1.x; tt[5]=t1.y; tt[6]=t1.z; tt[7]=t1.w;
  }

  const float* Ab = &sAB[((2 + p)*34)*68];
  const float* Bb = &sAB[(p*34)*68];
  const float* Mp = &s_M[p*512];
  const float4* fb4 = (const float4*)s_fb;

  #pragma unroll
  for (int i4 = 0; i4 < 4; i4++) {
    const int o4 = q*4 + i4;
    float4 A0 = *(const float4*)&Ab[lbA*68 + o4*4];
    float4 A1 = *(const float4*)&Ab[(lbA+1)*68 + o4*4];
    float4 B0 = *(const float4*)&Bb[lbB*68 + o4*4];
    float4 B1 = *(const float4*)&Bb[(lbB+1)*68 + o4*4];
    float4 r = fb4[o4];
    r = f4maf(wA0, A0, r); r = f4maf(wA1, A1, r);
    r = f4maf(wB0, B0, r); r = f4maf(wB1, B1, r);
    #pragma unroll
    for (int j = 0; j < 8; j++) {
      float4 m4 = *(const float4*)&Mp[j*64 + o4*4];
      r = f4maf(tt[j], m4, r);
    }
    float* op = out + ((size_t)(b*CC + o4*4)*HOUT + Y)*WOUT + X0 + u;
    op[0]              = r.x;
    op[HOUT*WOUT]      = r.y;
    op[2*HOUT*WOUT]    = r.z;
    op[3*HOUT*WOUT]    = r.w;
  }
}

// ---------------------------------------------------------------------------
extern "C" void kernel_launch(void* const* d_in, const int* in_sizes, int n_in,
                              void* d_out, int out_size) {
  const float* x    = (const float*)d_in[0];
  const float* st   = (const float*)d_in[1];
  const float* kcw  = (const float*)d_in[2];
  const float* kcb  = (const float*)d_in[3];
  const float* wc   = (const float*)d_in[4];
  const float* we   = (const float*)d_in[5];
  const float* b1w  = (const float*)d_in[6];
  const float* b1b  = (const float*)d_in[7];
  const float* b2w  = (const float*)d_in[8];
  const float* b2b  = (const float*)d_in[9];
  const float* rw   = (const float*)d_in[10];
  const float* rb   = (const float*)d_in[11];
  const float* ow   = (const float*)d_in[12];
  const float* ob   = (const float*)d_in[13];
  const float* sow  = (const float*)d_in[14];
  const float* sob  = (const float*)d_in[15];
  const float* fusw = (const float*)d_in[16];
  const float* fusb = (const float*)d_in[17];
  float* out = (float*)d_out;

  const int smem2 = K2_SMEM_FLOATS * 4;
  const int smemb = K2B_SMEM_FLOATS * 4;
  cudaFuncSetAttribute(k2_sta_mma, cudaFuncAttributeMaxDynamicSharedMemorySize, smem2);
  cudaFuncSetAttribute(k2b_gemm,   cudaFuncAttributeMaxDynamicSharedMemorySize, smemb);

  k01_prep<<<104, 256>>>(kcw, b1w, b1b, b2w, b2b, rw, rb, ow, ob, sow, sob, wc, we, fusw);
  k2x_transpose<<<dim3(NPX/32, 2, BB), 256>>>(x);
  k2u_gemm<<<dim3(NPX/128, BB), 256>>>();
  k2_sta_mma<<<dim3(WIN/32, HIN/2, BB), 256, smem2>>>(x, st, kcb);
  k2b_gemm<<<dim3(NPX/128, BB, 2), 256, smemb>>>(x, fusw);
  k3_fuse<<<dim3(WOUT/64, HOUT, BB), 256>>>(fusb, out);
}

// round 10
// speedup vs baseline: 1.5802x; 1.1590x over previous
#include <cuda_runtime.h>
#include <cuda_bf16.h>
#include <cstdint>

#define BB 4
#define CC 64
#define HIN 96
#define WIN 96
#define HOUT 192
#define WOUT 192
#define NPX (HIN*WIN)          // 9216

// Scratch + precomputed data (allocation-free rule: device globals)
__device__ float g_sta[BB*CC*NPX];       // sta_feat  [b][c][96][96]
__device__ float g_A[BB*NPX*CC];         // fusL@sta, channel-last [b][px][64]
__device__ float g_B[BB*NPX*CC];         // fusR@x,   channel-last
__device__ float g_U[BB*4*NPX*8];        // wc_ci @ X, [b][ci][src][8]
__device__ float g_off[4][2];
__device__ float g_stoff[4][2];
__device__ float g_wcpx[4][512];         // [j*64+c]
__device__ float g_M[4][512];            // [j*64+o]  (fusR @ we_par)
// kc_w repacked: [t 25][q 8][ks 4][lane 32] uint4 = (b0h, b1h, b0l, b1l) bf16x2
__device__ uint4 g_b[25600];

// ============================ helpers ======================================
__device__ __forceinline__ uint32_t smem_u32(const void* p) {
  uint32_t a;
  asm("{ .reg .u64 t; cvta.to.shared.u64 t, %1; cvt.u32.u64 %0, t; }" : "=r"(a) : "l"(p));
  return a;
}
__device__ __forceinline__ void cp16(uint32_t dst, const float* src) {
  asm volatile("cp.async.cg.shared.global [%0], [%1], 16;" :: "r"(dst), "l"(src));
}
#define CP_COMMIT() asm volatile("cp.async.commit_group;" ::: "memory")
#define CP_WAIT0()  asm volatile("cp.async.wait_group 0;" ::: "memory")

__device__ __forceinline__ uint32_t bf16_split2(float v0, float v1, uint32_t& lo_out) {
  __nv_bfloat162 h = __floats2bfloat162_rn(v0, v1);
  float r0 = v0 - __bfloat162float(h.x);
  float r1 = v1 - __bfloat162float(h.y);
  __nv_bfloat162 lo = __floats2bfloat162_rn(r0, r1);
  lo_out = *(uint32_t*)&lo;
  return *(uint32_t*)&h;
}

#define MMA_BF16(d, a, b0v, b1v) \
  asm volatile("mma.sync.aligned.m16n8k16.row.col.f32.bf16.bf16.f32 " \
      "{%0,%1,%2,%3}, {%4,%5,%6,%7}, {%8,%9}, {%0,%1,%2,%3};" \
      : "+f"((d)[0]), "+f"((d)[1]), "+f"((d)[2]), "+f"((d)[3]) \
      : "r"((a)[0]), "r"((a)[1]), "r"((a)[2]), "r"((a)[3]), "r"(b0v), "r"(b1v))

__device__ __forceinline__ float4 f4maf(float s, float4 a, float4 r) {
  r.x = fmaf(s, a.x, r.x); r.y = fmaf(s, a.y, r.y);
  r.z = fmaf(s, a.z, r.z); r.w = fmaf(s, a.w, r.w);
  return r;
}

// ---------------------------------------------------------------------------
// K01: blocks 0..99 repack kc_w -> bf16 hi/lo fragments; blocks 100..103 parity
// ---------------------------------------------------------------------------
__global__ void k01_prep(const float* __restrict__ kcw,
                         const float* __restrict__ b1w, const float* __restrict__ b1b,
                         const float* __restrict__ b2w, const float* __restrict__ b2b,
                         const float* __restrict__ rw,  const float* __restrict__ rb,
                         const float* __restrict__ ow,  const float* __restrict__ ob,
                         const float* __restrict__ sow, const float* __restrict__ sob,
                         const float* __restrict__ wc,  const float* __restrict__ we,
                         const float* __restrict__ fusw) {
  const int tid = threadIdx.x;
  if (blockIdx.x < 100) {
    int idx = blockIdx.x*256 + tid;
    int l  = idx & 31;
    int ks = (idx >> 5) & 3;
    int q  = (idx >> 7) & 7;
    int t  = idx >> 10;
    int g = l >> 2, tg = l & 3;
    int c  = q*8 + g;
    int k0 = ks*16 + 2*tg;
    const float* row = kcw + (c*25 + t)*64;
    float v0 = row[k0], v1 = row[k0 + 1], v2 = row[k0 + 8], v3 = row[k0 + 9];
    uint32_t l01, l23;
    uint32_t h01 = bf16_split2(v0, v1, l01);
    uint32_t h23 = bf16_split2(v2, v3, l23);
    g_b[idx] = make_uint4(h01, h23, l01, l23);
    return;
  }
  __shared__ float hid[64], emb[64], r[4];
  __shared__ float s_we2[512];
  __shared__ float s_fr[64*65];
  const int ci = blockIdx.x - 100;
  const float in2 = (ci >> 1) ? 0.25f : -0.25f;
  const float in3 = (ci & 1)  ? 0.25f : -0.25f;

  for (int e = tid; e < 4096; e += 256) {
    int o = e >> 6, c = e & 63;
    s_fr[c*65 + o] = fusw[o*128 + 64 + c];
  }
  if (tid < 64) {
    float a = b1b[tid] + 0.5f*b1w[tid*4+0] + 0.5f*b1w[tid*4+1]
            + in2*b1w[tid*4+2] + in3*b1w[tid*4+3];
    hid[tid] = fmaxf(a, 0.f);
  }
  __syncthreads();
  if (tid < 64) {
    float a = b2b[tid];
    #pragma unroll 8
    for (int k = 0; k < 64; k++) a = fmaf(b2w[tid*64+k], hid[k], a);
    emb[tid] = fmaxf(a, 0.f);
  }
  __syncthreads();
  if (tid < 4) {
    float a = rb[tid];
    for (int k = 0; k < 64; k++) a = fmaf(rw[tid*64+k], emb[k], a);
    r[tid] = 1.f / (1.f + expf(-a));
  } else if (tid < 6) {
    int t = tid - 4; float a = ob[t];
    for (int k = 0; k < 64; k++) a = fmaf(ow[t*64+k], emb[k], a);
    g_off[ci][t] = a;
  } else if (tid < 8) {
    int t = tid - 6; float a = sob[t];
    for (int k = 0; k < 64; k++) a = fmaf(sow[t*64+k], emb[k], a);
    g_stoff[ci][t] = a;
  }
  __syncthreads();
  for (int e = tid; e < 512; e += 256) {
    float a = 0.f, bsum = 0.f;
    #pragma unroll
    for (int ex = 0; ex < 4; ex++) {
      a    = fmaf(r[ex], wc[ex*512+e], a);
      bsum = fmaf(r[ex], we[ex*512+e], bsum);
    }
    g_wcpx[ci][e] = a;
    s_we2[e] = bsum;
  }
  __syncthreads();
  for (int e = tid; e < 512; e += 256) {
    int j = e >> 6, o = e & 63;
    float a = 0.f;
    #pragma unroll 8
    for (int c = 0; c < 64; c++) a = fmaf(s_fr[c*65 + o], s_we2[c*8 + j], a);
    g_M[ci][j*64 + o] = a;
  }
}

// ---------------------------------------------------------------------------
// KPREP1: from x (read once): U[b][ci][src][8] = wc_ci@x,  B = fusR @ x.
// grid (72, BB), 256 thr, dynamic smem.
// ---------------------------------------------------------------------------
#define KP1_SMEM_FLOATS (64*129 + 64*68 + 2048)

__global__ __launch_bounds__(256, 3) void kprep1(const float* __restrict__ x,
                                                 const float* __restrict__ fusw) {
  extern __shared__ float sm[];
  float* s_src = sm;                 // [c 64][px 129]
  float* s_wT  = sm + 8256;          // [k 64][o 68]  (fusR^T)
  float* swc   = sm + 8256 + 4352;   // [4][512]

  const int px0 = blockIdx.x*128, b = blockIdx.y;
  const int tid = threadIdx.x;
  const float* xb = x + (size_t)b*CC*NPX;

  for (int e = tid; e < 8192; e += 256) {
    int k = e >> 7, p = e & 127;
    s_src[k*129 + p] = xb[(size_t)k*NPX + px0 + p];
  }
  for (int e = tid; e < 4096; e += 256) {
    int o = e >> 6, k = e & 63;
    s_wT[k*68 + o] = fusw[o*128 + 64 + k];
  }
  for (int e = tid; e < 2048; e += 256) swc[e] = g_wcpx[e >> 9][e & 511];
  __syncthreads();

  // U: thread = (px 128, half 2); 2 ci x 8 j dots over c
  {
    const int px = tid & 127, half = tid >> 7;
    float acc[2][8];
    #pragma unroll
    for (int i = 0; i < 2; i++)
      #pragma unroll
      for (int j = 0; j < 8; j++) acc[i][j] = 0.f;
    #pragma unroll 4
    for (int c = 0; c < 64; c++) {
      float xv = s_src[c*129 + px];
      #pragma unroll
      for (int i = 0; i < 2; i++) {
        const float* w = &swc[(half*2 + i)*512 + c];
        #pragma unroll
        for (int j = 0; j < 8; j++)
          acc[i][j] = fmaf(w[j*64], xv, acc[i][j]);
      }
    }
    #pragma unroll
    for (int i = 0; i < 2; i++) {
      float* dst = g_U + ((size_t)(b*4 + half*2 + i)*NPX + px0 + px)*8;
      *(float4*)dst       = make_float4(acc[i][0], acc[i][1], acc[i][2], acc[i][3]);
      *(float4*)(dst + 4) = make_float4(acc[i][4], acc[i][5], acc[i][6], acc[i][7]);
    }
  }

  // B GEMM: 64o x 128px, K=64
  {
    const int o0 = (tid & 15)*4, p0 = (tid >> 4)*8;
    float4 acc[8];
    #pragma unroll
    for (int i = 0; i < 8; i++) acc[i] = make_float4(0.f, 0.f, 0.f, 0.f);
    #pragma unroll 4
    for (int k = 0; k < 64; k++) {
      float4 w4 = *(const float4*)&s_wT[k*68 + o0];
      const float* sr = s_src + k*129 + p0;
      #pragma unroll
      for (int pp = 0; pp < 8; pp++) {
        float s = sr[pp];
        acc[pp] = f4maf(s, w4, acc[pp]);
      }
    }
    float* dst = g_B + (size_t)b*NPX*CC;
    #pragma unroll
    for (int pp = 0; pp < 8; pp++)
      *(float4*)&dst[(size_t)(px0 + p0 + pp)*CC + o0] = acc[pp];
  }
}

// ---------------------------------------------------------------------------
// KPREP2: A = fusL @ sta, channel-last. grid (72, BB).
// ---------------------------------------------------------------------------
#define KP2_SMEM_FLOATS (8192 + 64*68)

__global__ __launch_bounds__(256, 4) void kprep2(const float* __restrict__ fusw) {
  extern __shared__ float sm[];
  float* s_src = sm;           // [k 64][px 128]
  float* s_wT  = sm + 8192;    // [k 64][o 68]  (fusL^T)

  const int px0 = blockIdx.x*128, b = blockIdx.y;
  const int tid = threadIdx.x;
  const float* src = g_sta + (size_t)b*CC*NPX;

  for (int e = tid; e < 8192; e += 256) {
    int k = e >> 7, p = e & 127;
    s_src[e] = src[(size_t)k*NPX + px0 + p];
  }
  for (int e = tid; e < 4096; e += 256) {
    int o = e >> 6, k = e & 63;
    s_wT[k*68 + o] = fusw[o*128 + k];
  }
  __syncthreads();

  const int o0 = (tid & 15)*4, p0 = (tid >> 4)*8;
  float4 acc[8];
  #pragma unroll
  for (int i = 0; i < 8; i++) acc[i] = make_float4(0.f, 0.f, 0.f, 0.f);
  #pragma unroll 4
  for (int k = 0; k < 64; k++) {
    float4 w4 = *(const float4*)&s_wT[k*68 + o0];
    const float* sr = s_src + k*128 + p0;
    #pragma unroll
    for (int pp = 0; pp < 8; pp++) {
      float s = sr[pp];
      acc[pp] = f4maf(s, w4, acc[pp]);
    }
  }
  float* dst = g_A + (size_t)b*NPX*CC;
  #pragma unroll
  for (int pp = 0; pp < 8; pp++)
    *(float4*)&dst[(size_t)(px0 + p0 + pp)*CC + o0] = acc[pp];
}

// ---------------------------------------------------------------------------
// K2 v6 (mma.sync bf16, 3-term hi/lo, double-buffered B, x row-ring,
// 3 blocks/SM): fused kernel_warp GEMM + 25-tap sta conv.
// Block: 256 thr / 8 warps, tile (b, 2 rows, 32 px), M=64.
// smem: s_b 2x16KB, s_x ring [c 64][slot 3][36], s_kb.
// ---------------------------------------------------------------------------
#define K2_SMEM_FLOATS (8192 + 6912 + 1600)

__global__ __launch_bounds__(256, 3) void k2_sta_mma(const float* __restrict__ x,
                                                     const float* __restrict__ st,
                                                     const float* __restrict__ kcb) {
  extern __shared__ float sm[];
  float* s_b  = sm;                // [2][1024 uint4]
  float* s_x  = sm + 8192;         // [c 64][slot 3][36]
  float* s_kb = sm + 15104;        // [1600]

  const int b = blockIdx.z, h0 = blockIdx.y*2, w0 = blockIdx.x*32;
  const int tid = threadIdx.x, wid = tid >> 5, l = tid & 31;
  const int g = l >> 2, tg = l & 3;
  const int mt = wid & 3, nth = wid >> 2;
  const uint32_t sb = smem_u32(s_b);

  // B(0) prologue
  {
    const float* src = (const float*)g_b;
    #pragma unroll
    for (int i = 0; i < 4; i++) {
      int j = tid + i*256;
      cp16(sb + (uint32_t)j*16u, src + j*4);
    }
    CP_COMMIT();
  }

  // x rows 0..2 (r_local) into slots 0..2
  for (int e = tid; e < 64*3*36; e += 256) {
    int col = e % 36; int slot = (e / 36) % 3; int c = e / 108;
    int gy = min(max(h0 - 2 + slot, 0), HIN - 1);
    int gx = min(max(w0 - 2 + col, 0), WIN - 1);
    s_x[c*108 + slot*36 + col] = x[((b*CC + c)*HIN + gy)*WIN + gx];
  }
  for (int e = tid; e < 1600; e += 256) s_kb[e] = kcb[e];

  // A fragments (bf16 hi/lo) direct from gmem, tap-invariant
  uint32_t ahi[4][4], alo[4][4];
  {
    const int pxg = mt*16 + g, pxg8 = pxg + 8;
    const int r0 = h0 + (pxg >> 5),  ca = w0 + (pxg & 31);
    const int r1 = h0 + (pxg8 >> 5), cb2 = w0 + (pxg8 & 31);
    const float* stb = st + (size_t)b*CC*NPX;
    #pragma unroll
    for (int ks = 0; ks < 4; ks++) {
      int kb = ks*16 + 2*tg;
      const float* p0 = stb + (size_t)kb*NPX;
      float v00 = p0[r0*WIN + ca],        v01 = p0[NPX + r0*WIN + ca];
      float v10 = p0[r1*WIN + cb2],       v11 = p0[NPX + r1*WIN + cb2];
      float v20 = p0[8*NPX + r0*WIN + ca], v21 = p0[9*NPX + r0*WIN + ca];
      float v30 = p0[8*NPX + r1*WIN + cb2], v31 = p0[9*NPX + r1*WIN + cb2];
      ahi[ks][0] = bf16_split2(v00, v01, alo[ks][0]);
      ahi[ks][1] = bf16_split2(v10, v11, alo[ks][1]);
      ahi[ks][2] = bf16_split2(v20, v21, alo[ks][2]);
      ahi[ks][3] = bf16_split2(v30, v31, alo[ks][3]);
    }
  }
  __syncthreads();

  float sacc[16];
  #pragma unroll
  for (int i = 0; i < 16; i++) sacc[i] = 0.f;

  const int prow  = mt >> 1;
  const int pcol0 = (mt & 1)*16 + g;

  for (int t = 0; t < 25; t++) {
    const int buf = t & 1;
    CP_WAIT0();
    __syncthreads();
    // issue next tap's B into the other buffer (reads of it finished pre-barrier)
    if (t < 24) {
      const float* src = (const float*)(g_b + (t + 1)*1024);
      const uint32_t nb = sb + (uint32_t)(1 - buf)*16384u;
      #pragma unroll
      for (int i = 0; i < 4; i++) {
        int j = tid + i*256;
        cp16(nb + (uint32_t)j*16u, src + j*4);
      }
      CP_COMMIT();
    }
    // row-ring refill at group transitions: row rl = t/5+2 into slot rl%3
    if (t == 5 || t == 10 || t == 15) {
      const int rl = t/5 + 2;
      const int slot = rl % 3;
      const int gy = min(max(h0 - 2 + rl, 0), HIN - 1);
      for (int e = tid; e < 2304; e += 256) {
        int col = e % 36; int c = e / 36;
        int gx = min(max(w0 - 2 + col, 0), WIN - 1);
        s_x[c*108 + slot*36 + col] = x[((b*CC + c)*HIN + gy)*WIN + gx];
      }
    }

    const int rr = t / 5, dw = t - rr*5;

    float d[4][4];
    #pragma unroll
    for (int n = 0; n < 4; n++) {
      int c0 = ((nth*4 + n)*8 + 2*tg)*25 + t;
      d[n][0] = s_kb[c0];      d[n][1] = s_kb[c0 + 25];
      d[n][2] = d[n][0];       d[n][3] = d[n][1];
    }

    const uint4* bb = (const uint4*)(s_b + buf*4096);
    #pragma unroll
    for (int ks = 0; ks < 4; ks++) {
      #pragma unroll
      for (int n = 0; n < 4; n++) {
        uint4 bv = bb[((nth*4 + n)*4 + ks)*32 + l];
        MMA_BF16(d[n], ahi[ks], bv.x, bv.y);
        MMA_BF16(d[n], ahi[ks], bv.z, bv.w);
        MMA_BF16(d[n], alo[ks], bv.x, bv.y);
      }
    }

    // epilogue: lrelu(gate) * x_halo, accumulate
    const int sl = (prow + rr) % 3;
    #pragma unroll
    for (int n = 0; n < 4; n++) {
      int cb = (nth*4 + n)*8 + 2*tg;
      #pragma unroll
      for (int j = 0; j < 4; j++) {
        int c  = cb + (j & 1);
        int px = pcol0 + (j >> 1)*8;
        float gv = d[n][j];
        float lv = fmaf(0.45f, fabsf(gv), 0.55f*gv);
        float xv = s_x[c*108 + sl*36 + px + dw];
        sacc[n*4 + j] = fmaf(lv, xv, sacc[n*4 + j]);
      }
    }
  }

  #pragma unroll
  for (int n = 0; n < 4; n++) {
    int cb = (nth*4 + n)*8 + 2*tg;
    #pragma unroll
    for (int j = 0; j < 4; j++) {
      int c  = cb + (j & 1);
      int px = pcol0 + (j >> 1)*8;
      g_sta[((b*CC + c)*HIN + h0 + prow)*WIN + w0 + px] = sacc[n*4 + j];
    }
  }
}

// ---------------------------------------------------------------------------
// K3 v4: staged + row-precombined bilinear taps; t via interp of U.
// out = tapA(sA) + tapB(sB) + M_par @ tap(sU) + fus_b
// ---------------------------------------------------------------------------
__global__ __launch_bounds__(256, 4) void k3_fuse(const float* __restrict__ fusb,
                                                  float* __restrict__ out) {
  __shared__ float sAB[4*34*68];
  __shared__ float sU[2*34*8];
  __shared__ float s_M[1024];
  __shared__ float s_fb[64];
  __shared__ float s_w0[2][64], s_w1[2][64];
  __shared__ int   s_lb[2][64];
  __shared__ int   s_rows[2][2][2];
  __shared__ float s_wy[2][2][2];
  __shared__ int   s_fc[2][2];
  __shared__ float s_frc[2][2];
  __shared__ int   s_base[2];

  const int b = blockIdx.z, Y = blockIdx.y, X0 = blockIdx.x * 64;
  const int tid = threadIdx.x;
  const int ph = Y & 1;

  if (tid < 2) {
    const int k = tid;
    int fc0 = 0, fc1 = 0;
    #pragma unroll
    for (int p = 0; p < 2; p++) {
      int ci = ph*2 + p;
      float offx = k ? g_stoff[ci][0] : g_off[ci][0];
      float offy = k ? g_stoff[ci][1] : g_off[ci][1];
      float pyf = (Y + 0.5f)*0.5f - 0.5f + offy;
      float yf = floorf(pyf); int iy = (int)yf; float fy = pyf - yf;
      s_wy[k][p][0] = (iy   >= 0 && iy   <= HIN-1) ? (1.f - fy) : 0.f;
      s_wy[k][p][1] = (iy+1 >= 0 && iy+1 <= HIN-1) ? fy : 0.f;
      s_rows[k][p][0] = min(max(iy, 0), HIN-1);
      s_rows[k][p][1] = min(max(iy+1, 0), HIN-1);
      float xo = (p ? 0.25f : -0.25f) + offx;
      float xf = floorf(xo); int fc = (int)xf;
      s_fc[k][p] = fc; s_frc[k][p] = xo - xf;
      if (p == 0) fc0 = fc; else fc1 = fc;
    }
    s_base[k] = X0/2 + min(fc0, fc1);
  }
  __syncthreads();

  if (tid < 128) {
    int k = tid >> 6, u = tid & 63, p = u & 1;
    int sg = X0/2 + (u >> 1) + s_fc[k][p];
    float fr = s_frc[k][p];
    s_lb[k][u] = sg - s_base[k];
    s_w0[k][u] = (sg   >= 0 && sg   <= WIN-1) ? (1.f - fr) : 0.f;
    s_w1[k][u] = (sg+1 >= 0 && sg+1 <= WIN-1) ? fr : 0.f;
  }

  for (int e = tid; e < 2176; e += 256) {
    int kp = e / 544, rem = e - kp*544;
    int i = rem >> 4, c4 = rem & 15;
    int k = kp >> 1, p = kp & 1;
    int cg = min(max(s_base[k] + i, 0), WIN-1);
    const float4* src = (const float4*)(k ? g_A : g_B) + (size_t)(b*NPX)*16;
    float4 v0 = src[(s_rows[k][p][0]*WIN + cg)*16 + c4];
    float4 v1 = src[(s_rows[k][p][1]*WIN + cg)*16 + c4];
    float wy0 = s_wy[k][p][0], wy1 = s_wy[k][p][1];
    float4 vv;
    vv.x = wy0*v0.x + wy1*v1.x;  vv.y = wy0*v0.y + wy1*v1.y;
    vv.z = wy0*v0.z + wy1*v1.z;  vv.w = wy0*v0.w + wy1*v1.w;
    *(float4*)&sAB[(kp*34 + i)*68 + c4*4] = vv;
  }
  if (tid < 136) {
    int p = tid / 68, rem = tid - p*68;
    int i = rem >> 1, h = rem & 1;
    int ci = ph*2 + p;
    int cg = min(max(s_base[0] + i, 0), WIN-1);
    const float4* src = (const float4*)g_U + ((size_t)(b*4 + ci)*NPX)*2;
    float4 u0 = src[(s_rows[0][p][0]*WIN + cg)*2 + h];
    float4 u1 = src[(s_rows[0][p][1]*WIN + cg)*2 + h];
    float wy0 = s_wy[0][p][0], wy1 = s_wy[0][p][1];
    float4 vv;
    vv.x = wy0*u0.x + wy1*u1.x;  vv.y = wy0*u0.y + wy1*u1.y;
    vv.z = wy0*u0.z + wy1*u1.z;  vv.w = wy0*u0.w + wy1*u1.w;
    *(float4*)&sU[(p*34 + i)*8 + h*4] = vv;
  }
  for (int e = tid; e < 1024; e += 256)
    s_M[e] = g_M[ph*2 + (e >> 9)][e & 511];
  if (tid < 64) s_fb[tid] = fusb[tid];
  __syncthreads();

  const int u = tid & 63, q = tid >> 6, p = u & 1;
  const int   lbB = s_lb[0][u], lbA = s_lb[1][u];
  const float wB0 = s_w0[0][u], wB1 = s_w1[0][u];
  const float wA0 = s_w0[1][u], wA1 = s_w1[1][u];

  float tt[8];
  {
    const float4* Up = (const float4*)&sU[(p*34 + lbB)*8];
    float4 t0 = f4maf(wB1, Up[2], f4maf(wB0, Up[0], make_float4(0,0,0,0)));
    float4 t1 = f4maf(wB1, Up[3], f4maf(wB0, Up[1], make_float4(0,0,0,0)));
    tt[0]=t0.x; tt[1]=t0.y; tt[2]=t0.z; tt[3]=t0.w;
    tt[4]=t1.x; tt[5]=t1.y; tt[6]=t1.z; tt[7]=t1.w;
  }

  const float* Ab = &sAB[((2 + p)*34)*68];
  const float* Bb = &sAB[(p*34)*68];
  const float* Mp = &s_M[p*512];
  const float4* fb4 = (const float4*)s_fb;

  #pragma unroll
  for (int i4 = 0; i4 < 4; i4++) {
    const int o4 = q*4 + i4;
    float4 A0 = *(const float4*)&Ab[lbA*68 + o4*4];
    float4 A1 = *(const float4*)&Ab[(lbA+1)*68 + o4*4];
    float4 B0 = *(const float4*)&Bb[lbB*68 + o4*4];
    float4 B1 = *(const float4*)&Bb[(lbB+1)*68 + o4*4];
    float4 r = fb4[o4];
    r = f4maf(wA0, A0, r); r = f4maf(wA1, A1, r);
    r = f4maf(wB0, B0, r); r = f4maf(wB1, B1, r);
    #pragma unroll
    for (int j = 0; j < 8; j++) {
      float4 m4 = *(const float4*)&Mp[j*64 + o4*4];
      r = f4maf(tt[j], m4, r);
    }
    float* op = out + ((size_t)(b*CC + o4*4)*HOUT + Y)*WOUT + X0 + u;
    op[0]              = r.x;
    op[HOUT*WOUT]      = r.y;
    op[2*HOUT*WOUT]    = r.z;
    op[3*HOUT*WOUT]    = r.w;
  }
}

// ---------------------------------------------------------------------------
extern "C" void kernel_launch(void* const* d_in, const int* in_sizes, int n_in,
                              void* d_out, int out_size) {
  const float* x    = (const float*)d_in[0];
  const float* st   = (const float*)d_in[1];
  const float* kcw  = (const float*)d_in[2];
  const float* kcb  = (const float*)d_in[3];
  const float* wc   = (const float*)d_in[4];
  const float* we   = (const float*)d_in[5];
  const float* b1w  = (const float*)d_in[6];
  const float* b1b  = (const float*)d_in[7];
  const float* b2w  = (const float*)d_in[8];
  const float* b2b  = (const float*)d_in[9];
  const float* rw   = (const float*)d_in[10];
  const float* rb   = (const float*)d_in[11];
  const float* ow   = (const float*)d_in[12];
  const float* ob   = (const float*)d_in[13];
  const float* sow  = (const float*)d_in[14];
  const float* sob  = (const float*)d_in[15];
  const float* fusw = (const float*)d_in[16];
  const float* fusb = (const float*)d_in[17];
  float* out = (float*)d_out;

  const int smem2  = K2_SMEM_FLOATS * 4;
  const int smemp1 = KP1_SMEM_FLOATS * 4;
  const int smemp2 = KP2_SMEM_FLOATS * 4;
  cudaFuncSetAttribute(k2_sta_mma, cudaFuncAttributeMaxDynamicSharedMemorySize, smem2);
  cudaFuncSetAttribute(kprep1,     cudaFuncAttributeMaxDynamicSharedMemorySize, smemp1);
  cudaFuncSetAttribute(kprep2,     cudaFuncAttributeMaxDynamicSharedMemorySize, smemp2);

  k01_prep<<<104, 256>>>(kcw, b1w, b1b, b2w, b2b, rw, rb, ow, ob, sow, sob, wc, we, fusw);
  kprep1<<<dim3(NPX/128, BB), 256, smemp1>>>(x, fusw);
  k2_sta_mma<<<dim3(WIN/32, HIN/2, BB), 256, smem2>>>(x, st, kcb);
  kprep2<<<dim3(NPX/128, BB), 256, smemp2>>>(fusw);
  k3_fuse<<<dim3(WOUT/64, HOUT, BB), 256>>>(fusb, out);
}

// round 11
// speedup vs baseline: 1.6657x; 1.0541x over previous
#include <cuda_runtime.h>
#include <cuda_bf16.h>
#include <cstdint>

#define BB 4
#define CC 64
#define HIN 96
#define WIN 96
#define HOUT 192
#define WOUT 192
#define NPX (HIN*WIN)          // 9216

// Scratch + precomputed data (allocation-free rule: device globals)
__device__ float g_A[BB*NPX*CC];         // fusL@sta, channel-last [b][px][64]
__device__ float g_B[BB*NPX*CC];         // fusR@x,   channel-last
__device__ float g_U[BB*4*NPX*8];        // wc_ci @ X, [b][ci][src][8]
__device__ float g_off[4][2];
__device__ float g_stoff[4][2];
__device__ float g_wcpx[4][512];         // [j*64+c]
__device__ float g_M[4][512];            // [j*64+o]  (fusR @ we_par)
// kc_w repacked: [t 25][q 8][ks 4][lane 32] uint4 = (b0h, b1h, b0l, b1l) bf16x2
__device__ uint4 g_b[25600];

// ============================ helpers ======================================
__device__ __forceinline__ uint32_t smem_u32(const void* p) {
  uint32_t a;
  asm("{ .reg .u64 t; cvta.to.shared.u64 t, %1; cvt.u32.u64 %0, t; }" : "=r"(a) : "l"(p));
  return a;
}
__device__ __forceinline__ void cp16(uint32_t dst, const float* src) {
  asm volatile("cp.async.cg.shared.global [%0], [%1], 16;" :: "r"(dst), "l"(src));
}
#define CP_COMMIT() asm volatile("cp.async.commit_group;" ::: "memory")
#define CP_WAIT0()  asm volatile("cp.async.wait_group 0;" ::: "memory")

__device__ __forceinline__ uint32_t bf16_split2(float v0, float v1, uint32_t& lo_out) {
  __nv_bfloat162 h = __floats2bfloat162_rn(v0, v1);
  float r0 = v0 - __bfloat162float(h.x);
  float r1 = v1 - __bfloat162float(h.y);
  __nv_bfloat162 lo = __floats2bfloat162_rn(r0, r1);
  lo_out = *(uint32_t*)&lo;
  return *(uint32_t*)&h;
}

#define MMA_BF16(d, a, b0v, b1v) \
  asm volatile("mma.sync.aligned.m16n8k16.row.col.f32.bf16.bf16.f32 " \
      "{%0,%1,%2,%3}, {%4,%5,%6,%7}, {%8,%9}, {%0,%1,%2,%3};" \
      : "+f"((d)[0]), "+f"((d)[1]), "+f"((d)[2]), "+f"((d)[3]) \
      : "r"((a)[0]), "r"((a)[1]), "r"((a)[2]), "r"((a)[3]), "r"(b0v), "r"(b1v))

__device__ __forceinline__ float4 f4maf(float s, float4 a, float4 r) {
  r.x = fmaf(s, a.x, r.x); r.y = fmaf(s, a.y, r.y);
  r.z = fmaf(s, a.z, r.z); r.w = fmaf(s, a.w, r.w);
  return r;
}

// ---------------------------------------------------------------------------
// K01: blocks 0..99 repack kc_w -> bf16 hi/lo fragments; blocks 100..103 parity
// ---------------------------------------------------------------------------
__global__ void k01_prep(const float* __restrict__ kcw,
                         const float* __restrict__ b1w, const float* __restrict__ b1b,
                         const float* __restrict__ b2w, const float* __restrict__ b2b,
                         const float* __restrict__ rw,  const float* __restrict__ rb,
                         const float* __restrict__ ow,  const float* __restrict__ ob,
                         const float* __restrict__ sow, const float* __restrict__ sob,
                         const float* __restrict__ wc,  const float* __restrict__ we,
                         const float* __restrict__ fusw) {
  const int tid = threadIdx.x;
  if (blockIdx.x < 100) {
    int idx = blockIdx.x*256 + tid;
    int l  = idx & 31;
    int ks = (idx >> 5) & 3;
    int q  = (idx >> 7) & 7;
    int t  = idx >> 10;
    int g = l >> 2, tg = l & 3;
    int c  = q*8 + g;
    int k0 = ks*16 + 2*tg;
    const float* row = kcw + (c*25 + t)*64;
    float v0 = row[k0], v1 = row[k0 + 1], v2 = row[k0 + 8], v3 = row[k0 + 9];
    uint32_t l01, l23;
    uint32_t h01 = bf16_split2(v0, v1, l01);
    uint32_t h23 = bf16_split2(v2, v3, l23);
    g_b[idx] = make_uint4(h01, h23, l01, l23);
    return;
  }
  __shared__ float hid[64], emb[64], r[4];
  __shared__ float s_we2[512];
  __shared__ float s_fr[64*65];
  const int ci = blockIdx.x - 100;
  const float in2 = (ci >> 1) ? 0.25f : -0.25f;
  const float in3 = (ci & 1)  ? 0.25f : -0.25f;

  for (int e = tid; e < 4096; e += 256) {
    int o = e >> 6, c = e & 63;
    s_fr[c*65 + o] = fusw[o*128 + 64 + c];
  }
  if (tid < 64) {
    float a = b1b[tid] + 0.5f*b1w[tid*4+0] + 0.5f*b1w[tid*4+1]
            + in2*b1w[tid*4+2] + in3*b1w[tid*4+3];
    hid[tid] = fmaxf(a, 0.f);
  }
  __syncthreads();
  if (tid < 64) {
    float a = b2b[tid];
    #pragma unroll 8
    for (int k = 0; k < 64; k++) a = fmaf(b2w[tid*64+k], hid[k], a);
    emb[tid] = fmaxf(a, 0.f);
  }
  __syncthreads();
  if (tid < 4) {
    float a = rb[tid];
    for (int k = 0; k < 64; k++) a = fmaf(rw[tid*64+k], emb[k], a);
    r[tid] = 1.f / (1.f + expf(-a));
  } else if (tid < 6) {
    int t = tid - 4; float a = ob[t];
    for (int k = 0; k < 64; k++) a = fmaf(ow[t*64+k], emb[k], a);
    g_off[ci][t] = a;
  } else if (tid < 8) {
    int t = tid - 6; float a = sob[t];
    for (int k = 0; k < 64; k++) a = fmaf(sow[t*64+k], emb[k], a);
    g_stoff[ci][t] = a;
  }
  __syncthreads();
  for (int e = tid; e < 512; e += 256) {
    float a = 0.f, bsum = 0.f;
    #pragma unroll
    for (int ex = 0; ex < 4; ex++) {
      a    = fmaf(r[ex], wc[ex*512+e], a);
      bsum = fmaf(r[ex], we[ex*512+e], bsum);
    }
    g_wcpx[ci][e] = a;
    s_we2[e] = bsum;
  }
  __syncthreads();
  for (int e = tid; e < 512; e += 256) {
    int j = e >> 6, o = e & 63;
    float a = 0.f;
    #pragma unroll 8
    for (int c = 0; c < 64; c++) a = fmaf(s_fr[c*65 + o], s_we2[c*8 + j], a);
    g_M[ci][j*64 + o] = a;
  }
}

// ---------------------------------------------------------------------------
// KPREP1: from x (read once): U[b][ci][src][8] = wc_ci@x,  B = fusR @ x.
// ---------------------------------------------------------------------------
#define KP1_SMEM_FLOATS (64*129 + 64*68 + 2048)

__global__ __launch_bounds__(256, 3) void kprep1(const float* __restrict__ x,
                                                 const float* __restrict__ fusw) {
  extern __shared__ float sm[];
  float* s_src = sm;                 // [c 64][px 129]
  float* s_wT  = sm + 8256;          // [k 64][o 68]  (fusR^T)
  float* swc   = sm + 8256 + 4352;   // [4][512]

  const int px0 = blockIdx.x*128, b = blockIdx.y;
  const int tid = threadIdx.x;
  const float* xb = x + (size_t)b*CC*NPX;

  for (int e = tid; e < 8192; e += 256) {
    int k = e >> 7, p = e & 127;
    s_src[k*129 + p] = xb[(size_t)k*NPX + px0 + p];
  }
  for (int e = tid; e < 4096; e += 256) {
    int o = e >> 6, k = e & 63;
    s_wT[k*68 + o] = fusw[o*128 + 64 + k];
  }
  for (int e = tid; e < 2048; e += 256) swc[e] = g_wcpx[e >> 9][e & 511];
  __syncthreads();

  {
    const int px = tid & 127, half = tid >> 7;
    float acc[2][8];
    #pragma unroll
    for (int i = 0; i < 2; i++)
      #pragma unroll
      for (int j = 0; j < 8; j++) acc[i][j] = 0.f;
    #pragma unroll 4
    for (int c = 0; c < 64; c++) {
      float xv = s_src[c*129 + px];
      #pragma unroll
      for (int i = 0; i < 2; i++) {
        const float* w = &swc[(half*2 + i)*512 + c];
        #pragma unroll
        for (int j = 0; j < 8; j++)
          acc[i][j] = fmaf(w[j*64], xv, acc[i][j]);
      }
    }
    #pragma unroll
    for (int i = 0; i < 2; i++) {
      float* dst = g_U + ((size_t)(b*4 + half*2 + i)*NPX + px0 + px)*8;
      *(float4*)dst       = make_float4(acc[i][0], acc[i][1], acc[i][2], acc[i][3]);
      *(float4*)(dst + 4) = make_float4(acc[i][4], acc[i][5], acc[i][6], acc[i][7]);
    }
  }

  {
    const int o0 = (tid & 15)*4, p0 = (tid >> 4)*8;
    float4 acc[8];
    #pragma unroll
    for (int i = 0; i < 8; i++) acc[i] = make_float4(0.f, 0.f, 0.f, 0.f);
    #pragma unroll 4
    for (int k = 0; k < 64; k++) {
      float4 w4 = *(const float4*)&s_wT[k*68 + o0];
      const float* sr = s_src + k*129 + p0;
      #pragma unroll
      for (int pp = 0; pp < 8; pp++) {
        float s = sr[pp];
        acc[pp] = f4maf(s, w4, acc[pp]);
      }
    }
    float* dst = g_B + (size_t)b*NPX*CC;
    #pragma unroll
    for (int pp = 0; pp < 8; pp++)
      *(float4*)&dst[(size_t)(px0 + p0 + pp)*CC + o0] = acc[pp];
  }
}

// ---------------------------------------------------------------------------
// K2 v7: fused kernel_warp GEMM + 25-tap sta conv + A = fusL @ sta epilogue.
// Writes g_A directly (channel-last, coalesced); g_sta eliminated.
// Block: 256 thr / 8 warps, tile (b, 2 rows, 32 px), M=64.
// ---------------------------------------------------------------------------
#define K2_SMEM_FLOATS (8192 + 6912 + 1600)

__global__ __launch_bounds__(256, 3) void k2_sta_mma(const float* __restrict__ x,
                                                     const float* __restrict__ st,
                                                     const float* __restrict__ kcb,
                                                     const float* __restrict__ fusw) {
  extern __shared__ float sm[];
  float* s_b  = sm;                // [2][1024 uint4]
  float* s_x  = sm + 8192;         // [c 64][slot 3][36]
  float* s_kb = sm + 15104;        // [1600]
  // post-loop reuse (B buffers + x ring dead):
  float* s_sta = sm;               // [c 64][px 66]  4224
  float* s_fl  = sm + 4224;        // [k 64][o 68]   4352

  const int b = blockIdx.z, h0 = blockIdx.y*2, w0 = blockIdx.x*32;
  const int tid = threadIdx.x, wid = tid >> 5, l = tid & 31;
  const int g = l >> 2, tg = l & 3;
  const int mt = wid & 3, nth = wid >> 2;
  const uint32_t sb = smem_u32(s_b);

  // B(0) prologue
  {
    const float* src = (const float*)g_b;
    #pragma unroll
    for (int i = 0; i < 4; i++) {
      int j = tid + i*256;
      cp16(sb + (uint32_t)j*16u, src + j*4);
    }
    CP_COMMIT();
  }

  // x rows 0..2 into slots 0..2
  for (int e = tid; e < 64*3*36; e += 256) {
    int col = e % 36; int slot = (e / 36) % 3; int c = e / 108;
    int gy = min(max(h0 - 2 + slot, 0), HIN - 1);
    int gx = min(max(w0 - 2 + col, 0), WIN - 1);
    s_x[c*108 + slot*36 + col] = x[((b*CC + c)*HIN + gy)*WIN + gx];
  }
  for (int e = tid; e < 1600; e += 256) s_kb[e] = kcb[e];

  // A fragments (bf16 hi/lo) direct from gmem, tap-invariant
  uint32_t ahi[4][4], alo[4][4];
  {
    const int pxg = mt*16 + g, pxg8 = pxg + 8;
    const int r0 = h0 + (pxg >> 5),  ca = w0 + (pxg & 31);
    const int r1 = h0 + (pxg8 >> 5), cb2 = w0 + (pxg8 & 31);
    const float* stb = st + (size_t)b*CC*NPX;
    #pragma unroll
    for (int ks = 0; ks < 4; ks++) {
      int kb = ks*16 + 2*tg;
      const float* p0 = stb + (size_t)kb*NPX;
      float v00 = p0[r0*WIN + ca],        v01 = p0[NPX + r0*WIN + ca];
      float v10 = p0[r1*WIN + cb2],       v11 = p0[NPX + r1*WIN + cb2];
      float v20 = p0[8*NPX + r0*WIN + ca], v21 = p0[9*NPX + r0*WIN + ca];
      float v30 = p0[8*NPX + r1*WIN + cb2], v31 = p0[9*NPX + r1*WIN + cb2];
      ahi[ks][0] = bf16_split2(v00, v01, alo[ks][0]);
      ahi[ks][1] = bf16_split2(v10, v11, alo[ks][1]);
      ahi[ks][2] = bf16_split2(v20, v21, alo[ks][2]);
      ahi[ks][3] = bf16_split2(v30, v31, alo[ks][3]);
    }
  }
  __syncthreads();

  float sacc[16];
  #pragma unroll
  for (int i = 0; i < 16; i++) sacc[i] = 0.f;

  const int prow  = mt >> 1;
  const int pcol0 = (mt & 1)*16 + g;

  for (int t = 0; t < 25; t++) {
    const int buf = t & 1;
    CP_WAIT0();
    __syncthreads();
    if (t < 24) {
      const float* src = (const float*)(g_b + (t + 1)*1024);
      const uint32_t nb = sb + (uint32_t)(1 - buf)*16384u;
      #pragma unroll
      for (int i = 0; i < 4; i++) {
        int j = tid + i*256;
        cp16(nb + (uint32_t)j*16u, src + j*4);
      }
      CP_COMMIT();
    }
    if (t == 5 || t == 10 || t == 15) {
      const int rl = t/5 + 2;
      const int slot = rl % 3;
      const int gy = min(max(h0 - 2 + rl, 0), HIN - 1);
      for (int e = tid; e < 2304; e += 256) {
        int col = e % 36; int c = e / 36;
        int gx = min(max(w0 - 2 + col, 0), WIN - 1);
        s_x[c*108 + slot*36 + col] = x[((b*CC + c)*HIN + gy)*WIN + gx];
      }
    }

    const int rr = t / 5, dw = t - rr*5;

    float d[4][4];
    #pragma unroll
    for (int n = 0; n < 4; n++) {
      int c0 = ((nth*4 + n)*8 + 2*tg)*25 + t;
      d[n][0] = s_kb[c0];      d[n][1] = s_kb[c0 + 25];
      d[n][2] = d[n][0];       d[n][3] = d[n][1];
    }

    const uint4* bb = (const uint4*)(s_b + buf*4096);
    #pragma unroll
    for (int ks = 0; ks < 4; ks++) {
      #pragma unroll
      for (int n = 0; n < 4; n++) {
        uint4 bv = bb[((nth*4 + n)*4 + ks)*32 + l];
        MMA_BF16(d[n], ahi[ks], bv.x, bv.y);
        MMA_BF16(d[n], ahi[ks], bv.z, bv.w);
        MMA_BF16(d[n], alo[ks], bv.x, bv.y);
      }
    }

    const int sl = (prow + rr) % 3;
    #pragma unroll
    for (int n = 0; n < 4; n++) {
      int cb = (nth*4 + n)*8 + 2*tg;
      #pragma unroll
      for (int j = 0; j < 4; j++) {
        int c  = cb + (j & 1);
        int px = pcol0 + (j >> 1)*8;
        float gv = d[n][j];
        float lv = fmaf(0.45f, fabsf(gv), 0.55f*gv);
        float xv = s_x[c*108 + sl*36 + px + dw];
        sacc[n*4 + j] = fmaf(lv, xv, sacc[n*4 + j]);
      }
    }
  }

  // ================= fused A = fusL @ sta epilogue =================
  __syncthreads();   // all B/x reads retired before s_sta/s_fl overwrite
  // spill sta tile: s_sta[c][tilepx 0..63] (tilepx = prow*32 + col)
  #pragma unroll
  for (int n = 0; n < 4; n++) {
    int cb = (nth*4 + n)*8 + 2*tg;
    #pragma unroll
    for (int j = 0; j < 4; j++) {
      int c  = cb + (j & 1);
      int px = prow*32 + pcol0 + (j >> 1)*8;
      s_sta[c*66 + px] = sacc[n*4 + j];
    }
  }
  // stage fusL^T
  for (int e = tid; e < 4096; e += 256) {
    int o = e >> 6, k = e & 63;
    s_fl[k*68 + o] = fusw[o*128 + k];
  }
  __syncthreads();

  // 64o x 64px GEMM, K=64; thread = (o0 16, p0 16)
  {
    const int o0 = (tid & 15)*4, p0 = (tid >> 4)*4;
    float4 acc[4];
    #pragma unroll
    for (int i = 0; i < 4; i++) acc[i] = make_float4(0.f, 0.f, 0.f, 0.f);
    #pragma unroll 4
    for (int c = 0; c < 64; c++) {
      float4 w4 = *(const float4*)&s_fl[c*68 + o0];
      const float* sr = s_sta + c*66 + p0;
      #pragma unroll
      for (int pp = 0; pp < 4; pp++)
        acc[pp] = f4maf(sr[pp], w4, acc[pp]);
    }
    float* dst = g_A + (size_t)b*NPX*CC;
    #pragma unroll
    for (int pp = 0; pp < 4; pp++) {
      int pxt = p0 + pp;
      int gpx = (h0 + (pxt >> 5))*WIN + w0 + (pxt & 31);
      *(float4*)&dst[(size_t)gpx*CC + o0] = acc[pp];
    }
  }
}

// ---------------------------------------------------------------------------
// K3 v4: staged + row-precombined bilinear taps; t via interp of U.
// ---------------------------------------------------------------------------
__global__ __launch_bounds__(256, 4) void k3_fuse(const float* __restrict__ fusb,
                                                  float* __restrict__ out) {
  __shared__ float sAB[4*34*68];
  __shared__ float sU[2*34*8];
  __shared__ float s_M[1024];
  __shared__ float s_fb[64];
  __shared__ float s_w0[2][64], s_w1[2][64];
  __shared__ int   s_lb[2][64];
  __shared__ int   s_rows[2][2][2];
  __shared__ float s_wy[2][2][2];
  __shared__ int   s_fc[2][2];
  __shared__ float s_frc[2][2];
  __shared__ int   s_base[2];

  const int b = blockIdx.z, Y = blockIdx.y, X0 = blockIdx.x * 64;
  const int tid = threadIdx.x;
  const int ph = Y & 1;

  if (tid < 2) {
    const int k = tid;
    int fc0 = 0, fc1 = 0;
    #pragma unroll
    for (int p = 0; p < 2; p++) {
      int ci = ph*2 + p;
      float offx = k ? g_stoff[ci][0] : g_off[ci][0];
      float offy = k ? g_stoff[ci][1] : g_off[ci][1];
      float pyf = (Y + 0.5f)*0.5f - 0.5f + offy;
      float yf = floorf(pyf); int iy = (int)yf; float fy = pyf - yf;
      s_wy[k][p][0] = (iy   >= 0 && iy   <= HIN-1) ? (1.f - fy) : 0.f;
      s_wy[k][p][1] = (iy+1 >= 0 && iy+1 <= HIN-1) ? fy : 0.f;
      s_rows[k][p][0] = min(max(iy, 0), HIN-1);
      s_rows[k][p][1] = min(max(iy+1, 0), HIN-1);
      float xo = (p ? 0.25f : -0.25f) + offx;
      float xf = floorf(xo); int fc = (int)xf;
      s_fc[k][p] = fc; s_frc[k][p] = xo - xf;
      if (p == 0) fc0 = fc; else fc1 = fc;
    }
    s_base[k] = X0/2 + min(fc0, fc1);
  }
  __syncthreads();

  if (tid < 128) {
    int k = tid >> 6, u = tid & 63, p = u & 1;
    int sg = X0/2 + (u >> 1) + s_fc[k][p];
    float fr = s_frc[k][p];
    s_lb[k][u] = sg - s_base[k];
    s_w0[k][u] = (sg   >= 0 && sg   <= WIN-1) ? (1.f - fr) : 0.f;
    s_w1[k][u] = (sg+1 >= 0 && sg+1 <= WIN-1) ? fr : 0.f;
  }

  for (int e = tid; e < 2176; e += 256) {
    int kp = e / 544, rem = e - kp*544;
    int i = rem >> 4, c4 = rem & 15;
    int k = kp >> 1, p = kp & 1;
    int cg = min(max(s_base[k] + i, 0), WIN-1);
    const float4* src = (const float4*)(k ? g_A : g_B) + (size_t)(b*NPX)*16;
    float4 v0 = src[(s_rows[k][p][0]*WIN + cg)*16 + c4];
    float4 v1 = src[(s_rows[k][p][1]*WIN + cg)*16 + c4];
    float wy0 = s_wy[k][p][0], wy1 = s_wy[k][p][1];
    float4 vv;
    vv.x = wy0*v0.x + wy1*v1.x;  vv.y = wy0*v0.y + wy1*v1.y;
    vv.z = wy0*v0.z + wy1*v1.z;  vv.w = wy0*v0.w + wy1*v1.w;
    *(float4*)&sAB[(kp*34 + i)*68 + c4*4] = vv;
  }
  if (tid < 136) {
    int p = tid / 68, rem = tid - p*68;
    int i = rem >> 1, h = rem & 1;
    int ci = ph*2 + p;
    int cg = min(max(s_base[0] + i, 0), WIN-1);
    const float4* src = (const float4*)g_U + ((size_t)(b*4 + ci)*NPX)*2;
    float4 u0 = src[(s_rows[0][p][0]*WIN + cg)*2 + h];
    float4 u1 = src[(s_rows[0][p][1]*WIN + cg)*2 + h];
    float wy0 = s_wy[0][p][0], wy1 = s_wy[0][p][1];
    float4 vv;
    vv.x = wy0*u0.x + wy1*u1.x;  vv.y = wy0*u0.y + wy1*u1.y;
    vv.z = wy0*u0.z + wy1*u1.z;  vv.w = wy0*u0.w + wy1*u1.w;
    *(float4*)&sU[(p*34 + i)*8 + h*4] = vv;
  }
  for (int e = tid; e < 1024; e += 256)
    s_M[e] = g_M[ph*2 + (e >> 9)][e & 511];
  if (tid < 64) s_fb[tid] = fusb[tid];
  __syncthreads();

  const int u = tid & 63, q = tid >> 6, p = u & 1;
  const int   lbB = s_lb[0][u], lbA = s_lb[1][u];
  const float wB0 = s_w0[0][u], wB1 = s_w1[0][u];
  const float wA0 = s_w0[1][u], wA1 = s_w1[1][u];

  float tt[8];
  {
    const float4* Up = (const float4*)&sU[(p*34 + lbB)*8];
    float4 t0 = f4maf(wB1, Up[2], f4maf(wB0, Up[0], make_float4(0,0,0,0)));
    float4 t1 = f4maf(wB1, Up[3], f4maf(wB0, Up[1], make_float4(0,0,0,0)));
    tt[0]=t0.x; tt[1]=t0.y; tt[2]=t0.z; tt[3]=t0.w;
    tt[4]=t1.x; tt[5]=t1.y; tt[6]=t1.z; tt[7]=t1.w;
  }

  const float* Ab = &sAB[((2 + p)*34)*68];
  const float* Bb = &sAB[(p*34)*68];
  const float* Mp = &s_M[p*512];
  const float4* fb4 = (const float4*)s_fb;

  #pragma unroll
  for (int i4 = 0; i4 < 4; i4++) {
    const int o4 = q*4 + i4;
    float4 A0 = *(const float4*)&Ab[lbA*68 + o4*4];
    float4 A1 = *(const float4*)&Ab[(lbA+1)*68 + o4*4];
    float4 B0 = *(const float4*)&Bb[lbB*68 + o4*4];
    float4 B1 = *(const float4*)&Bb[(lbB+1)*68 + o4*4];
    float4 r = fb4[o4];
    r = f4maf(wA0, A0, r); r = f4maf(wA1, A1, r);
    r = f4maf(wB0, B0, r); r = f4maf(wB1, B1, r);
    #pragma unroll
    for (int j = 0; j < 8; j++) {
      float4 m4 = *(const float4*)&Mp[j*64 + o4*4];
      r = f4maf(tt[j], m4, r);
    }
    float* op = out + ((size_t)(b*CC + o4*4)*HOUT + Y)*WOUT + X0 + u;
    op[0]              = r.x;
    op[HOUT*WOUT]      = r.y;
    op[2*HOUT*WOUT]    = r.z;
    op[3*HOUT*WOUT]    = r.w;
  }
}

// ---------------------------------------------------------------------------
extern "C" void kernel_launch(void* const* d_in, const int* in_sizes, int n_in,
                              void* d_out, int out_size) {
  const float* x    = (const float*)d_in[0];
  const float* st   = (const float*)d_in[1];
  const float* kcw  = (const float*)d_in[2];
  const float* kcb  = (const float*)d_in[3];
  const float* wc   = (const float*)d_in[4];
  const float* we   = (const float*)d_in[5];
  const float* b1w  = (const float*)d_in[6];
  const float* b1b  = (const float*)d_in[7];
  const float* b2w  = (const float*)d_in[8];
  const float* b2b  = (const float*)d_in[9];
  const float* rw   = (const float*)d_in[10];
  const float* rb   = (const float*)d_in[11];
  const float* ow   = (const float*)d_in[12];
  const float* ob   = (const float*)d_in[13];
  const float* sow  = (const float*)d_in[14];
  const float* sob  = (const float*)d_in[15];
  const float* fusw = (const float*)d_in[16];
  const float* fusb = (const float*)d_in[17];
  float* out = (float*)d_out;

  const int smem2  = K2_SMEM_FLOATS * 4;
  const int smemp1 = KP1_SMEM_FLOATS * 4;
  cudaFuncSetAttribute(k2_sta_mma, cudaFuncAttributeMaxDynamicSharedMemorySize, smem2);
  cudaFuncSetAttribute(kprep1,     cudaFuncAttributeMaxDynamicSharedMemorySize, smemp1);

  k01_prep<<<104, 256>>>(kcw, b1w, b1b, b2w, b2b, rw, rb, ow, ob, sow, sob, wc, we, fusw);
  kprep1<<<dim3(NPX/128, BB), 256, smemp1>>>(x, fusw);
  k2_sta_mma<<<dim3(WIN/32, HIN/2, BB), 256, smem2>>>(x, st, kcb, fusw);
  k3_fuse<<<dim3(WOUT/64, HOUT, BB), 256>>>(fusb, out);
}

// round 12
// speedup vs baseline: 1.8647x; 1.1195x over previous
#include <cuda_runtime.h>
#include <cuda_bf16.h>
#include <cuda_fp16.h>
#include <cstdint>

#define BB 4
#define CC 64
#define HIN 96
#define WIN 96
#define HOUT 192
#define WOUT 192
#define NPX (HIN*WIN)          // 9216

// Scratch + precomputed data (allocation-free rule: device globals)
__device__ float g_A[BB*NPX*CC];         // fusL@sta, channel-last [b][px][64]
__device__ float g_B[BB*NPX*CC];         // fusR@x,   channel-last
__device__ float g_U[BB*4*NPX*8];        // wc_ci @ X, [b][ci][src][8]
__device__ float g_off[4][2];
__device__ float g_stoff[4][2];
__device__ float g_wcpx[4][512];         // [j*64+c]
__device__ float g_M[4][512];            // [j*64+o]  (fusR @ we_par)
// kc_w repacked: [t 25][q 8][ks 4][lane 32] uint2 = (b0h, b1h) fp16x2 (hi only)
__device__ uint2 g_b[25600];

// ============================ helpers ======================================
__device__ __forceinline__ uint32_t smem_u32(const void* p) {
  uint32_t a;
  asm("{ .reg .u64 t; cvta.to.shared.u64 t, %1; cvt.u32.u64 %0, t; }" : "=r"(a) : "l"(p));
  return a;
}
__device__ __forceinline__ void cp16(uint32_t dst, const float* src) {
  asm volatile("cp.async.cg.shared.global [%0], [%1], 16;" :: "r"(dst), "l"(src));
}
#define CP_COMMIT() asm volatile("cp.async.commit_group;" ::: "memory")
#define CP_WAIT0()  asm volatile("cp.async.wait_group 0;" ::: "memory")

// fp16 hi/lo split of two floats, packed as fp16x2
__device__ __forceinline__ uint32_t fp16_split2(float v0, float v1, uint32_t& lo_out) {
  __half2 h = __floats2half2_rn(v0, v1);
  float r0 = v0 - __half2float(__low2half(h));
  float r1 = v1 - __half2float(__high2half(h));
  __half2 lo = __floats2half2_rn(r0, r1);
  lo_out = *(uint32_t*)&lo;
  return *(uint32_t*)&h;
}

#define MMA_FP16(d, a, b0v, b1v) \
  asm volatile("mma.sync.aligned.m16n8k16.row.col.f32.f16.f16.f32 " \
      "{%0,%1,%2,%3}, {%4,%5,%6,%7}, {%8,%9}, {%0,%1,%2,%3};" \
      : "+f"((d)[0]), "+f"((d)[1]), "+f"((d)[2]), "+f"((d)[3]) \
      : "r"((a)[0]), "r"((a)[1]), "r"((a)[2]), "r"((a)[3]), "r"(b0v), "r"(b1v))

__device__ __forceinline__ float4 f4maf(float s, float4 a, float4 r) {
  r.x = fmaf(s, a.x, r.x); r.y = fmaf(s, a.y, r.y);
  r.z = fmaf(s, a.z, r.z); r.w = fmaf(s, a.w, r.w);
  return r;
}

// ---------------------------------------------------------------------------
// K01: blocks 0..99 repack kc_w -> fp16 hi fragments; blocks 100..103 parity
// ---------------------------------------------------------------------------
__global__ void k01_prep(const float* __restrict__ kcw,
                         const float* __restrict__ b1w, const float* __restrict__ b1b,
                         const float* __restrict__ b2w, const float* __restrict__ b2b,
                         const float* __restrict__ rw,  const float* __restrict__ rb,
                         const float* __restrict__ ow,  const float* __restrict__ ob,
                         const float* __restrict__ sow, const float* __restrict__ sob,
                         const float* __restrict__ wc,  const float* __restrict__ we,
                         const float* __restrict__ fusw) {
  const int tid = threadIdx.x;
  if (blockIdx.x < 100) {
    int idx = blockIdx.x*256 + tid;
    int l  = idx & 31;
    int ks = (idx >> 5) & 3;
    int q  = (idx >> 7) & 7;
    int t  = idx >> 10;
    int g = l >> 2, tg = l & 3;
    int c  = q*8 + g;
    int k0 = ks*16 + 2*tg;
    const float* row = kcw + (c*25 + t)*64;
    __half2 h01 = __floats2half2_rn(row[k0],     row[k0 + 1]);
    __half2 h23 = __floats2half2_rn(row[k0 + 8], row[k0 + 9]);
    g_b[idx] = make_uint2(*(uint32_t*)&h01, *(uint32_t*)&h23);
    return;
  }
  __shared__ float hid[64], emb[64], r[4];
  __shared__ float s_we2[512];
  __shared__ float s_fr[64*65];
  const int ci = blockIdx.x - 100;
  const float in2 = (ci >> 1) ? 0.25f : -0.25f;
  const float in3 = (ci & 1)  ? 0.25f : -0.25f;

  for (int e = tid; e < 4096; e += 256) {
    int o = e >> 6, c = e & 63;
    s_fr[c*65 + o] = fusw[o*128 + 64 + c];
  }
  if (tid < 64) {
    float a = b1b[tid] + 0.5f*b1w[tid*4+0] + 0.5f*b1w[tid*4+1]
            + in2*b1w[tid*4+2] + in3*b1w[tid*4+3];
    hid[tid] = fmaxf(a, 0.f);
  }
  __syncthreads();
  if (tid < 64) {
    float a = b2b[tid];
    #pragma unroll 8
    for (int k = 0; k < 64; k++) a = fmaf(b2w[tid*64+k], hid[k], a);
    emb[tid] = fmaxf(a, 0.f);
  }
  __syncthreads();
  if (tid < 4) {
    float a = rb[tid];
    for (int k = 0; k < 64; k++) a = fmaf(rw[tid*64+k], emb[k], a);
    r[tid] = 1.f / (1.f + expf(-a));
  } else if (tid < 6) {
    int t = tid - 4; float a = ob[t];
    for (int k = 0; k < 64; k++) a = fmaf(ow[t*64+k], emb[k], a);
    g_off[ci][t] = a;
  } else if (tid < 8) {
    int t = tid - 6; float a = sob[t];
    for (int k = 0; k < 64; k++) a = fmaf(sow[t*64+k], emb[k], a);
    g_stoff[ci][t] = a;
  }
  __syncthreads();
  for (int e = tid; e < 512; e += 256) {
    float a = 0.f, bsum = 0.f;
    #pragma unroll
    for (int ex = 0; ex < 4; ex++) {
      a    = fmaf(r[ex], wc[ex*512+e], a);
      bsum = fmaf(r[ex], we[ex*512+e], bsum);
    }
    g_wcpx[ci][e] = a;
    s_we2[e] = bsum;
  }
  __syncthreads();
  for (int e = tid; e < 512; e += 256) {
    int j = e >> 6, o = e & 63;
    float a = 0.f;
    #pragma unroll 8
    for (int c = 0; c < 64; c++) a = fmaf(s_fr[c*65 + o], s_we2[c*8 + j], a);
    g_M[ci][j*64 + o] = a;
  }
}

// ---------------------------------------------------------------------------
// KPREP1: from x (read once): U[b][ci][src][8] = wc_ci@x,  B = fusR @ x.
// ---------------------------------------------------------------------------
#define KP1_SMEM_FLOATS (64*129 + 64*68 + 2048)

__global__ __launch_bounds__(256, 3) void kprep1(const float* __restrict__ x,
                                                 const float* __restrict__ fusw) {
  extern __shared__ float sm[];
  float* s_src = sm;                 // [c 64][px 129]
  float* s_wT  = sm + 8256;          // [k 64][o 68]  (fusR^T)
  float* swc   = sm + 8256 + 4352;   // [4][512]

  const int px0 = blockIdx.x*128, b = blockIdx.y;
  const int tid = threadIdx.x;
  const float* xb = x + (size_t)b*CC*NPX;

  for (int e = tid; e < 8192; e += 256) {
    int k = e >> 7, p = e & 127;
    s_src[k*129 + p] = xb[(size_t)k*NPX + px0 + p];
  }
  for (int e = tid; e < 4096; e += 256) {
    int o = e >> 6, k = e & 63;
    s_wT[k*68 + o] = fusw[o*128 + 64 + k];
  }
  for (int e = tid; e < 2048; e += 256) swc[e] = g_wcpx[e >> 9][e & 511];
  __syncthreads();

  {
    const int px = tid & 127, half = tid >> 7;
    float acc[2][8];
    #pragma unroll
    for (int i = 0; i < 2; i++)
      #pragma unroll
      for (int j = 0; j < 8; j++) acc[i][j] = 0.f;
    #pragma unroll 4
    for (int c = 0; c < 64; c++) {
      float xv = s_src[c*129 + px];
      #pragma unroll
      for (int i = 0; i < 2; i++) {
        const float* w = &swc[(half*2 + i)*512 + c];
        #pragma unroll
        for (int j = 0; j < 8; j++)
          acc[i][j] = fmaf(w[j*64], xv, acc[i][j]);
      }
    }
    #pragma unroll
    for (int i = 0; i < 2; i++) {
      float* dst = g_U + ((size_t)(b*4 + half*2 + i)*NPX + px0 + px)*8;
      *(float4*)dst       = make_float4(acc[i][0], acc[i][1], acc[i][2], acc[i][3]);
      *(float4*)(dst + 4) = make_float4(acc[i][4], acc[i][5], acc[i][6], acc[i][7]);
    }
  }

  {
    const int o0 = (tid & 15)*4, p0 = (tid >> 4)*8;
    float4 acc[8];
    #pragma unroll
    for (int i = 0; i < 8; i++) acc[i] = make_float4(0.f, 0.f, 0.f, 0.f);
    #pragma unroll 4
    for (int k = 0; k < 64; k++) {
      float4 w4 = *(const float4*)&s_wT[k*68 + o0];
      const float* sr = s_src + k*129 + p0;
      #pragma unroll
      for (int pp = 0; pp < 8; pp++) {
        float s = sr[pp];
        acc[pp] = f4maf(s, w4, acc[pp]);
      }
    }
    float* dst = g_B + (size_t)b*NPX*CC;
    #pragma unroll
    for (int pp = 0; pp < 8; pp++)
      *(float4*)&dst[(size_t)(px0 + p0 + pp)*CC + o0] = acc[pp];
  }
}

// ---------------------------------------------------------------------------
// K2 v8 (mma.sync fp16 m16n8k16, 2-term a-split, double-buffered 8KB B,
// x row-ring, fused A=fusL@sta epilogue): 32 MMA per warp-tap.
// Block: 256 thr / 8 warps, tile (b, 2 rows, 32 px), M=64.
// ---------------------------------------------------------------------------
#define K2_SMEM_FLOATS (4096 + 6912 + 1600)

__global__ __launch_bounds__(256, 3) void k2_sta_mma(const float* __restrict__ x,
                                                     const float* __restrict__ st,
                                                     const float* __restrict__ kcb,
                                                     const float* __restrict__ fusw) {
  extern __shared__ float sm[];
  float* s_b  = sm;                // [2][512 uint4] = 2x8KB
  float* s_x  = sm + 4096;         // [c 64][slot 3][36]
  float* s_kb = sm + 11008;        // [1600]
  // post-loop reuse:
  float* s_sta = sm;               // [c 64][px 66]  4224
  float* s_fl  = sm + 4224;        // [k 64][o 68]   4352

  const int b = blockIdx.z, h0 = blockIdx.y*2, w0 = blockIdx.x*32;
  const int tid = threadIdx.x, wid = tid >> 5, l = tid & 31;
  const int g = l >> 2, tg = l & 3;
  const int mt = wid & 3, nth = wid >> 2;
  const uint32_t sb = smem_u32(s_b);

  // B(0) prologue: 8KB = 512 x 16B chunks
  {
    const float* src = (const float*)g_b;
    #pragma unroll
    for (int i = 0; i < 2; i++) {
      int j = tid + i*256;
      cp16(sb + (uint32_t)j*16u, src + j*4);
    }
    CP_COMMIT();
  }

  // x rows 0..2 into slots 0..2
  for (int e = tid; e < 64*3*36; e += 256) {
    int col = e % 36; int slot = (e / 36) % 3; int c = e / 108;
    int gy = min(max(h0 - 2 + slot, 0), HIN - 1);
    int gx = min(max(w0 - 2 + col, 0), WIN - 1);
    s_x[c*108 + slot*36 + col] = x[((b*CC + c)*HIN + gy)*WIN + gx];
  }
  for (int e = tid; e < 1600; e += 256) s_kb[e] = kcb[e];

  // A fragments (fp16 hi/lo) direct from gmem, tap-invariant
  uint32_t ahi[4][4], alo[4][4];
  {
    const int pxg = mt*16 + g, pxg8 = pxg + 8;
    const int r0 = h0 + (pxg >> 5),  ca = w0 + (pxg & 31);
    const int r1 = h0 + (pxg8 >> 5), cb2 = w0 + (pxg8 & 31);
    const float* stb = st + (size_t)b*CC*NPX;
    #pragma unroll
    for (int ks = 0; ks < 4; ks++) {
      int kb = ks*16 + 2*tg;
      const float* p0 = stb + (size_t)kb*NPX;
      float v00 = p0[r0*WIN + ca],        v01 = p0[NPX + r0*WIN + ca];
      float v10 = p0[r1*WIN + cb2],       v11 = p0[NPX + r1*WIN + cb2];
      float v20 = p0[8*NPX + r0*WIN + ca], v21 = p0[9*NPX + r0*WIN + ca];
      float v30 = p0[8*NPX + r1*WIN + cb2], v31 = p0[9*NPX + r1*WIN + cb2];
      ahi[ks][0] = fp16_split2(v00, v01, alo[ks][0]);
      ahi[ks][1] = fp16_split2(v10, v11, alo[ks][1]);
      ahi[ks][2] = fp16_split2(v20, v21, alo[ks][2]);
      ahi[ks][3] = fp16_split2(v30, v31, alo[ks][3]);
    }
  }
  __syncthreads();

  float sacc[16];
  #pragma unroll
  for (int i = 0; i < 16; i++) sacc[i] = 0.f;

  const int prow  = mt >> 1;
  const int pcol0 = (mt & 1)*16 + g;

  for (int t = 0; t < 25; t++) {
    const int buf = t & 1;
    CP_WAIT0();
    __syncthreads();
    if (t < 24) {
      const float* src = (const float*)(g_b + (t + 1)*1024);
      const uint32_t nb = sb + (uint32_t)(1 - buf)*8192u;
      #pragma unroll
      for (int i = 0; i < 2; i++) {
        int j = tid + i*256;
        cp16(nb + (uint32_t)j*16u, src + j*4);
      }
      CP_COMMIT();
    }
    if (t == 5 || t == 10 || t == 15) {
      const int rl = t/5 + 2;
      const int slot = rl % 3;
      const int gy = min(max(h0 - 2 + rl, 0), HIN - 1);
      for (int e = tid; e < 2304; e += 256) {
        int col = e % 36; int c = e / 36;
        int gx = min(max(w0 - 2 + col, 0), WIN - 1);
        s_x[c*108 + slot*36 + col] = x[((b*CC + c)*HIN + gy)*WIN + gx];
      }
    }

    const int rr = t / 5, dw = t - rr*5;

    float d[4][4];
    #pragma unroll
    for (int n = 0; n < 4; n++) {
      int c0 = ((nth*4 + n)*8 + 2*tg)*25 + t;
      d[n][0] = s_kb[c0];      d[n][1] = s_kb[c0 + 25];
      d[n][2] = d[n][0];       d[n][3] = d[n][1];
    }

    const uint2* bb = (const uint2*)(s_b + buf*2048);
    #pragma unroll
    for (int ks = 0; ks < 4; ks++) {
      #pragma unroll
      for (int n = 0; n < 4; n++) {
        uint2 bv = bb[((nth*4 + n)*4 + ks)*32 + l];
        MMA_FP16(d[n], ahi[ks], bv.x, bv.y);   // ahi * bhi
        MMA_FP16(d[n], alo[ks], bv.x, bv.y);   // alo * bhi
      }
    }

    const int sl = (prow + rr) % 3;
    #pragma unroll
    for (int n = 0; n < 4; n++) {
      int cb = (nth*4 + n)*8 + 2*tg;
      #pragma unroll
      for (int j = 0; j < 4; j++) {
        int c  = cb + (j & 1);
        int px = pcol0 + (j >> 1)*8;
        float gv = d[n][j];
        float lv = fmaf(0.45f, fabsf(gv), 0.55f*gv);
        float xv = s_x[c*108 + sl*36 + px + dw];
        sacc[n*4 + j] = fmaf(lv, xv, sacc[n*4 + j]);
      }
    }
  }

  // ================= fused A = fusL @ sta epilogue =================
  __syncthreads();
  #pragma unroll
  for (int n = 0; n < 4; n++) {
    int cb = (nth*4 + n)*8 + 2*tg;
    #pragma unroll
    for (int j = 0; j < 4; j++) {
      int c  = cb + (j & 1);
      int px = prow*32 + pcol0 + (j >> 1)*8;
      s_sta[c*66 + px] = sacc[n*4 + j];
    }
  }
  for (int e = tid; e < 4096; e += 256) {
    int o = e >> 6, k = e & 63;
    s_fl[k*68 + o] = fusw[o*128 + k];
  }
  __syncthreads();

  {
    const int o0 = (tid & 15)*4, p0 = (tid >> 4)*4;
    float4 acc[4];
    #pragma unroll
    for (int i = 0; i < 4; i++) acc[i] = make_float4(0.f, 0.f, 0.f, 0.f);
    #pragma unroll 4
    for (int c = 0; c < 64; c++) {
      float4 w4 = *(const float4*)&s_fl[c*68 + o0];
      const float* sr = s_sta + c*66 + p0;
      #pragma unroll
      for (int pp = 0; pp < 4; pp++)
        acc[pp] = f4maf(sr[pp], w4, acc[pp]);
    }
    float* dst = g_A + (size_t)b*NPX*CC;
    #pragma unroll
    for (int pp = 0; pp < 4; pp++) {
      int pxt = p0 + pp;
      int gpx = (h0 + (pxt >> 5))*WIN + w0 + (pxt & 31);
      *(float4*)&dst[(size_t)gpx*CC + o0] = acc[pp];
    }
  }
}

// ---------------------------------------------------------------------------
// K3 v4: staged + row-precombined bilinear taps; t via interp of U.
// ---------------------------------------------------------------------------
__global__ __launch_bounds__(256, 4) void k3_fuse(const float* __restrict__ fusb,
                                                  float* __restrict__ out) {
  __shared__ float sAB[4*34*68];
  __shared__ float sU[2*34*8];
  __shared__ float s_M[1024];
  __shared__ float s_fb[64];
  __shared__ float s_w0[2][64], s_w1[2][64];
  __shared__ int   s_lb[2][64];
  __shared__ int   s_rows[2][2][2];
  __shared__ float s_wy[2][2][2];
  __shared__ int   s_fc[2][2];
  __shared__ float s_frc[2][2];
  __shared__ int   s_base[2];

  const int b = blockIdx.z, Y = blockIdx.y, X0 = blockIdx.x * 64;
  const int tid = threadIdx.x;
  const int ph = Y & 1;

  if (tid < 2) {
    const int k = tid;
    int fc0 = 0, fc1 = 0;
    #pragma unroll
    for (int p = 0; p < 2; p++) {
      int ci = ph*2 + p;
      float offx = k ? g_stoff[ci][0] : g_off[ci][0];
      float offy = k ? g_stoff[ci][1] : g_off[ci][1];
      float pyf = (Y + 0.5f)*0.5f - 0.5f + offy;
      float yf = floorf(pyf); int iy = (int)yf; float fy = pyf - yf;
      s_wy[k][p][0] = (iy   >= 0 && iy   <= HIN-1) ? (1.f - fy) : 0.f;
      s_wy[k][p][1] = (iy+1 >= 0 && iy+1 <= HIN-1) ? fy : 0.f;
      s_rows[k][p][0] = min(max(iy, 0), HIN-1);
      s_rows[k][p][1] = min(max(iy+1, 0), HIN-1);
      float xo = (p ? 0.25f : -0.25f) + offx;
      float xf = floorf(xo); int fc = (int)xf;
      s_fc[k][p] = fc; s_frc[k][p] = xo - xf;
      if (p == 0) fc0 = fc; else fc1 = fc;
    }
    s_base[k] = X0/2 + min(fc0, fc1);
  }
  __syncthreads();

  if (tid < 128) {
    int k = tid >> 6, u = tid & 63, p = u & 1;
    int sg = X0/2 + (u >> 1) + s_fc[k][p];
    float fr = s_frc[k][p];
    s_lb[k][u] = sg - s_base[k];
    s_w0[k][u] = (sg   >= 0 && sg   <= WIN-1) ? (1.f - fr) : 0.f;
    s_w1[k][u] = (sg+1 >= 0 && sg+1 <= WIN-1) ? fr : 0.f;
  }

  for (int e = tid; e < 2176; e += 256) {
    int kp = e / 544, rem = e - kp*544;
    int i = rem >> 4, c4 = rem & 15;
    int k = kp >> 1, p = kp & 1;
    int cg = min(max(s_base[k] + i, 0), WIN-1);
    const float4* src = (const float4*)(k ? g_A : g_B) + (size_t)(b*NPX)*16;
    float4 v0 = src[(s_rows[k][p][0]*WIN + cg)*16 + c4];
    float4 v1 = src[(s_rows[k][p][1]*WIN + cg)*16 + c4];
    float wy0 = s_wy[k][p][0], wy1 = s_wy[k][p][1];
    float4 vv;
    vv.x = wy0*v0.x + wy1*v1.x;  vv.y = wy0*v0.y + wy1*v1.y;
    vv.z = wy0*v0.z + wy1*v1.z;  vv.w = wy0*v0.w + wy1*v1.w;
    *(float4*)&sAB[(kp*34 + i)*68 + c4*4] = vv;
  }
  if (tid < 136) {
    int p = tid / 68, rem = tid - p*68;
    int i = rem >> 1, h = rem & 1;
    int ci = ph*2 + p;
    int cg = min(max(s_base[0] + i, 0), WIN-1);
    const float4* src = (const float4*)g_U + ((size_t)(b*4 + ci)*NPX)*2;
    float4 u0 = src[(s_rows[0][p][0]*WIN + cg)*2 + h];
    float4 u1 = src[(s_rows[0][p][1]*WIN + cg)*2 + h];
    float wy0 = s_wy[0][p][0], wy1 = s_wy[0][p][1];
    float4 vv;
    vv.x = wy0*u0.x + wy1*u1.x;  vv.y = wy0*u0.y + wy1*u1.y;
    vv.z = wy0*u0.z + wy1*u1.z;  vv.w = wy0*u0.w + wy1*u1.w;
    *(float4*)&sU[(p*34 + i)*8 + h*4] = vv;
  }
  for (int e = tid; e < 1024; e += 256)
    s_M[e] = g_M[ph*2 + (e >> 9)][e & 511];
  if (tid < 64) s_fb[tid] = fusb[tid];
  __syncthreads();

  const int u = tid & 63, q = tid >> 6, p = u & 1;
  const int   lbB = s_lb[0][u], lbA = s_lb[1][u];
  const float wB0 = s_w0[0][u], wB1 = s_w1[0][u];
  const float wA0 = s_w0[1][u], wA1 = s_w1[1][u];

  float tt[8];
  {
    const float4* Up = (const float4*)&sU[(p*34 + lbB)*8];
    float4 t0 = f4maf(wB1, Up[2], f4maf(wB0, Up[0], make_float4(0,0,0,0)));
    float4 t1 = f4maf(wB1, Up[3], f4maf(wB0, Up[1], make_float4(0,0,0,0)));
    tt[0]=t0.x; tt[1]=t0.y; tt[2]=t0.z; tt[3]=t0.w;
    tt[4]=t1.x; tt[5]=t1.y; tt[6]=t1.z; tt[7]=t1.w;
  }

  const float* Ab = &sAB[((2 + p)*34)*68];
  const float* Bb = &sAB[(p*34)*68];
  const float* Mp = &s_M[p*512];
  const float4* fb4 = (const float4*)s_fb;

  #pragma unroll
  for (int i4 = 0; i4 < 4; i4++) {
    const int o4 = q*4 + i4;
    float4 A0 = *(const float4*)&Ab[lbA*68 + o4*4];
    float4 A1 = *(const float4*)&Ab[(lbA+1)*68 + o4*4];
    float4 B0 = *(const float4*)&Bb[lbB*68 + o4*4];
    float4 B1 = *(const float4*)&Bb[(lbB+1)*68 + o4*4];
    float4 r = fb4[o4];
    r = f4maf(wA0, A0, r); r = f4maf(wA1, A1, r);
    r = f4maf(wB0, B0, r); r = f4maf(wB1, B1, r);
    #pragma unroll
    for (int j = 0; j < 8; j++) {
      float4 m4 = *(const float4*)&Mp[j*64 + o4*4];
      r = f4maf(tt[j], m4, r);
    }
    float* op = out + ((size_t)(b*CC + o4*4)*HOUT + Y)*WOUT + X0 + u;
    op[0]              = r.x;
    op[HOUT*WOUT]      = r.y;
    op[2*HOUT*WOUT]    = r.z;
    op[3*HOUT*WOUT]    = r.w;
  }
}

// ---------------------------------------------------------------------------
extern "C" void kernel_launch(void* const* d_in, const int* in_sizes, int n_in,
                              void* d_out, int out_size) {
  const float* x    = (const float*)d_in[0];
  const float* st   = (const float*)d_in[1];
  const float* kcw  = (const float*)d_in[2];
  const float* kcb  = (const float*)d_in[3];
  const float* wc   = (const float*)d_in[4];
  const float* we   = (const float*)d_in[5];
  const float* b1w  = (const float*)d_in[6];
  const float* b1b  = (const float*)d_in[7];
  const float* b2w  = (const float*)d_in[8];
  const float* b2b  = (const float*)d_in[9];
  const float* rw   = (const float*)d_in[10];
  const float* rb   = (const float*)d_in[11];
  const float* ow   = (const float*)d_in[12];
  const float* ob   = (const float*)d_in[13];
  const float* sow  = (const float*)d_in[14];
  const float* sob  = (const float*)d_in[15];
  const float* fusw = (const float*)d_in[16];
  const float* fusb = (const float*)d_in[17];
  float* out = (float*)d_out;

  const int smem2  = K2_SMEM_FLOATS * 4;
  const int smemp1 = KP1_SMEM_FLOATS * 4;
  cudaFuncSetAttribute(k2_sta_mma, cudaFuncAttributeMaxDynamicSharedMemorySize, smem2);
  cudaFuncSetAttribute(kprep1,     cudaFuncAttributeMaxDynamicSharedMemorySize, smemp1);

  k01_prep<<<104, 256>>>(kcw, b1w, b1b, b2w, b2b, rw, rb, ow, ob, sow, sob, wc, we, fusw);
  kprep1<<<dim3(NPX/128, BB), 256, smemp1>>>(x, fusw);
  k2_sta_mma<<<dim3(WIN/32, HIN/2, BB), 256, smem2>>>(x, st, kcb, fusw);
  k3_fuse<<<dim3(WOUT/64, HOUT, BB), 256>>>(fusb, out);
}

// round 13
// speedup vs baseline: 2.1157x; 1.1346x over previous
#include <cuda_runtime.h>
#include <cuda_bf16.h>
#include <cuda_fp16.h>
#include <cstdint>

#define BB 4
#define CC 64
#define HIN 96
#define WIN 96
#define HOUT 192
#define WOUT 192
#define NPX (HIN*WIN)          // 9216

// Scratch + precomputed data (allocation-free rule: device globals)
__device__ float g_A[BB*NPX*CC];         // fusL@sta, channel-last [b][px][64]
__device__ float g_B[BB*NPX*CC];         // fusR@x,   channel-last
__device__ float g_U[BB*4*NPX*8];        // wc_ci @ X, [b][ci][src][8]
__device__ float g_off[4][2];
__device__ float g_stoff[4][2];
__device__ float g_wcpx[4][512];         // [j*64+c]
__device__ float g_M[4][512];            // [j*64+o]  (fusR @ we_par)
// kc_w repacked: [t 25][q 8][ks 4][lane 32] uint2 = (b0h, b1h) fp16x2 (hi only)
__device__ uint2 g_b[25600];

// ============================ helpers ======================================
__device__ __forceinline__ uint32_t smem_u32(const void* p) {
  uint32_t a;
  asm("{ .reg .u64 t; cvta.to.shared.u64 t, %1; cvt.u32.u64 %0, t; }" : "=r"(a) : "l"(p));
  return a;
}
__device__ __forceinline__ void cp16(uint32_t dst, const float* src) {
  asm volatile("cp.async.cg.shared.global [%0], [%1], 16;" :: "r"(dst), "l"(src));
}
#define CP_COMMIT() asm volatile("cp.async.commit_group;" ::: "memory")
#define CP_WAIT0()  asm volatile("cp.async.wait_group 0;" ::: "memory")

__device__ __forceinline__ uint32_t fp16_pack2(float v0, float v1) {
  __half2 h = __floats2half2_rn(v0, v1);
  return *(uint32_t*)&h;
}

#define MMA_FP16(d, a, b0v, b1v) \
  asm volatile("mma.sync.aligned.m16n8k16.row.col.f32.f16.f16.f32 " \
      "{%0,%1,%2,%3}, {%4,%5,%6,%7}, {%8,%9}, {%0,%1,%2,%3};" \
      : "+f"((d)[0]), "+f"((d)[1]), "+f"((d)[2]), "+f"((d)[3]) \
      : "r"((a)[0]), "r"((a)[1]), "r"((a)[2]), "r"((a)[3]), "r"(b0v), "r"(b1v))

__device__ __forceinline__ float4 f4maf(float s, float4 a, float4 r) {
  r.x = fmaf(s, a.x, r.x); r.y = fmaf(s, a.y, r.y);
  r.z = fmaf(s, a.z, r.z); r.w = fmaf(s, a.w, r.w);
  return r;
}

// ---------------------------------------------------------------------------
// K01: blocks 0..99 repack kc_w -> fp16 hi fragments; blocks 100..103 parity
// ---------------------------------------------------------------------------
__global__ void k01_prep(const float* __restrict__ kcw,
                         const float* __restrict__ b1w, const float* __restrict__ b1b,
                         const float* __restrict__ b2w, const float* __restrict__ b2b,
                         const float* __restrict__ rw,  const float* __restrict__ rb,
                         const float* __restrict__ ow,  const float* __restrict__ ob,
                         const float* __restrict__ sow, const float* __restrict__ sob,
                         const float* __restrict__ wc,  const float* __restrict__ we,
                         const float* __restrict__ fusw) {
  const int tid = threadIdx.x;
  if (blockIdx.x < 100) {
    int idx = blockIdx.x*256 + tid;
    int l  = idx & 31;
    int ks = (idx >> 5) & 3;
    int q  = (idx >> 7) & 7;
    int t  = idx >> 10;
    int g = l >> 2, tg = l & 3;
    int c  = q*8 + g;
    int k0 = ks*16 + 2*tg;
    const float* row = kcw + (c*25 + t)*64;
    g_b[idx] = make_uint2(fp16_pack2(row[k0],     row[k0 + 1]),
                          fp16_pack2(row[k0 + 8], row[k0 + 9]));
    return;
  }
  __shared__ float hid[64], emb[64], r[4];
  __shared__ float s_we2[512];
  __shared__ float s_fr[64*65];
  const int ci = blockIdx.x - 100;
  const float in2 = (ci >> 1) ? 0.25f : -0.25f;
  const float in3 = (ci & 1)  ? 0.25f : -0.25f;

  for (int e = tid; e < 4096; e += 256) {
    int o = e >> 6, c = e & 63;
    s_fr[c*65 + o] = fusw[o*128 + 64 + c];
  }
  if (tid < 64) {
    float a = b1b[tid] + 0.5f*b1w[tid*4+0] + 0.5f*b1w[tid*4+1]
            + in2*b1w[tid*4+2] + in3*b1w[tid*4+3];
    hid[tid] = fmaxf(a, 0.f);
  }
  __syncthreads();
  if (tid < 64) {
    float a = b2b[tid];
    #pragma unroll 8
    for (int k = 0; k < 64; k++) a = fmaf(b2w[tid*64+k], hid[k], a);
    emb[tid] = fmaxf(a, 0.f);
  }
  __syncthreads();
  if (tid < 4) {
    float a = rb[tid];
    for (int k = 0; k < 64; k++) a = fmaf(rw[tid*64+k], emb[k], a);
    r[tid] = 1.f / (1.f + expf(-a));
  } else if (tid < 6) {
    int t = tid - 4; float a = ob[t];
    for (int k = 0; k < 64; k++) a = fmaf(ow[t*64+k], emb[k], a);
    g_off[ci][t] = a;
  } else if (tid < 8) {
    int t = tid - 6; float a = sob[t];
    for (int k = 0; k < 64; k++) a = fmaf(sow[t*64+k], emb[k], a);
    g_stoff[ci][t] = a;
  }
  __syncthreads();
  for (int e = tid; e < 512; e += 256) {
    float a = 0.f, bsum = 0.f;
    #pragma unroll
    for (int ex = 0; ex < 4; ex++) {
      a    = fmaf(r[ex], wc[ex*512+e], a);
      bsum = fmaf(r[ex], we[ex*512+e], bsum);
    }
    g_wcpx[ci][e] = a;
    s_we2[e] = bsum;
  }
  __syncthreads();
  for (int e = tid; e < 512; e += 256) {
    int j = e >> 6, o = e & 63;
    float a = 0.f;
    #pragma unroll 8
    for (int c = 0; c < 64; c++) a = fmaf(s_fr[c*65 + o], s_we2[c*8 + j], a);
    g_M[ci][j*64 + o] = a;
  }
}

// ---------------------------------------------------------------------------
// KPREP1: from x (read once): U[b][ci][src][8] = wc_ci@x,  B = fusR @ x.
// ---------------------------------------------------------------------------
#define KP1_SMEM_FLOATS (64*129 + 64*68 + 2048)

__global__ __launch_bounds__(256, 3) void kprep1(const float* __restrict__ x,
                                                 const float* __restrict__ fusw) {
  extern __shared__ float sm[];
  float* s_src = sm;                 // [c 64][px 129]
  float* s_wT  = sm + 8256;          // [k 64][o 68]  (fusR^T)
  float* swc   = sm + 8256 + 4352;   // [4][512]

  const int px0 = blockIdx.x*128, b = blockIdx.y;
  const int tid = threadIdx.x;
  const float* xb = x + (size_t)b*CC*NPX;

  for (int e = tid; e < 8192; e += 256) {
    int k = e >> 7, p = e & 127;
    s_src[k*129 + p] = xb[(size_t)k*NPX + px0 + p];
  }
  for (int e = tid; e < 4096; e += 256) {
    int o = e >> 6, k = e & 63;
    s_wT[k*68 + o] = fusw[o*128 + 64 + k];
  }
  for (int e = tid; e < 2048; e += 256) swc[e] = g_wcpx[e >> 9][e & 511];
  __syncthreads();

  {
    const int px = tid & 127, half = tid >> 7;
    float acc[2][8];
    #pragma unroll
    for (int i = 0; i < 2; i++)
      #pragma unroll
      for (int j = 0; j < 8; j++) acc[i][j] = 0.f;
    #pragma unroll 4
    for (int c = 0; c < 64; c++) {
      float xv = s_src[c*129 + px];
      #pragma unroll
      for (int i = 0; i < 2; i++) {
        const float* w = &swc[(half*2 + i)*512 + c];
        #pragma unroll
        for (int j = 0; j < 8; j++)
          acc[i][j] = fmaf(w[j*64], xv, acc[i][j]);
      }
    }
    #pragma unroll
    for (int i = 0; i < 2; i++) {
      float* dst = g_U + ((size_t)(b*4 + half*2 + i)*NPX + px0 + px)*8;
      *(float4*)dst       = make_float4(acc[i][0], acc[i][1], acc[i][2], acc[i][3]);
      *(float4*)(dst + 4) = make_float4(acc[i][4], acc[i][5], acc[i][6], acc[i][7]);
    }
  }

  {
    const int o0 = (tid & 15)*4, p0 = (tid >> 4)*8;
    float4 acc[8];
    #pragma unroll
    for (int i = 0; i < 8; i++) acc[i] = make_float4(0.f, 0.f, 0.f, 0.f);
    #pragma unroll 4
    for (int k = 0; k < 64; k++) {
      float4 w4 = *(const float4*)&s_wT[k*68 + o0];
      const float* sr = s_src + k*129 + p0;
      #pragma unroll
      for (int pp = 0; pp < 8; pp++) {
        float s = sr[pp];
        acc[pp] = f4maf(s, w4, acc[pp]);
      }
    }
    float* dst = g_B + (size_t)b*NPX*CC;
    #pragma unroll
    for (int pp = 0; pp < 8; pp++)
      *(float4*)&dst[(size_t)(px0 + p0 + pp)*CC + o0] = acc[pp];
  }
}

// ---------------------------------------------------------------------------
// K2 v9 (mma.sync fp16 m16n8k16, single-term, double-buffered 8KB B,
// x row-ring, fused A=fusL@sta epilogue): 16 MMA per warp-tap.
// Block: 256 thr / 8 warps, tile (b, 2 rows, 32 px), M=64.
// ---------------------------------------------------------------------------
#define K2_SMEM_FLOATS (4096 + 6912 + 1600)

__global__ __launch_bounds__(256, 3) void k2_sta_mma(const float* __restrict__ x,
                                                     const float* __restrict__ st,
                                                     const float* __restrict__ kcb,
                                                     const float* __restrict__ fusw) {
  extern __shared__ float sm[];
  float* s_b  = sm;                // [2][512 uint4] = 2x8KB
  float* s_x  = sm + 4096;         // [c 64][slot 3][36]
  float* s_kb = sm + 11008;        // [1600]
  // post-loop reuse:
  float* s_sta = sm;               // [c 64][px 66]  4224
  float* s_fl  = sm + 4224;        // [k 64][o 68]   4352

  const int b = blockIdx.z, h0 = blockIdx.y*2, w0 = blockIdx.x*32;
  const int tid = threadIdx.x, wid = tid >> 5, l = tid & 31;
  const int g = l >> 2, tg = l & 3;
  const int mt = wid & 3, nth = wid >> 2;
  const uint32_t sb = smem_u32(s_b);

  // B(0) prologue: 8KB = 512 x 16B chunks
  {
    const float* src = (const float*)g_b;
    #pragma unroll
    for (int i = 0; i < 2; i++) {
      int j = tid + i*256;
      cp16(sb + (uint32_t)j*16u, src + j*4);
    }
    CP_COMMIT();
  }

  // x rows 0..2 into slots 0..2
  for (int e = tid; e < 64*3*36; e += 256) {
    int col = e % 36; int slot = (e / 36) % 3; int c = e / 108;
    int gy = min(max(h0 - 2 + slot, 0), HIN - 1);
    int gx = min(max(w0 - 2 + col, 0), WIN - 1);
    s_x[c*108 + slot*36 + col] = x[((b*CC + c)*HIN + gy)*WIN + gx];
  }
  for (int e = tid; e < 1600; e += 256) s_kb[e] = kcb[e];

  // A fragments (fp16 hi) direct from gmem, tap-invariant
  uint32_t ahi[4][4];
  {
    const int pxg = mt*16 + g, pxg8 = pxg + 8;
    const int r0 = h0 + (pxg >> 5),  ca = w0 + (pxg & 31);
    const int r1 = h0 + (pxg8 >> 5), cb2 = w0 + (pxg8 & 31);
    const float* stb = st + (size_t)b*CC*NPX;
    #pragma unroll
    for (int ks = 0; ks < 4; ks++) {
      int kb = ks*16 + 2*tg;
      const float* p0 = stb + (size_t)kb*NPX;
      ahi[ks][0] = fp16_pack2(p0[r0*WIN + ca],         p0[NPX + r0*WIN + ca]);
      ahi[ks][1] = fp16_pack2(p0[r1*WIN + cb2],        p0[NPX + r1*WIN + cb2]);
      ahi[ks][2] = fp16_pack2(p0[8*NPX + r0*WIN + ca], p0[9*NPX + r0*WIN + ca]);
      ahi[ks][3] = fp16_pack2(p0[8*NPX + r1*WIN + cb2], p0[9*NPX + r1*WIN + cb2]);
    }
  }
  __syncthreads();

  float sacc[16];
  #pragma unroll
  for (int i = 0; i < 16; i++) sacc[i] = 0.f;

  const int prow  = mt >> 1;
  const int pcol0 = (mt & 1)*16 + g;

  for (int t = 0; t < 25; t++) {
    const int buf = t & 1;
    CP_WAIT0();
    __syncthreads();
    if (t < 24) {
      const float* src = (const float*)(g_b + (t + 1)*1024);
      const uint32_t nb = sb + (uint32_t)(1 - buf)*8192u;
      #pragma unroll
      for (int i = 0; i < 2; i++) {
        int j = tid + i*256;
        cp16(nb + (uint32_t)j*16u, src + j*4);
      }
      CP_COMMIT();
    }
    if (t == 5 || t == 10 || t == 15) {
      const int rl = t/5 + 2;
      const int slot = rl % 3;
      const int gy = min(max(h0 - 2 + rl, 0), HIN - 1);
      for (int e = tid; e < 2304; e += 256) {
        int col = e % 36; int c = e / 36;
        int gx = min(max(w0 - 2 + col, 0), WIN - 1);
        s_x[c*108 + slot*36 + col] = x[((b*CC + c)*HIN + gy)*WIN + gx];
      }
    }

    const int rr = t / 5, dw = t - rr*5;

    float d[4][4];
    #pragma unroll
    for (int n = 0; n < 4; n++) {
      int c0 = ((nth*4 + n)*8 + 2*tg)*25 + t;
      d[n][0] = s_kb[c0];      d[n][1] = s_kb[c0 + 25];
      d[n][2] = d[n][0];       d[n][3] = d[n][1];
    }

    const uint2* bb = (const uint2*)(s_b + buf*2048);
    #pragma unroll
    for (int ks = 0; ks < 4; ks++) {
      #pragma unroll
      for (int n = 0; n < 4; n++) {
        uint2 bv = bb[((nth*4 + n)*4 + ks)*32 + l];
        MMA_FP16(d[n], ahi[ks], bv.x, bv.y);   // ahi * bhi (single term)
      }
    }

    const int sl = (prow + rr) % 3;
    #pragma unroll
    for (int n = 0; n < 4; n++) {
      int cb = (nth*4 + n)*8 + 2*tg;
      #pragma unroll
      for (int j = 0; j < 4; j++) {
        int c  = cb + (j & 1);
        int px = pcol0 + (j >> 1)*8;
        float gv = d[n][j];
        float lv = fmaf(0.45f, fabsf(gv), 0.55f*gv);
        float xv = s_x[c*108 + sl*36 + px + dw];
        sacc[n*4 + j] = fmaf(lv, xv, sacc[n*4 + j]);
      }
    }
  }

  // ================= fused A = fusL @ sta epilogue =================
  __syncthreads();
  #pragma unroll
  for (int n = 0; n < 4; n++) {
    int cb = (nth*4 + n)*8 + 2*tg;
    #pragma unroll
    for (int j = 0; j < 4; j++) {
      int c  = cb + (j & 1);
      int px = prow*32 + pcol0 + (j >> 1)*8;
      s_sta[c*66 + px] = sacc[n*4 + j];
    }
  }
  for (int e = tid; e < 4096; e += 256) {
    int o = e >> 6, k = e & 63;
    s_fl[k*68 + o] = fusw[o*128 + k];
  }
  __syncthreads();

  {
    const int o0 = (tid & 15)*4, p0 = (tid >> 4)*4;
    float4 acc[4];
    #pragma unroll
    for (int i = 0; i < 4; i++) acc[i] = make_float4(0.f, 0.f, 0.f, 0.f);
    #pragma unroll 4
    for (int c = 0; c < 64; c++) {
      float4 w4 = *(const float4*)&s_fl[c*68 + o0];
      const float* sr = s_sta + c*66 + p0;
      #pragma unroll
      for (int pp = 0; pp < 4; pp++)
        acc[pp] = f4maf(sr[pp], w4, acc[pp]);
    }
    float* dst = g_A + (size_t)b*NPX*CC;
    #pragma unroll
    for (int pp = 0; pp < 4; pp++) {
      int pxt = p0 + pp;
      int gpx = (h0 + (pxt >> 5))*WIN + w0 + (pxt & 31);
      *(float4*)&dst[(size_t)gpx*CC + o0] = acc[pp];
    }
  }
}

// ---------------------------------------------------------------------------
// K3 v4: staged + row-precombined bilinear taps; t via interp of U.
// ---------------------------------------------------------------------------
__global__ __launch_bounds__(256, 4) void k3_fuse(const float* __restrict__ fusb,
                                                  float* __restrict__ out) {
  __shared__ float sAB[4*34*68];
  __shared__ float sU[2*34*8];
  __shared__ float s_M[1024];
  __shared__ float s_fb[64];
  __shared__ float s_w0[2][64], s_w1[2][64];
  __shared__ int   s_lb[2][64];
  __shared__ int   s_rows[2][2][2];
  __shared__ float s_wy[2][2][2];
  __shared__ int   s_fc[2][2];
  __shared__ float s_frc[2][2];
  __shared__ int   s_base[2];

  const int b = blockIdx.z, Y = blockIdx.y, X0 = blockIdx.x * 64;
  const int tid = threadIdx.x;
  const int ph = Y & 1;

  if (tid < 2) {
    const int k = tid;
    int fc0 = 0, fc1 = 0;
    #pragma unroll
    for (int p = 0; p < 2; p++) {
      int ci = ph*2 + p;
      float offx = k ? g_stoff[ci][0] : g_off[ci][0];
      float offy = k ? g_stoff[ci][1] : g_off[ci][1];
      float pyf = (Y + 0.5f)*0.5f - 0.5f + offy;
      float yf = floorf(pyf); int iy = (int)yf; float fy = pyf - yf;
      s_wy[k][p][0] = (iy   >= 0 && iy   <= HIN-1) ? (1.f - fy) : 0.f;
      s_wy[k][p][1] = (iy+1 >= 0 && iy+1 <= HIN-1) ? fy : 0.f;
      s_rows[k][p][0] = min(max(iy, 0), HIN-1);
      s_rows[k][p][1] = min(max(iy+1, 0), HIN-1);
      float xo = (p ? 0.25f : -0.25f) + offx;
      float xf = floorf(xo); int fc = (int)xf;
      s_fc[k][p] = fc; s_frc[k][p] = xo - xf;
      if (p == 0) fc0 = fc; else fc1 = fc;
    }
    s_base[k] = X0/2 + min(fc0, fc1);
  }
  __syncthreads();

  if (tid < 128) {
    int k = tid >> 6, u = tid & 63, p = u & 1;
    int sg = X0/2 + (u >> 1) + s_fc[k][p];
    float fr = s_frc[k][p];
    s_lb[k][u] = sg - s_base[k];
    s_w0[k][u] = (sg   >= 0 && sg   <= WIN-1) ? (1.f - fr) : 0.f;
    s_w1[k][u] = (sg+1 >= 0 && sg+1 <= WIN-1) ? fr : 0.f;
  }

  for (int e = tid; e < 2176; e += 256) {
    int kp = e / 544, rem = e - kp*544;
    int i = rem >> 4, c4 = rem & 15;
    int k = kp >> 1, p = kp & 1;
    int cg = min(max(s_base[k] + i, 0), WIN-1);
    const float4* src = (const float4*)(k ? g_A : g_B) + (size_t)(b*NPX)*16;
    float4 v0 = src[(s_rows[k][p][0]*WIN + cg)*16 + c4];
    float4 v1 = src[(s_rows[k][p][1]*WIN + cg)*16 + c4];
    float wy0 = s_wy[k][p][0], wy1 = s_wy[k][p][1];
    float4 vv;
    vv.x = wy0*v0.x + wy1*v1.x;  vv.y = wy0*v0.y + wy1*v1.y;
    vv.z = wy0*v0.z + wy1*v1.z;  vv.w = wy0*v0.w + wy1*v1.w;
    *(float4*)&sAB[(kp*34 + i)*68 + c4*4] = vv;
  }
  if (tid < 136) {
    int p = tid / 68, rem = tid - p*68;
    int i = rem >> 1, h = rem & 1;
    int ci = ph*2 + p;
    int cg = min(max(s_base[0] + i, 0), WIN-1);
    const float4* src = (const float4*)g_U + ((size_t)(b*4 + ci)*NPX)*2;
    float4 u0 = src[(s_rows[0][p][0]*WIN + cg)*2 + h];
    float4 u1 = src[(s_rows[0][p][1]*WIN + cg)*2 + h];
    float wy0 = s_wy[0][p][0], wy1 = s_wy[0][p][1];
    float4 vv;
    vv.x = wy0*u0.x + wy1*u1.x;  vv.y = wy0*u0.y + wy1*u1.y;
    vv.z = wy0*u0.z + wy1*u1.z;  vv.w = wy0*u0.w + wy1*u1.w;
    *(float4*)&sU[(p*34 + i)*8 + h*4] = vv;
  }
  for (int e = tid; e < 1024; e += 256)
    s_M[e] = g_M[ph*2 + (e >> 9)][e & 511];
  if (tid < 64) s_fb[tid] = fusb[tid];
  __syncthreads();

  const int u = tid & 63, q = tid >> 6, p = u & 1;
  const int   lbB = s_lb[0][u], lbA = s_lb[1][u];
  const float wB0 = s_w0[0][u], wB1 = s_w1[0][u];
  const float wA0 = s_w0[1][u], wA1 = s_w1[1][u];

  float tt[8];
  {
    const float4* Up = (const float4*)&sU[(p*34 + lbB)*8];
    float4 t0 = f4maf(wB1, Up[2], f4maf(wB0, Up[0], make_float4(0,0,0,0)));
    float4 t1 = f4maf(wB1, Up[3], f4maf(wB0, Up[1], make_float4(0,0,0,0)));
    tt[0]=t0.x; tt[1]=t0.y; tt[2]=t0.z; tt[3]=t0.w;
    tt[4]=t1.x; tt[5]=t1.y; tt[6]=t1.z; tt[7]=t1.w;
  }

  const float* Ab = &sAB[((2 + p)*34)*68];
  const float* Bb = &sAB[(p*34)*68];
  const float* Mp = &s_M[p*512];
  const float4* fb4 = (const float4*)s_fb;

  #pragma unroll
  for (int i4 = 0; i4 < 4; i4++) {
    const int o4 = q*4 + i4;
    float4 A0 = *(const float4*)&Ab[lbA*68 + o4*4];
    float4 A1 = *(const float4*)&Ab[(lbA+1)*68 + o4*4];
    float4 B0 = *(const float4*)&Bb[lbB*68 + o4*4];
    float4 B1 = *(const float4*)&Bb[(lbB+1)*68 + o4*4];
    float4 r = fb4[o4];
    r = f4maf(wA0, A0, r); r = f4maf(wA1, A1, r);
    r = f4maf(wB0, B0, r); r = f4maf(wB1, B1, r);
    #pragma unroll
    for (int j = 0; j < 8; j++) {
      float4 m4 = *(const float4*)&Mp[j*64 + o4*4];
      r = f4maf(tt[j], m4, r);
    }
    float* op = out + ((size_t)(b*CC + o4*4)*HOUT + Y)*WOUT + X0 + u;
    op[0]              = r.x;
    op[HOUT*WOUT]      = r.y;
    op[2*HOUT*WOUT]    = r.z;
    op[3*HOUT*WOUT]    = r.w;
  }
}

// ---------------------------------------------------------------------------
extern "C" void kernel_launch(void* const* d_in, const int* in_sizes, int n_in,
                              void* d_out, int out_size) {
  const float* x    = (const float*)d_in[0];
  const float* st   = (const float*)d_in[1];
  const float* kcw  = (const float*)d_in[2];
  const float* kcb  = (const float*)d_in[3];
  const float* wc   = (const float*)d_in[4];
  const float* we   = (const float*)d_in[5];
  const float* b1w  = (const float*)d_in[6];
  const float* b1b  = (const float*)d_in[7];
  const float* b2w  = (const float*)d_in[8];
  const float* b2b  = (const float*)d_in[9];
  const float* rw   = (const float*)d_in[10];
  const float* rb   = (const float*)d_in[11];
  const float* ow   = (const float*)d_in[12];
  const float* ob   = (const float*)d_in[13];
  const float* sow  = (const float*)d_in[14];
  const float* sob  = (const float*)d_in[15];
  const float* fusw = (const float*)d_in[16];
  const float* fusb = (const float*)d_in[17];
  float* out = (float*)d_out;

  const int smem2  = K2_SMEM_FLOATS * 4;
  const int smemp1 = KP1_SMEM_FLOATS * 4;
  cudaFuncSetAttribute(k2_sta_mma, cudaFuncAttributeMaxDynamicSharedMemorySize, smem2);
  cudaFuncSetAttribute(kprep1,     cudaFuncAttributeMaxDynamicSharedMemorySize, smemp1);

  k01_prep<<<104, 256>>>(kcw, b1w, b1b, b2w, b2b, rw, rb, ow, ob, sow, sob, wc, we, fusw);
  kprep1<<<dim3(NPX/128, BB), 256, smemp1>>>(x, fusw);
  k2_sta_mma<<<dim3(WIN/32, HIN/2, BB), 256, smem2>>>(x, st, kcb, fusw);
  k3_fuse<<<dim3(WOUT/64, HOUT, BB), 256>>>(fusb, out);
}